// round 4
// baseline (speedup 1.0000x reference)
#include <cuda_runtime.h>
#include <math.h>

#define NB 32
#define LL 1024
#define DM 128
#define TT 4095
#define NDIAG 2047
#define DSTRIDE ((size_t)NDIAG*LL)
#define INFV __int_as_float(0x7f800000)

// ---------------- device scratch ----------------
__device__ float g_wp[DM*12*7];
__device__ float g_h[(size_t)NB*LL*DM];
__device__ float g_norm2[NB*LL];
__device__ float g_Dskew[(size_t)NB*NDIAG*LL];   // D, then R in place (skewed)
__device__ float g_Rmin[NB];
__device__ float g_Rmax[NB];
__device__ float g_Rn[(size_t)NB*LL*LL];         // normalized R -> scores -> attn
__device__ float g_qkv[(size_t)NB*LL*384];
__device__ float g_sa[(size_t)NB*LL*DM];
__device__ float g_tmp[(size_t)NB*LL*DM];
__device__ float g_h1[(size_t)NB*LL*DM];
__device__ float g_ff[(size_t)NB*LL*DM];
__device__ float g_h2[(size_t)NB*LL*DM];

// ---------------- 0: fold conv+avgpool weights ----------------
__global__ void prep_wp(const float* __restrict__ conv_w) {
    int d = threadIdx.x;
    for (int c = 0; c < 12; c++)
        for (int p = 0; p < 7; p++) {
            float s = 0.f;
            int klo = p - 3 > 0 ? p - 3 : 0;
            int khi = p < 3 ? p : 3;
            for (int k = klo; k <= khi; k++) s += conv_w[(d*12 + c)*4 + k];
            g_wp[(d*12 + c)*7 + p] = 0.25f * s;
        }
}

// ---------------- 1: conv+pool+relu+mask -> h[B,L,128] ----------------
__global__ void conv_kernel(const float* __restrict__ x, const float* __restrict__ conv_b,
                            const float* __restrict__ mask) {
    int b = blockIdx.y, l0 = blockIdx.x * 16, d = threadIdx.x;
    __shared__ float xs[12][68];
    __shared__ float wps[128][85];
    for (int i = d; i < 128*84; i += 128) { wps[i/84][i%84] = g_wp[i]; }
    for (int i = d; i < 12*67; i += 128) {
        int c = i / 67, t = i % 67;
        int xi = 4*l0 - 2 + t;
        xs[c][t] = (xi >= 0 && xi < TT) ? x[((size_t)b*12 + c)*TT + xi] : 0.f;
    }
    __syncthreads();
    float bb = conv_b[d];
    for (int ll = 0; ll < 16; ll++) {
        float acc = bb;
        #pragma unroll
        for (int c = 0; c < 12; c++)
            #pragma unroll
            for (int p = 0; p < 7; p++)
                acc += xs[c][4*ll + p] * wps[d][c*7 + p];
        float hv = fmaxf(acc, 0.f) * mask[b*LL + l0 + ll];
        g_h[((size_t)b*LL + l0 + ll)*DM + d] = hv;
    }
}

// ---------------- 2: row squared norms ----------------
__global__ void norm2_kernel() {
    int row = blockIdx.x, t = threadIdx.x;
    float v = g_h[(size_t)row*DM + t];
    float s = v * v;
    for (int o = 16; o; o >>= 1) s += __shfl_down_sync(0xffffffffu, s, o);
    __shared__ float ws[4];
    if ((t & 31) == 0) ws[t >> 5] = s;
    __syncthreads();
    if (t == 0) g_norm2[row] = ws[0] + ws[1] + ws[2] + ws[3];
}

// ---------------- 3: pairwise D2 -> skewed Dskew[b][i+j][i] ----------------
__global__ void d2_kernel() {
    int b = blockIdx.z, i0 = blockIdx.y*64, j0 = blockIdx.x*64;
    __shared__ float As[64][17], Bs[64][17];
    __shared__ float Cs[64][66];
    __shared__ float na[64], ns[64];
    int tid = threadIdx.x, ty = tid/16, tx = tid%16;
    const float* A  = g_h;                      // anchor = batch 0
    const float* Bm = g_h + (size_t)b*LL*DM;
    float acc[4][4] = {};
    for (int kc = 0; kc < 128; kc += 16) {
        for (int i = tid; i < 1024; i += 256) {
            int r = i >> 4, c = i & 15;
            As[r][c] = A [(size_t)(i0+r)*DM + kc + c];
            Bs[r][c] = Bm[(size_t)(j0+r)*DM + kc + c];
        }
        __syncthreads();
        #pragma unroll
        for (int kk = 0; kk < 16; kk++) {
            float a[4], bb[4];
            #pragma unroll
            for (int u = 0; u < 4; u++) { a[u] = As[ty*4+u][kk]; bb[u] = Bs[tx*4+u][kk]; }
            #pragma unroll
            for (int u = 0; u < 4; u++)
                #pragma unroll
                for (int v = 0; v < 4; v++) acc[u][v] += a[u]*bb[v];
        }
        __syncthreads();
    }
    if (tid < 64) na[tid] = g_norm2[i0 + tid];
    else if (tid < 128) ns[tid - 64] = g_norm2[b*LL + j0 + tid - 64];
    __syncthreads();
    #pragma unroll
    for (int u = 0; u < 4; u++)
        #pragma unroll
        for (int v = 0; v < 4; v++)
            Cs[ty*4+u][tx*4+v] = na[ty*4+u] + ns[tx*4+v] - 2.f*acc[u][v];
    __syncthreads();
    float* Dk = g_Dskew + (size_t)b*DSTRIDE;
    for (int kb = 0; kb < 128; kb += 4) {
        int kk = kb + (tid >> 6);
        int lane = tid & 63;
        if (kk < 127) {
            int k = i0 + j0 + kk;
            int ilo = i0 > (k - j0 - 63) ? i0 : (k - j0 - 63);
            int ihi = (i0 + 63) < (k - j0) ? (i0 + 63) : (k - j0);
            int i = ilo + lane;
            if (i <= ihi) Dk[(size_t)k*LL + i] = Cs[i - i0][k - i - j0];
        }
    }
}

// ---------------- 4: soft-DTW wavefront (R in place) ----------------
__global__ void __launch_bounds__(1024) softdtw_kernel() {
    int b = blockIdx.x, i = threadIdx.x;
    __shared__ float s0[1024], s1[1024], s2[1024];
    __shared__ float rmn[32], rmx[32];
    float *prev2 = s0, *prev1 = s1, *cur = s2;
    prev2[i] = INFV; prev1[i] = INFV;
    float* Dk = g_Dskew + (size_t)b*DSTRIDE;
    float vmin = INFV, vmax = -INFV;
    const float cExp = 0.28853900817779268f;   // 1/(gamma*ln2), gamma=5
    const float cLog = 3.4657359027997265f;    // gamma*ln2
    float dbuf[8];
    #pragma unroll
    for (int p = 0; p < 8; p++) dbuf[p] = Dk[(size_t)p*LL + i];
    __syncthreads();
    for (int kb = 0; kb < 2048; kb += 8) {
        #pragma unroll
        for (int p = 0; p < 8; p++) {
            int k = kb + p;
            if (k >= NDIAG) break;
            float d = dbuf[p];
            if (k + 8 < NDIAG) dbuf[p] = Dk[(size_t)(k+8)*LL + i];
            float r_l = prev1[i];
            float r_u, r_ul;
            if (i == 0) { r_u = INFV; r_ul = (k == 0) ? 0.f : INFV; }
            else        { r_u = prev1[i-1]; r_ul = prev2[i-1]; }
            int j = k - i;
            if (j >= 0 && j < LL) {
                float m = fminf(r_ul, fminf(r_u, r_l));
                float s = exp2f((m - r_ul)*cExp) + exp2f((m - r_u)*cExp) + exp2f((m - r_l)*cExp);
                float rv = d + m - cLog * log2f(s);
                cur[i] = rv;
                Dk[(size_t)k*LL + i] = rv;
                vmin = fminf(vmin, rv); vmax = fmaxf(vmax, rv);
            } else cur[i] = INFV;
            __syncthreads();
            float* t = prev2; prev2 = prev1; prev1 = cur; cur = t;
        }
    }
    for (int o = 16; o; o >>= 1) {
        vmin = fminf(vmin, __shfl_down_sync(0xffffffffu, vmin, o));
        vmax = fmaxf(vmax, __shfl_down_sync(0xffffffffu, vmax, o));
    }
    if ((i & 31) == 0) { rmn[i >> 5] = vmin; rmx[i >> 5] = vmax; }
    __syncthreads();
    if (i < 32) {
        vmin = rmn[i]; vmax = rmx[i];
        for (int o = 16; o; o >>= 1) {
            vmin = fminf(vmin, __shfl_down_sync(0xffffffffu, vmin, o));
            vmax = fmaxf(vmax, __shfl_down_sync(0xffffffffu, vmax, o));
        }
        if (i == 0) { g_Rmin[b] = vmin; g_Rmax[b] = vmax; }
    }
}

// ---------------- 5: unskew + minmax-normalize -> Rn[b][i][j] ----------------
__global__ void normalize_kernel() {
    int b = blockIdx.z, i0 = blockIdx.y*32, j0 = blockIdx.x*32;
    __shared__ float s[63*33];
    int tid = threadIdx.y*32 + threadIdx.x;
    float mn = g_Rmin[b];
    float inv = 1.f / (g_Rmax[b] - mn);
    const float* Rk = g_Dskew + (size_t)b*DSTRIDE;
    for (int idx = tid; idx < 63*32; idx += 1024) {
        int r = idx >> 5, c = idx & 31;
        s[r*33 + c] = Rk[(size_t)(i0 + j0 + r)*LL + i0 + c];
    }
    __syncthreads();
    float v = s[(threadIdx.y + threadIdx.x)*33 + threadIdx.y];
    g_Rn[(size_t)b*LL*LL + (size_t)(i0 + threadIdx.y)*LL + j0 + threadIdx.x] = (v - mn)*inv + 1.f;
}

// ---------------- generic NT GEMM: C[M,N]=A[M,128]*B[N,128]^T (+bias)(relu) ----------------
__global__ void gemm_nt_kernel(const float* __restrict__ A, const float* __restrict__ Bw,
                               const float* __restrict__ bias, float* __restrict__ C,
                               int N, int relu) {
    int m0 = blockIdx.y*64, n0 = blockIdx.x*64;
    __shared__ float As[64][17], Bs[64][17];
    int tid = threadIdx.x, ty = tid/16, tx = tid%16;
    float acc[4][4] = {};
    for (int kc = 0; kc < 128; kc += 16) {
        for (int i = tid; i < 1024; i += 256) {
            int r = i >> 4, c = i & 15;
            As[r][c] = A [(size_t)(m0 + r)*128 + kc + c];
            Bs[r][c] = Bw[(size_t)(n0 + r)*128 + kc + c];
        }
        __syncthreads();
        #pragma unroll
        for (int kk = 0; kk < 16; kk++) {
            float a[4], b4[4];
            #pragma unroll
            for (int u = 0; u < 4; u++) { a[u] = As[ty*4+u][kk]; b4[u] = Bs[tx*4+u][kk]; }
            #pragma unroll
            for (int u = 0; u < 4; u++)
                #pragma unroll
                for (int v = 0; v < 4; v++) acc[u][v] += a[u]*b4[v];
        }
        __syncthreads();
    }
    #pragma unroll
    for (int u = 0; u < 4; u++)
        #pragma unroll
        for (int v = 0; v < 4; v++) {
            int n = n0 + tx*4 + v;
            float val = acc[u][v] + (bias ? bias[n] : 0.f);
            if (relu) val = fmaxf(val, 0.f);
            C[(size_t)(m0 + ty*4 + u)*N + n] = val;
        }
}

// ---------------- 6: scores: Rn += (Q K^T)/sqrt(128) ----------------
__global__ void qk_kernel() {
    int b = blockIdx.z, l0 = blockIdx.y*64, m0 = blockIdx.x*64;
    const float* Q = g_qkv + (size_t)b*LL*384;
    const float* K = Q + 128;
    __shared__ float As[64][17], Bs[64][17];
    int tid = threadIdx.x, ty = tid/16, tx = tid%16;
    float acc[4][4] = {};
    for (int kc = 0; kc < 128; kc += 16) {
        for (int i = tid; i < 1024; i += 256) {
            int r = i >> 4, c = i & 15;
            As[r][c] = Q[(size_t)(l0 + r)*384 + kc + c];
            Bs[r][c] = K[(size_t)(m0 + r)*384 + kc + c];
        }
        __syncthreads();
        #pragma unroll
        for (int kk = 0; kk < 16; kk++) {
            float a[4], b4[4];
            #pragma unroll
            for (int u = 0; u < 4; u++) { a[u] = As[ty*4+u][kk]; b4[u] = Bs[tx*4+u][kk]; }
            #pragma unroll
            for (int u = 0; u < 4; u++)
                #pragma unroll
                for (int v = 0; v < 4; v++) acc[u][v] += a[u]*b4[v];
        }
        __syncthreads();
    }
    const float scale = 0.08838834764831845f;  // 1/sqrt(128)
    float* Rn = g_Rn + (size_t)b*LL*LL;
    #pragma unroll
    for (int u = 0; u < 4; u++)
        #pragma unroll
        for (int v = 0; v < 4; v++) {
            size_t idx = (size_t)(l0 + ty*4 + u)*LL + m0 + tx*4 + v;
            Rn[idx] = Rn[idx] + acc[u][v]*scale;
        }
}

// ---------------- 7: row softmax (with key padding) in place ----------------
__global__ void softmax_kernel(const float* __restrict__ mask) {
    int row = blockIdx.x, t = threadIdx.x, b = row >> 10;
    float* S = g_Rn + (size_t)row*LL;
    const float* mk = mask + (size_t)b*LL;
    float v[4]; float mx = -INFV;
    #pragma unroll
    for (int u = 0; u < 4; u++) {
        int m = t + u*256;
        float x = S[m];
        x = (mk[m] > 0.f) ? x : -INFV;
        v[u] = x; mx = fmaxf(mx, x);
    }
    __shared__ float red[8];
    for (int o = 16; o; o >>= 1) mx = fmaxf(mx, __shfl_xor_sync(0xffffffffu, mx, o));
    if ((t & 31) == 0) red[t >> 5] = mx;
    __syncthreads();
    mx = red[0];
    #pragma unroll
    for (int w = 1; w < 8; w++) mx = fmaxf(mx, red[w]);
    float sum = 0.f;
    #pragma unroll
    for (int u = 0; u < 4; u++) { float e = __expf(v[u] - mx); v[u] = e; sum += e; }
    for (int o = 16; o; o >>= 1) sum += __shfl_xor_sync(0xffffffffu, sum, o);
    __syncthreads();
    if ((t & 31) == 0) red[t >> 5] = sum;
    __syncthreads();
    sum = red[0] + red[1] + red[2] + red[3] + red[4] + red[5] + red[6] + red[7];
    float inv = 1.f / sum;
    #pragma unroll
    for (int u = 0; u < 4; u++) S[t + u*256] = v[u]*inv;
}

// ---------------- 8: PV (NN): sa = attn @ v ----------------
__global__ void pv_kernel() {
    int b = blockIdx.z, l0 = blockIdx.y*64, n0 = blockIdx.x*64;
    const float* Am = g_Rn + (size_t)b*LL*LL;
    const float* V  = g_qkv + (size_t)b*LL*384 + 256;
    __shared__ float As[64][17], Bs[16][68];
    int tid = threadIdx.x, ty = tid/16, tx = tid%16;
    float acc[4][4] = {};
    for (int kc = 0; kc < 1024; kc += 16) {
        for (int i = tid; i < 1024; i += 256) {
            int r = i >> 4, c = i & 15;
            As[r][c] = Am[(size_t)(l0 + r)*LL + kc + c];
        }
        for (int i = tid; i < 16*64; i += 256) {
            int r = i >> 6, c = i & 63;
            Bs[r][c] = V[(size_t)(kc + r)*384 + n0 + c];
        }
        __syncthreads();
        #pragma unroll
        for (int kk = 0; kk < 16; kk++) {
            float a[4], b4[4];
            #pragma unroll
            for (int u = 0; u < 4; u++) { a[u] = As[ty*4+u][kk]; b4[u] = Bs[kk][tx*4+u]; }
            #pragma unroll
            for (int u = 0; u < 4; u++)
                #pragma unroll
                for (int v = 0; v < 4; v++) acc[u][v] += a[u]*b4[v];
        }
        __syncthreads();
    }
    #pragma unroll
    for (int u = 0; u < 4; u++)
        #pragma unroll
        for (int v = 0; v < 4; v++)
            g_sa[((size_t)b*LL + l0 + ty*4 + u)*DM + n0 + tx*4 + v] = acc[u][v];
}

// ---------------- 9: residual + layernorm ----------------
__global__ void ln_kernel(const float* __restrict__ a, const float* __restrict__ bsrc,
                          const float* __restrict__ g, const float* __restrict__ beta,
                          float* __restrict__ out) {
    int row = blockIdx.x, t = threadIdx.x;
    float x = a[(size_t)row*DM + t] + bsrc[(size_t)row*DM + t];
    float s = x, q = x*x;
    for (int o = 16; o; o >>= 1) {
        s += __shfl_xor_sync(0xffffffffu, s, o);
        q += __shfl_xor_sync(0xffffffffu, q, o);
    }
    __shared__ float ss[4], qq[4];
    if ((t & 31) == 0) { ss[t >> 5] = s; qq[t >> 5] = q; }
    __syncthreads();
    s = ss[0]+ss[1]+ss[2]+ss[3];
    q = qq[0]+qq[1]+qq[2]+qq[3];
    float m = s * (1.f/128.f);
    float v = q * (1.f/128.f) - m*m;
    out[(size_t)row*DM + t] = (x - m) * rsqrtf(v + 1e-5f) * g[t] + beta[t];
}

// ---------------- 10: final projection 128->16 (masked) ----------------
__global__ void out_kernel(const float* __restrict__ w_lin, const float* __restrict__ mask,
                           float* __restrict__ dout) {
    int row = blockIdx.x, t = threadIdx.x;
    __shared__ float hs[128];
    hs[t] = g_h2[(size_t)row*DM + t];
    __syncthreads();
    if (t < 16) {
        float s = 0.f;
        #pragma unroll
        for (int d = 0; d < 128; d++) s += hs[d] * w_lin[t*128 + d];
        dout[(size_t)row*16 + t] = s * mask[row];
    }
}

// ---------------- 11: length = sum(mask, axis=1) ----------------
__global__ void len_kernel(const float* __restrict__ mask, float* __restrict__ dout) {
    int b = blockIdx.x, t = threadIdx.x;
    float s = mask[(size_t)b*LL + t];
    for (int o = 16; o; o >>= 1) s += __shfl_xor_sync(0xffffffffu, s, o);
    __shared__ float ws[32];
    if ((t & 31) == 0) ws[t >> 5] = s;
    __syncthreads();
    if (t == 0) {
        float tot = 0.f;
        for (int w = 0; w < 32; w++) tot += ws[w];
        dout[(size_t)NB*LL*16 + b] = tot;
    }
}

extern "C" void kernel_launch(void* const* d_in, const int* in_sizes, int n_in,
                              void* d_out, int out_size) {
    const float* x      = (const float*)d_in[0];
    const float* mask   = (const float*)d_in[1];
    const float* conv_w = (const float*)d_in[2];
    const float* conv_b = (const float*)d_in[3];
    const float* w_in   = (const float*)d_in[4];
    const float* b_in   = (const float*)d_in[5];
    const float* w_out  = (const float*)d_in[6];
    const float* b_out  = (const float*)d_in[7];
    const float* w_ff1  = (const float*)d_in[8];
    const float* b_ff1  = (const float*)d_in[9];
    const float* w_ff2  = (const float*)d_in[10];
    const float* b_ff2  = (const float*)d_in[11];
    const float* ln1_g  = (const float*)d_in[12];
    const float* ln1_b  = (const float*)d_in[13];
    const float* ln2_g  = (const float*)d_in[14];
    const float* ln2_b  = (const float*)d_in[15];
    const float* w_lin  = (const float*)d_in[16];
    float* dout = (float*)d_out;

    float* ph;   cudaGetSymbolAddress((void**)&ph,   g_h);
    float* pqkv; cudaGetSymbolAddress((void**)&pqkv, g_qkv);
    float* psa;  cudaGetSymbolAddress((void**)&psa,  g_sa);
    float* ptmp; cudaGetSymbolAddress((void**)&ptmp, g_tmp);
    float* ph1;  cudaGetSymbolAddress((void**)&ph1,  g_h1);
    float* pff;  cudaGetSymbolAddress((void**)&pff,  g_ff);
    float* ph2;  cudaGetSymbolAddress((void**)&ph2,  g_h2);

    prep_wp<<<1, 128>>>(conv_w);
    conv_kernel<<<dim3(64, 32), 128>>>(x, conv_b, mask);
    norm2_kernel<<<NB*LL, 128>>>();
    d2_kernel<<<dim3(16, 16, NB), 256>>>();
    softdtw_kernel<<<NB, 1024>>>();
    normalize_kernel<<<dim3(32, 32, NB), dim3(32, 32)>>>();
    gemm_nt_kernel<<<dim3(6, 512), 256>>>(ph, w_in, b_in, pqkv, 384, 0);
    qk_kernel<<<dim3(16, 16, NB), 256>>>();
    softmax_kernel<<<NB*LL, 256>>>(mask);
    pv_kernel<<<dim3(2, 16, NB), 256>>>();
    gemm_nt_kernel<<<dim3(2, 512), 256>>>(psa, w_out, b_out, ptmp, 128, 0);
    ln_kernel<<<NB*LL, 128>>>(ph, ptmp, ln1_g, ln1_b, ph1);
    gemm_nt_kernel<<<dim3(2, 512), 256>>>(ph1, w_ff1, b_ff1, pff, 128, 1);
    gemm_nt_kernel<<<dim3(2, 512), 256>>>(pff, w_ff2, b_ff2, ptmp, 128, 0);
    ln_kernel<<<NB*LL, 128>>>(ph1, ptmp, ln2_g, ln2_b, ph2);
    out_kernel<<<NB*LL, 128>>>(w_lin, mask, dout);
    len_kernel<<<NB, 1024>>>(mask, dout);
}

// round 7
// speedup vs baseline: 1.1827x; 1.1827x over previous
#include <cuda_runtime.h>
#include <math.h>

#define NB 32
#define LL 1024
#define DM 128
#define TT 4095
#define NDIAG 2047
#define DSTRIDE ((size_t)NDIAG*LL)
#define INFV __int_as_float(0x7f800000)

// ---------------- device scratch ----------------
__device__ float g_wp[DM*12*7];
__device__ float g_h[(size_t)NB*LL*DM];
__device__ float g_norm2[NB*LL];
__device__ float g_Dskew[(size_t)NB*NDIAG*LL];   // D, then R in place (skewed)
__device__ float g_Rmin[NB];
__device__ float g_Rmax[NB];
__device__ float g_Rn[(size_t)NB*LL*LL];         // normalized R (attention bias)
__device__ float g_qkv[(size_t)NB*LL*384];
__device__ float g_sa[(size_t)NB*LL*DM];
__device__ float g_tmp[(size_t)NB*LL*DM];
__device__ float g_h1[(size_t)NB*LL*DM];
__device__ float g_ff[(size_t)NB*LL*DM];
__device__ float g_h2[(size_t)NB*LL*DM];

// ---------------- 0: fold conv+avgpool weights ----------------
__global__ void prep_wp(const float* __restrict__ conv_w) {
    int d = threadIdx.x;
    for (int c = 0; c < 12; c++)
        for (int p = 0; p < 7; p++) {
            float s = 0.f;
            int klo = p - 3 > 0 ? p - 3 : 0;
            int khi = p < 3 ? p : 3;
            for (int k = klo; k <= khi; k++) s += conv_w[(d*12 + c)*4 + k];
            g_wp[(d*12 + c)*7 + p] = 0.25f * s;
        }
}

// ---------------- 1: conv+pool+relu+mask -> h[B,L,128] ----------------
__global__ void conv_kernel(const float* __restrict__ x, const float* __restrict__ conv_b,
                            const float* __restrict__ mask) {
    int b = blockIdx.y, l0 = blockIdx.x * 16, d = threadIdx.x;
    __shared__ float xs[12][68];
    __shared__ float wps[128][85];
    for (int i = d; i < 128*84; i += 128) { wps[i/84][i%84] = g_wp[i]; }
    for (int i = d; i < 12*67; i += 128) {
        int c = i / 67, t = i % 67;
        int xi = 4*l0 - 2 + t;
        xs[c][t] = (xi >= 0 && xi < TT) ? x[((size_t)b*12 + c)*TT + xi] : 0.f;
    }
    __syncthreads();
    float bb = conv_b[d];
    for (int ll = 0; ll < 16; ll++) {
        float acc = bb;
        #pragma unroll
        for (int c = 0; c < 12; c++)
            #pragma unroll
            for (int p = 0; p < 7; p++)
                acc += xs[c][4*ll + p] * wps[d][c*7 + p];
        float hv = fmaxf(acc, 0.f) * mask[b*LL + l0 + ll];
        g_h[((size_t)b*LL + l0 + ll)*DM + d] = hv;
    }
}

// ---------------- 2: row squared norms ----------------
__global__ void norm2_kernel() {
    int row = blockIdx.x, t = threadIdx.x;
    float v = g_h[(size_t)row*DM + t];
    float s = v * v;
    for (int o = 16; o; o >>= 1) s += __shfl_down_sync(0xffffffffu, s, o);
    __shared__ float ws[4];
    if ((t & 31) == 0) ws[t >> 5] = s;
    __syncthreads();
    if (t == 0) g_norm2[row] = ws[0] + ws[1] + ws[2] + ws[3];
}

// ---------------- 3: pairwise D2 -> skewed Dskew[b][i+j][i] (k-major smem) ----------------
__global__ void __launch_bounds__(256) d2_kernel() {
    int b = blockIdx.z, i0 = blockIdx.y*64, j0 = blockIdx.x*64;
    __shared__ float As[16][68], Bs[16][68];
    __shared__ float Cs[64][66];
    __shared__ float na[64], ns[64];
    int tid = threadIdx.x, ty = tid>>4, tx = tid&15;
    int lr = tid>>2, lc4 = tid&3;
    const float* A  = g_h;
    const float* Bm = g_h + (size_t)b*LL*DM;
    float acc[4][4] = {};
    for (int kc = 0; kc < 8; kc++) {
        __syncthreads();
        float4 av = *(const float4*)&A [(size_t)(i0+lr)*DM + kc*16 + lc4*4];
        float4 bv = *(const float4*)&Bm[(size_t)(j0+lr)*DM + kc*16 + lc4*4];
        As[lc4*4+0][lr]=av.x; As[lc4*4+1][lr]=av.y; As[lc4*4+2][lr]=av.z; As[lc4*4+3][lr]=av.w;
        Bs[lc4*4+0][lr]=bv.x; Bs[lc4*4+1][lr]=bv.y; Bs[lc4*4+2][lr]=bv.z; Bs[lc4*4+3][lr]=bv.w;
        __syncthreads();
        #pragma unroll
        for (int kk = 0; kk < 16; kk++) {
            float4 a4 = *(const float4*)&As[kk][ty*4];
            float4 b4 = *(const float4*)&Bs[kk][tx*4];
            float a[4] = {a4.x, a4.y, a4.z, a4.w};
            float bb[4] = {b4.x, b4.y, b4.z, b4.w};
            #pragma unroll
            for (int u = 0; u < 4; u++)
                #pragma unroll
                for (int v = 0; v < 4; v++) acc[u][v] += a[u]*bb[v];
        }
    }
    __syncthreads();
    if (tid < 64) na[tid] = g_norm2[i0 + tid];
    else if (tid < 128) ns[tid - 64] = g_norm2[b*LL + j0 + tid - 64];
    __syncthreads();
    #pragma unroll
    for (int u = 0; u < 4; u++)
        #pragma unroll
        for (int v = 0; v < 4; v++)
            Cs[ty*4+u][tx*4+v] = na[ty*4+u] + ns[tx*4+v] - 2.f*acc[u][v];
    __syncthreads();
    float* Dk = g_Dskew + (size_t)b*DSTRIDE;
    for (int kb = 0; kb < 128; kb += 4) {
        int kk = kb + (tid >> 6);
        int lane = tid & 63;
        if (kk < 127) {
            int k = i0 + j0 + kk;
            int ilo = i0 > (k - j0 - 63) ? i0 : (k - j0 - 63);
            int ihi = (i0 + 63) < (k - j0) ? (i0 + 63) : (k - j0);
            int i = ilo + lane;
            if (i <= ihi) Dk[(size_t)k*LL + i] = Cs[i - i0][k - i - j0];
        }
    }
}

// ---------------- 4: soft-DTW wavefront (R in place) ----------------
__global__ void __launch_bounds__(1024) softdtw_kernel() {
    int b = blockIdx.x, i = threadIdx.x;
    __shared__ float s0[1024], s1[1024], s2[1024];
    __shared__ float rmn[32], rmx[32];
    float *prev2 = s0, *prev1 = s1, *cur = s2;
    prev2[i] = INFV; prev1[i] = INFV;
    float rprev = INFV;   // own prev1[i] kept in register
    float* Dk = g_Dskew + (size_t)b*DSTRIDE;
    float vmin = INFV, vmax = -INFV;
    const float cExp = 0.28853900817779268f;   // 1/(gamma*ln2), gamma=5
    const float cLog = 3.4657359027997265f;    // gamma*ln2
    float dbuf[8];
    #pragma unroll
    for (int p = 0; p < 8; p++) dbuf[p] = Dk[(size_t)p*LL + i];
    __syncthreads();
    for (int kb = 0; kb < 2048; kb += 8) {
        #pragma unroll
        for (int p = 0; p < 8; p++) {
            int k = kb + p;
            if (k >= NDIAG) break;
            float d = dbuf[p];
            if (k + 8 < NDIAG) dbuf[p] = Dk[(size_t)(k+8)*LL + i];
            float r_l = rprev;
            float r_u, r_ul;
            if (i == 0) { r_u = INFV; r_ul = (k == 0) ? 0.f : INFV; }
            else        { r_u = prev1[i-1]; r_ul = prev2[i-1]; }
            int j = k - i;
            float rv;
            if (j >= 0 && j < LL) {
                float m = fminf(r_ul, fminf(r_u, r_l));
                float s = exp2f((m - r_ul)*cExp) + exp2f((m - r_u)*cExp) + exp2f((m - r_l)*cExp);
                rv = d + m - cLog * __log2f(s);
                cur[i] = rv;
                Dk[(size_t)k*LL + i] = rv;
                vmin = fminf(vmin, rv); vmax = fmaxf(vmax, rv);
            } else { rv = INFV; cur[i] = INFV; }
            rprev = rv;
            __syncthreads();
            float* t = prev2; prev2 = prev1; prev1 = cur; cur = t;
        }
    }
    for (int o = 16; o; o >>= 1) {
        vmin = fminf(vmin, __shfl_down_sync(0xffffffffu, vmin, o));
        vmax = fmaxf(vmax, __shfl_down_sync(0xffffffffu, vmax, o));
    }
    if ((i & 31) == 0) { rmn[i >> 5] = vmin; rmx[i >> 5] = vmax; }
    __syncthreads();
    if (i < 32) {
        vmin = rmn[i]; vmax = rmx[i];
        for (int o = 16; o; o >>= 1) {
            vmin = fminf(vmin, __shfl_down_sync(0xffffffffu, vmin, o));
            vmax = fmaxf(vmax, __shfl_down_sync(0xffffffffu, vmax, o));
        }
        if (i == 0) { g_Rmin[b] = vmin; g_Rmax[b] = vmax; }
    }
}

// ---------------- 5: unskew + minmax-normalize -> Rn[b][i][j] ----------------
__global__ void normalize_kernel() {
    int b = blockIdx.z, i0 = blockIdx.y*32, j0 = blockIdx.x*32;
    __shared__ float s[63*33];
    int tid = threadIdx.y*32 + threadIdx.x;
    float mn = g_Rmin[b];
    float inv = 1.f / (g_Rmax[b] - mn);
    const float* Rk = g_Dskew + (size_t)b*DSTRIDE;
    for (int idx = tid; idx < 63*32; idx += 1024) {
        int r = idx >> 5, c = idx & 31;
        s[r*33 + c] = Rk[(size_t)(i0 + j0 + r)*LL + i0 + c];
    }
    __syncthreads();
    float v = s[(threadIdx.y + threadIdx.x)*33 + threadIdx.y];
    g_Rn[(size_t)b*LL*LL + (size_t)(i0 + threadIdx.y)*LL + j0 + threadIdx.x] = (v - mn)*inv + 1.f;
}

// ---------------- generic NT GEMM (k-major smem, float4): C=A*B^T (+bias)(relu) ----------------
__global__ void __launch_bounds__(256) gemm_nt_kernel(const float* __restrict__ A,
                               const float* __restrict__ Bw,
                               const float* __restrict__ bias, float* __restrict__ C,
                               int N, int relu) {
    int m0 = blockIdx.y*64, n0 = blockIdx.x*64;
    __shared__ float As[16][68], Bs[16][68];
    int tid = threadIdx.x, ty = tid>>4, tx = tid&15;
    int lr = tid>>2, lc4 = tid&3;
    float acc[4][4] = {};
    for (int kc = 0; kc < 8; kc++) {
        __syncthreads();
        float4 av = *(const float4*)&A [(size_t)(m0+lr)*128 + kc*16 + lc4*4];
        float4 bv = *(const float4*)&Bw[(size_t)(n0+lr)*128 + kc*16 + lc4*4];
        As[lc4*4+0][lr]=av.x; As[lc4*4+1][lr]=av.y; As[lc4*4+2][lr]=av.z; As[lc4*4+3][lr]=av.w;
        Bs[lc4*4+0][lr]=bv.x; Bs[lc4*4+1][lr]=bv.y; Bs[lc4*4+2][lr]=bv.z; Bs[lc4*4+3][lr]=bv.w;
        __syncthreads();
        #pragma unroll
        for (int kk = 0; kk < 16; kk++) {
            float4 a4 = *(const float4*)&As[kk][ty*4];
            float4 b4 = *(const float4*)&Bs[kk][tx*4];
            float a[4] = {a4.x, a4.y, a4.z, a4.w};
            float bb[4] = {b4.x, b4.y, b4.z, b4.w};
            #pragma unroll
            for (int u = 0; u < 4; u++)
                #pragma unroll
                for (int v = 0; v < 4; v++) acc[u][v] += a[u]*bb[v];
        }
    }
    #pragma unroll
    for (int u = 0; u < 4; u++) {
        float o[4];
        #pragma unroll
        for (int v = 0; v < 4; v++) {
            int n = n0 + tx*4 + v;
            float val = acc[u][v] + (bias ? bias[n] : 0.f);
            if (relu) val = fmaxf(val, 0.f);
            o[v] = val;
        }
        *(float4*)&C[(size_t)(m0 + ty*4 + u)*N + n0 + tx*4] = make_float4(o[0],o[1],o[2],o[3]);
    }
}

// ---------------- 6: flash attention (qk+bias+mask+softmax+pv fused) -> g_sa ----------------
__global__ void __launch_bounds__(256) flash_kernel(const float* __restrict__ mask) {
    int b = blockIdx.y, i0 = blockIdx.x*64;
    int tid = threadIdx.x, ty = tid>>4, tx = tid&15;
    int lr = tid>>2, lc4 = tid&3;        // QK loaders
    int vr = tid>>4, vc = (tid&15)*8;    // V loaders
    __shared__ float Qs[16][68], Ks[16][68], Vs[16][136], Ps[64][68];
    const float* Qg = g_qkv + (size_t)b*LL*384;
    const float* Kg = Qg + 128;
    const float* Vg = Qg + 256;
    const float* Rn = g_Rn + (size_t)b*LL*LL;
    const float* mk = mask + (size_t)b*LL;
    float Oacc[4][8] = {};
    float mrow[4], lrow[4];
    #pragma unroll
    for (int u = 0; u < 4; u++) { mrow[u] = -1e30f; lrow[u] = 0.f; }
    const float scale = 0.08838834764831845f;  // 1/sqrt(128)

    for (int kt = 0; kt < 16; kt++) {
        // ---- S = Q K^T ----
        float acc[4][4] = {};
        for (int kc = 0; kc < 8; kc++) {
            __syncthreads();
            float4 qv = *(const float4*)&Qg[(size_t)(i0+lr)*384 + kc*16 + lc4*4];
            float4 kv = *(const float4*)&Kg[(size_t)(kt*64+lr)*384 + kc*16 + lc4*4];
            Qs[lc4*4+0][lr]=qv.x; Qs[lc4*4+1][lr]=qv.y; Qs[lc4*4+2][lr]=qv.z; Qs[lc4*4+3][lr]=qv.w;
            Ks[lc4*4+0][lr]=kv.x; Ks[lc4*4+1][lr]=kv.y; Ks[lc4*4+2][lr]=kv.z; Ks[lc4*4+3][lr]=kv.w;
            __syncthreads();
            #pragma unroll
            for (int kk = 0; kk < 16; kk++) {
                float4 a4 = *(const float4*)&Qs[kk][ty*4];
                float4 b4 = *(const float4*)&Ks[kk][tx*4];
                float a[4] = {a4.x, a4.y, a4.z, a4.w};
                float bb[4] = {b4.x, b4.y, b4.z, b4.w};
                #pragma unroll
                for (int u = 0; u < 4; u++)
                    #pragma unroll
                    for (int v = 0; v < 4; v++) acc[u][v] += a[u]*bb[v];
            }
        }
        // ---- bias + mask + online softmax ----
        float4 mkv = *(const float4*)&mk[kt*64 + tx*4];
        float mvv[4] = {mkv.x, mkv.y, mkv.z, mkv.w};
        float s[4][4];
        #pragma unroll
        for (int u = 0; u < 4; u++) {
            float4 bi = *(const float4*)&Rn[(size_t)(i0+ty*4+u)*LL + kt*64 + tx*4];
            float bb4[4] = {bi.x, bi.y, bi.z, bi.w};
            float rm = -1e30f;
            #pragma unroll
            for (int v = 0; v < 4; v++) {
                float xv = acc[u][v]*scale + bb4[v];
                xv = (mvv[v] > 0.f) ? xv : -1e30f;
                s[u][v] = xv; rm = fmaxf(rm, xv);
            }
            for (int o = 8; o; o >>= 1) rm = fmaxf(rm, __shfl_xor_sync(0xffffffffu, rm, o));
            float mt = fmaxf(mrow[u], rm);
            float f = __expf(mrow[u] - mt);
            mrow[u] = mt;
            float rs = 0.f;
            #pragma unroll
            for (int v = 0; v < 4; v++) { float p = __expf(s[u][v] - mt); s[u][v] = p; rs += p; }
            for (int o = 8; o; o >>= 1) rs += __shfl_xor_sync(0xffffffffu, rs, o);
            lrow[u] = lrow[u]*f + rs;
            #pragma unroll
            for (int dd = 0; dd < 8; dd++) Oacc[u][dd] *= f;
        }
        // ---- stage P (Ps[q][k]) ----
        #pragma unroll
        for (int u = 0; u < 4; u++)
            *(float4*)&Ps[ty*4+u][tx*4] = make_float4(s[u][0], s[u][1], s[u][2], s[u][3]);
        // ---- O += P V ----
        for (int kc2 = 0; kc2 < 4; kc2++) {
            __syncthreads();
            const float* vrow = &Vg[(size_t)(kt*64 + kc2*16 + vr)*384 + vc];
            float4 v0 = *(const float4*)vrow;
            float4 v1 = *(const float4*)(vrow + 4);
            *(float4*)&Vs[vr][vc]   = v0;
            *(float4*)&Vs[vr][vc+4] = v1;
            __syncthreads();
            #pragma unroll
            for (int kk = 0; kk < 16; kk++) {
                float4 va = *(const float4*)&Vs[kk][tx*8];
                float4 vb = *(const float4*)&Vs[kk][tx*8+4];
                float pv[4];
                #pragma unroll
                for (int u = 0; u < 4; u++) pv[u] = Ps[ty*4+u][kc2*16+kk];
                #pragma unroll
                for (int u = 0; u < 4; u++) {
                    Oacc[u][0] += pv[u]*va.x; Oacc[u][1] += pv[u]*va.y;
                    Oacc[u][2] += pv[u]*va.z; Oacc[u][3] += pv[u]*va.w;
                    Oacc[u][4] += pv[u]*vb.x; Oacc[u][5] += pv[u]*vb.y;
                    Oacc[u][6] += pv[u]*vb.z; Oacc[u][7] += pv[u]*vb.w;
                }
            }
        }
    }
    // ---- epilogue ----
    #pragma unroll
    for (int u = 0; u < 4; u++) {
        float inv = 1.f / lrow[u];
        float* orow = &g_sa[((size_t)b*LL + i0 + ty*4 + u)*DM + tx*8];
        *(float4*)orow       = make_float4(Oacc[u][0]*inv, Oacc[u][1]*inv, Oacc[u][2]*inv, Oacc[u][3]*inv);
        *(float4*)(orow + 4) = make_float4(Oacc[u][4]*inv, Oacc[u][5]*inv, Oacc[u][6]*inv, Oacc[u][7]*inv);
    }
}

// ---------------- 9: residual + layernorm ----------------
__global__ void ln_kernel(const float* __restrict__ a, const float* __restrict__ bsrc,
                          const float* __restrict__ g, const float* __restrict__ beta,
                          float* __restrict__ out) {
    int row = blockIdx.x, t = threadIdx.x;
    float x = a[(size_t)row*DM + t] + bsrc[(size_t)row*DM + t];
    float s = x, q = x*x;
    for (int o = 16; o; o >>= 1) {
        s += __shfl_xor_sync(0xffffffffu, s, o);
        q += __shfl_xor_sync(0xffffffffu, q, o);
    }
    __shared__ float ss[4], qq[4];
    if ((t & 31) == 0) { ss[t >> 5] = s; qq[t >> 5] = q; }
    __syncthreads();
    s = ss[0]+ss[1]+ss[2]+ss[3];
    q = qq[0]+qq[1]+qq[2]+qq[3];
    float m = s * (1.f/128.f);
    float v = q * (1.f/128.f) - m*m;
    out[(size_t)row*DM + t] = (x - m) * rsqrtf(v + 1e-5f) * g[t] + beta[t];
}

// ---------------- 10: final projection 128->16 (masked) ----------------
__global__ void out_kernel(const float* __restrict__ w_lin, const float* __restrict__ mask,
                           float* __restrict__ dout) {
    int row = blockIdx.x, t = threadIdx.x;
    __shared__ float hs[128];
    hs[t] = g_h2[(size_t)row*DM + t];
    __syncthreads();
    if (t < 16) {
        float s = 0.f;
        #pragma unroll
        for (int d = 0; d < 128; d++) s += hs[d] * w_lin[t*128 + d];
        dout[(size_t)row*16 + t] = s * mask[row];
    }
}

// ---------------- 11: length = sum(mask, axis=1) ----------------
__global__ void len_kernel(const float* __restrict__ mask, float* __restrict__ dout) {
    int b = blockIdx.x, t = threadIdx.x;
    float s = mask[(size_t)b*LL + t];
    for (int o = 16; o; o >>= 1) s += __shfl_xor_sync(0xffffffffu, s, o);
    __shared__ float ws[32];
    if ((t & 31) == 0) ws[t >> 5] = s;
    __syncthreads();
    if (t == 0) {
        float tot = 0.f;
        for (int w = 0; w < 32; w++) tot += ws[w];
        dout[(size_t)NB*LL*16 + b] = tot;
    }
}

extern "C" void kernel_launch(void* const* d_in, const int* in_sizes, int n_in,
                              void* d_out, int out_size) {
    const float* x      = (const float*)d_in[0];
    const float* mask   = (const float*)d_in[1];
    const float* conv_w = (const float*)d_in[2];
    const float* conv_b = (const float*)d_in[3];
    const float* w_in   = (const float*)d_in[4];
    const float* b_in   = (const float*)d_in[5];
    const float* w_out  = (const float*)d_in[6];
    const float* b_out  = (const float*)d_in[7];
    const float* w_ff1  = (const float*)d_in[8];
    const float* b_ff1  = (const float*)d_in[9];
    const float* w_ff2  = (const float*)d_in[10];
    const float* b_ff2  = (const float*)d_in[11];
    const float* ln1_g  = (const float*)d_in[12];
    const float* ln1_b  = (const float*)d_in[13];
    const float* ln2_g  = (const float*)d_in[14];
    const float* ln2_b  = (const float*)d_in[15];
    const float* w_lin  = (const float*)d_in[16];
    float* dout = (float*)d_out;

    float* ph;   cudaGetSymbolAddress((void**)&ph,   g_h);
    float* pqkv; cudaGetSymbolAddress((void**)&pqkv, g_qkv);
    float* psa;  cudaGetSymbolAddress((void**)&psa,  g_sa);
    float* ptmp; cudaGetSymbolAddress((void**)&ptmp, g_tmp);
    float* ph1;  cudaGetSymbolAddress((void**)&ph1,  g_h1);
    float* pff;  cudaGetSymbolAddress((void**)&pff,  g_ff);
    float* ph2;  cudaGetSymbolAddress((void**)&ph2,  g_h2);

    prep_wp<<<1, 128>>>(conv_w);
    conv_kernel<<<dim3(64, 32), 128>>>(x, conv_b, mask);
    norm2_kernel<<<NB*LL, 128>>>();
    d2_kernel<<<dim3(16, 16, NB), 256>>>();
    softdtw_kernel<<<NB, 1024>>>();
    normalize_kernel<<<dim3(32, 32, NB), dim3(32, 32)>>>();
    gemm_nt_kernel<<<dim3(6, 512), 256>>>(ph, w_in, b_in, pqkv, 384, 0);
    flash_kernel<<<dim3(16, NB), 256>>>(mask);
    gemm_nt_kernel<<<dim3(2, 512), 256>>>(psa, w_out, b_out, ptmp, 128, 0);
    ln_kernel<<<NB*LL, 128>>>(ph, ptmp, ln1_g, ln1_b, ph1);
    gemm_nt_kernel<<<dim3(2, 512), 256>>>(ph1, w_ff1, b_ff1, pff, 128, 1);
    gemm_nt_kernel<<<dim3(2, 512), 256>>>(pff, w_ff2, b_ff2, ptmp, 128, 0);
    ln_kernel<<<NB*LL, 128>>>(ph1, ptmp, ln2_g, ln2_b, ph2);
    out_kernel<<<NB*LL, 128>>>(w_lin, mask, dout);
    len_kernel<<<NB, 1024>>>(mask, dout);
}

// round 8
// speedup vs baseline: 1.2037x; 1.0177x over previous
#include <cuda_runtime.h>
#include <math.h>

#define NB 32
#define LL 1024
#define DM 128
#define TT 4095
#define NDIAG 2047
#define DSTRIDE ((size_t)NDIAG*LL)
#define INFV __int_as_float(0x7f800000)

// ---------------- device scratch ----------------
__device__ float g_wp[DM*12*7];
__device__ float g_h[(size_t)NB*LL*DM];
__device__ float g_norm2[NB*LL];
__device__ float g_Dskew[(size_t)NB*NDIAG*LL];   // D, then R in place (skewed)
__device__ float g_Rmin[NB];
__device__ float g_Rmax[NB];
__device__ float g_Rn[(size_t)NB*LL*LL];         // normalized R (attention bias)
__device__ float g_qkv[(size_t)NB*LL*384];
__device__ float g_sa[(size_t)NB*LL*DM];
__device__ float g_tmp[(size_t)NB*LL*DM];
__device__ float g_h1[(size_t)NB*LL*DM];
__device__ float g_ff[(size_t)NB*LL*DM];
__device__ float g_h2[(size_t)NB*LL*DM];

// ---------------- 0: fold conv+avgpool weights ----------------
__global__ void prep_wp(const float* __restrict__ conv_w) {
    int d = threadIdx.x;
    for (int c = 0; c < 12; c++)
        for (int p = 0; p < 7; p++) {
            float s = 0.f;
            int klo = p - 3 > 0 ? p - 3 : 0;
            int khi = p < 3 ? p : 3;
            for (int k = klo; k <= khi; k++) s += conv_w[(d*12 + c)*4 + k];
            g_wp[(d*12 + c)*7 + p] = 0.25f * s;
        }
}

// ---------------- 1: conv+pool+relu+mask -> h[B,L,128] ----------------
__global__ void conv_kernel(const float* __restrict__ x, const float* __restrict__ conv_b,
                            const float* __restrict__ mask) {
    int b = blockIdx.y, l0 = blockIdx.x * 16, d = threadIdx.x;
    __shared__ float xs[12][68];
    __shared__ float wps[128][85];
    for (int i = d; i < 128*84; i += 128) { wps[i/84][i%84] = g_wp[i]; }
    for (int i = d; i < 12*67; i += 128) {
        int c = i / 67, t = i % 67;
        int xi = 4*l0 - 2 + t;
        xs[c][t] = (xi >= 0 && xi < TT) ? x[((size_t)b*12 + c)*TT + xi] : 0.f;
    }
    __syncthreads();
    float bb = conv_b[d];
    for (int ll = 0; ll < 16; ll++) {
        float acc = bb;
        #pragma unroll
        for (int c = 0; c < 12; c++)
            #pragma unroll
            for (int p = 0; p < 7; p++)
                acc += xs[c][4*ll + p] * wps[d][c*7 + p];
        float hv = fmaxf(acc, 0.f) * mask[b*LL + l0 + ll];
        g_h[((size_t)b*LL + l0 + ll)*DM + d] = hv;
    }
}

// ---------------- 2: row squared norms ----------------
__global__ void norm2_kernel() {
    int row = blockIdx.x, t = threadIdx.x;
    float v = g_h[(size_t)row*DM + t];
    float s = v * v;
    for (int o = 16; o; o >>= 1) s += __shfl_down_sync(0xffffffffu, s, o);
    __shared__ float ws[4];
    if ((t & 31) == 0) ws[t >> 5] = s;
    __syncthreads();
    if (t == 0) g_norm2[row] = ws[0] + ws[1] + ws[2] + ws[3];
}

// ---------------- 3: pairwise D2 (128x64 tile, 8x4 microtile) -> skewed ----------------
__global__ void __launch_bounds__(256) d2_kernel() {
    int b = blockIdx.z, i0 = blockIdx.y*128, j0 = blockIdx.x*64;
    __shared__ float As[16][132], Bs[16][68];
    __shared__ float Cs[128][66];
    __shared__ float na[128], ns[64];
    int tid = threadIdx.x, ty = tid>>4, tx = tid&15;
    const float* A  = g_h;
    const float* Bm = g_h + (size_t)b*LL*DM;
    float acc[8][4] = {};
    for (int kc = 0; kc < 8; kc++) {
        __syncthreads();
        #pragma unroll
        for (int rep = 0; rep < 2; rep++) {
            int idx = rep*256 + tid;
            int i = idx>>2, k4 = idx&3;
            float4 av = *(const float4*)&A[(size_t)(i0+i)*DM + kc*16 + k4*4];
            As[k4*4+0][i]=av.x; As[k4*4+1][i]=av.y; As[k4*4+2][i]=av.z; As[k4*4+3][i]=av.w;
        }
        {
            int jcol = tid>>2, k4 = tid&3;
            float4 bv = *(const float4*)&Bm[(size_t)(j0+jcol)*DM + kc*16 + k4*4];
            Bs[k4*4+0][jcol]=bv.x; Bs[k4*4+1][jcol]=bv.y; Bs[k4*4+2][jcol]=bv.z; Bs[k4*4+3][jcol]=bv.w;
        }
        __syncthreads();
        #pragma unroll
        for (int kk = 0; kk < 16; kk++) {
            float4 a0 = *(const float4*)&As[kk][ty*8];
            float4 a1 = *(const float4*)&As[kk][ty*8+4];
            float4 b4 = *(const float4*)&Bs[kk][tx*4];
            float a[8] = {a0.x,a0.y,a0.z,a0.w,a1.x,a1.y,a1.z,a1.w};
            float bb[4] = {b4.x,b4.y,b4.z,b4.w};
            #pragma unroll
            for (int u = 0; u < 8; u++)
                #pragma unroll
                for (int v = 0; v < 4; v++) acc[u][v] += a[u]*bb[v];
        }
    }
    __syncthreads();
    if (tid < 128) na[tid] = g_norm2[i0 + tid];
    else if (tid < 192) ns[tid-128] = g_norm2[b*LL + j0 + tid - 128];
    __syncthreads();
    #pragma unroll
    for (int u = 0; u < 8; u++)
        #pragma unroll
        for (int v = 0; v < 4; v++)
            Cs[ty*8+u][tx*4+v] = na[ty*8+u] + ns[tx*4+v] - 2.f*acc[u][v];
    __syncthreads();
    float* Dk = g_Dskew + (size_t)b*DSTRIDE;
    for (int kb = 0; kb < 192; kb += 4) {
        int kk = kb + (tid >> 6);
        int jo = tid & 63;
        if (kk < 191) {
            int io = kk - jo;
            if (io >= 0 && io < 128) {
                int k = i0 + j0 + kk;
                Dk[(size_t)k*LL + i0 + io] = Cs[io][jo];
            }
        }
    }
}

// ---------------- 4: soft-DTW wavefront (R in place) ----------------
__global__ void __launch_bounds__(1024) softdtw_kernel() {
    int b = blockIdx.x, i = threadIdx.x;
    __shared__ float s0[1024], s1[1024], s2[1024];
    __shared__ float rmn[32], rmx[32];
    float *prev2 = s0, *prev1 = s1, *cur = s2;
    prev2[i] = INFV; prev1[i] = INFV;
    float rprev = INFV;
    float* Dk = g_Dskew + (size_t)b*DSTRIDE;
    float vmin = INFV, vmax = -INFV;
    const float cExp = 0.28853900817779268f;   // 1/(gamma*ln2), gamma=5
    const float cLog = 3.4657359027997265f;    // gamma*ln2
    float dbuf[8];
    #pragma unroll
    for (int p = 0; p < 8; p++) dbuf[p] = Dk[(size_t)p*LL + i];
    __syncthreads();
    for (int kb = 0; kb < 2048; kb += 8) {
        #pragma unroll
        for (int p = 0; p < 8; p++) {
            int k = kb + p;
            if (k >= NDIAG) break;
            float d = dbuf[p];
            if (k + 8 < NDIAG) dbuf[p] = Dk[(size_t)(k+8)*LL + i];
            float r_l = rprev;
            float r_u, r_ul;
            if (i == 0) { r_u = INFV; r_ul = (k == 0) ? 0.f : INFV; }
            else        { r_u = prev1[i-1]; r_ul = prev2[i-1]; }
            int j = k - i;
            float rv;
            if (j >= 0 && j < LL) {
                float m = fminf(r_ul, fminf(r_u, r_l));
                float s = exp2f((m - r_ul)*cExp) + exp2f((m - r_u)*cExp) + exp2f((m - r_l)*cExp);
                rv = d + m - cLog * __log2f(s);
                cur[i] = rv;
                Dk[(size_t)k*LL + i] = rv;
                vmin = fminf(vmin, rv); vmax = fmaxf(vmax, rv);
            } else { rv = INFV; cur[i] = INFV; }
            rprev = rv;
            __syncthreads();
            float* t = prev2; prev2 = prev1; prev1 = cur; cur = t;
        }
    }
    for (int o = 16; o; o >>= 1) {
        vmin = fminf(vmin, __shfl_down_sync(0xffffffffu, vmin, o));
        vmax = fmaxf(vmax, __shfl_down_sync(0xffffffffu, vmax, o));
    }
    if ((i & 31) == 0) { rmn[i >> 5] = vmin; rmx[i >> 5] = vmax; }
    __syncthreads();
    if (i < 32) {
        vmin = rmn[i]; vmax = rmx[i];
        for (int o = 16; o; o >>= 1) {
            vmin = fminf(vmin, __shfl_down_sync(0xffffffffu, vmin, o));
            vmax = fmaxf(vmax, __shfl_down_sync(0xffffffffu, vmax, o));
        }
        if (i == 0) { g_Rmin[b] = vmin; g_Rmax[b] = vmax; }
    }
}

// ---------------- 5: unskew + minmax-normalize -> Rn[b][i][j] ----------------
__global__ void normalize_kernel() {
    int b = blockIdx.z, i0 = blockIdx.y*32, j0 = blockIdx.x*32;
    __shared__ float s[63*33];
    int tid = threadIdx.y*32 + threadIdx.x;
    float mn = g_Rmin[b];
    float inv = 1.f / (g_Rmax[b] - mn);
    const float* Rk = g_Dskew + (size_t)b*DSTRIDE;
    for (int idx = tid; idx < 63*32; idx += 1024) {
        int r = idx >> 5, c = idx & 31;
        s[r*33 + c] = Rk[(size_t)(i0 + j0 + r)*LL + i0 + c];
    }
    __syncthreads();
    float v = s[(threadIdx.y + threadIdx.x)*33 + threadIdx.y];
    g_Rn[(size_t)b*LL*LL + (size_t)(i0 + threadIdx.y)*LL + j0 + threadIdx.x] = (v - mn)*inv + 1.f;
}

// ---------------- generic NT GEMM (k-major smem, float4): C=A*B^T (+bias)(relu) ----------------
__global__ void __launch_bounds__(256) gemm_nt_kernel(const float* __restrict__ A,
                               const float* __restrict__ Bw,
                               const float* __restrict__ bias, float* __restrict__ C,
                               int N, int relu) {
    int m0 = blockIdx.y*64, n0 = blockIdx.x*64;
    __shared__ float As[16][68], Bs[16][68];
    int tid = threadIdx.x, ty = tid>>4, tx = tid&15;
    int lr = tid>>2, lc4 = tid&3;
    float acc[4][4] = {};
    for (int kc = 0; kc < 8; kc++) {
        __syncthreads();
        float4 av = *(const float4*)&A [(size_t)(m0+lr)*128 + kc*16 + lc4*4];
        float4 bv = *(const float4*)&Bw[(size_t)(n0+lr)*128 + kc*16 + lc4*4];
        As[lc4*4+0][lr]=av.x; As[lc4*4+1][lr]=av.y; As[lc4*4+2][lr]=av.z; As[lc4*4+3][lr]=av.w;
        Bs[lc4*4+0][lr]=bv.x; Bs[lc4*4+1][lr]=bv.y; Bs[lc4*4+2][lr]=bv.z; Bs[lc4*4+3][lr]=bv.w;
        __syncthreads();
        #pragma unroll
        for (int kk = 0; kk < 16; kk++) {
            float4 a4 = *(const float4*)&As[kk][ty*4];
            float4 b4 = *(const float4*)&Bs[kk][tx*4];
            float a[4] = {a4.x, a4.y, a4.z, a4.w};
            float bb[4] = {b4.x, b4.y, b4.z, b4.w};
            #pragma unroll
            for (int u = 0; u < 4; u++)
                #pragma unroll
                for (int v = 0; v < 4; v++) acc[u][v] += a[u]*bb[v];
        }
    }
    #pragma unroll
    for (int u = 0; u < 4; u++) {
        float o[4];
        #pragma unroll
        for (int v = 0; v < 4; v++) {
            int n = n0 + tx*4 + v;
            float val = acc[u][v] + (bias ? bias[n] : 0.f);
            if (relu) val = fmaxf(val, 0.f);
            o[v] = val;
        }
        *(float4*)&C[(size_t)(m0 + ty*4 + u)*N + n0 + tx*4] = make_float4(o[0],o[1],o[2],o[3]);
    }
}

// ---------------- 6: flash attention v2 (64q x 128k tiles, persistent Q) ----------------
#define FLASH_SMEM ((128*68 + 32*132 + 16*136 + 64*132)*4)
__global__ void __launch_bounds__(256) flash_kernel(const float* __restrict__ mask) {
    extern __shared__ float sm[];
    float* Qs = sm;                         // [128][68]  k-major
    float* Ks = sm + 128*68;                // [32][132]  k-major
    float* Vs = sm + 128*68 + 32*132;       // [16][136]  d-major
    float* Ps = sm + 128*68 + 32*132 + 16*136; // [64][132]
    int b = blockIdx.y, i0 = blockIdx.x*64;
    int tid = threadIdx.x, ty = tid>>4, tx = tid&15;
    const float* Qg = g_qkv + (size_t)b*LL*384;
    const float* Kg = Qg + 128;
    const float* Vg = Qg + 256;
    const float* Rn = g_Rn + (size_t)b*LL*LL;
    const float* mk = mask + (size_t)b*LL;
    const float scale = 0.08838834764831845f;  // 1/sqrt(128)

    // load Q tile once: [128 k][64 q]
    #pragma unroll
    for (int rep = 0; rep < 8; rep++) {
        int idx = rep*256 + tid;
        int q = idx>>5, k4 = idx&31;
        float4 qv = *(const float4*)&Qg[(size_t)(i0+q)*384 + k4*4];
        Qs[(k4*4+0)*68+q]=qv.x; Qs[(k4*4+1)*68+q]=qv.y;
        Qs[(k4*4+2)*68+q]=qv.z; Qs[(k4*4+3)*68+q]=qv.w;
    }
    __syncthreads();

    float Oacc[4][8] = {};
    float mrow[4], lrow[4];
    #pragma unroll
    for (int u = 0; u < 4; u++) { mrow[u] = -1e30f; lrow[u] = 0.f; }

    for (int kt = 0; kt < 8; kt++) {
        // ---- S = Q K^T  (64q x 128k) ----
        float acc[4][8] = {};
        for (int kc = 0; kc < 4; kc++) {
            __syncthreads();
            #pragma unroll
            for (int rep = 0; rep < 4; rep++) {
                int idx = rep*256 + tid;
                int key = idx>>3, k4 = idx&7;
                float4 kv = *(const float4*)&Kg[(size_t)(kt*128+key)*384 + kc*32 + k4*4];
                Ks[(k4*4+0)*132+key]=kv.x; Ks[(k4*4+1)*132+key]=kv.y;
                Ks[(k4*4+2)*132+key]=kv.z; Ks[(k4*4+3)*132+key]=kv.w;
            }
            __syncthreads();
            #pragma unroll
            for (int kk = 0; kk < 32; kk++) {
                float4 a4 = *(const float4*)&Qs[(kc*32+kk)*68 + ty*4];
                float4 b0 = *(const float4*)&Ks[kk*132 + tx*8];
                float4 b1 = *(const float4*)&Ks[kk*132 + tx*8 + 4];
                float a[4] = {a4.x,a4.y,a4.z,a4.w};
                float bb[8] = {b0.x,b0.y,b0.z,b0.w,b1.x,b1.y,b1.z,b1.w};
                #pragma unroll
                for (int u = 0; u < 4; u++)
                    #pragma unroll
                    for (int v = 0; v < 8; v++) acc[u][v] += a[u]*bb[v];
            }
        }
        // ---- bias + mask + online softmax ----
        float mkv[8];
        *(float4*)&mkv[0] = *(const float4*)&mk[kt*128 + tx*8];
        *(float4*)&mkv[4] = *(const float4*)&mk[kt*128 + tx*8 + 4];
        #pragma unroll
        for (int u = 0; u < 4; u++) {
            float bb[8];
            *(float4*)&bb[0] = *(const float4*)&Rn[(size_t)(i0+ty*4+u)*LL + kt*128 + tx*8];
            *(float4*)&bb[4] = *(const float4*)&Rn[(size_t)(i0+ty*4+u)*LL + kt*128 + tx*8 + 4];
            float rm = -1e30f;
            #pragma unroll
            for (int v = 0; v < 8; v++) {
                float xv = acc[u][v]*scale + bb[v];
                xv = (mkv[v] > 0.f) ? xv : -1e30f;
                acc[u][v] = xv; rm = fmaxf(rm, xv);
            }
            for (int o = 8; o; o >>= 1) rm = fmaxf(rm, __shfl_xor_sync(0xffffffffu, rm, o));
            float mt = fmaxf(mrow[u], rm);
            float f = __expf(mrow[u] - mt);
            mrow[u] = mt;
            float rs = 0.f;
            #pragma unroll
            for (int v = 0; v < 8; v++) { float p = __expf(acc[u][v] - mt); acc[u][v] = p; rs += p; }
            for (int o = 8; o; o >>= 1) rs += __shfl_xor_sync(0xffffffffu, rs, o);
            lrow[u] = lrow[u]*f + rs;
            #pragma unroll
            for (int dd = 0; dd < 8; dd++) Oacc[u][dd] *= f;
            *(float4*)&Ps[(ty*4+u)*132 + tx*8]     = make_float4(acc[u][0],acc[u][1],acc[u][2],acc[u][3]);
            *(float4*)&Ps[(ty*4+u)*132 + tx*8 + 4] = make_float4(acc[u][4],acc[u][5],acc[u][6],acc[u][7]);
        }
        // ---- O += P V ----
        for (int kc2 = 0; kc2 < 8; kc2++) {
            __syncthreads();
            {
                int vr = tid>>4, vc = (tid&15)*8;
                const float* vrow = &Vg[(size_t)(kt*128 + kc2*16 + vr)*384 + vc];
                *(float4*)&Vs[vr*136+vc]   = *(const float4*)vrow;
                *(float4*)&Vs[vr*136+vc+4] = *(const float4*)(vrow + 4);
            }
            __syncthreads();
            #pragma unroll
            for (int kk = 0; kk < 16; kk++) {
                float4 va = *(const float4*)&Vs[kk*136 + tx*8];
                float4 vb = *(const float4*)&Vs[kk*136 + tx*8 + 4];
                float pv[4];
                #pragma unroll
                for (int u = 0; u < 4; u++) pv[u] = Ps[(ty*4+u)*132 + kc2*16 + kk];
                #pragma unroll
                for (int u = 0; u < 4; u++) {
                    Oacc[u][0] += pv[u]*va.x; Oacc[u][1] += pv[u]*va.y;
                    Oacc[u][2] += pv[u]*va.z; Oacc[u][3] += pv[u]*va.w;
                    Oacc[u][4] += pv[u]*vb.x; Oacc[u][5] += pv[u]*vb.y;
                    Oacc[u][6] += pv[u]*vb.z; Oacc[u][7] += pv[u]*vb.w;
                }
            }
        }
    }
    // ---- epilogue ----
    #pragma unroll
    for (int u = 0; u < 4; u++) {
        float inv = 1.f / lrow[u];
        float* orow = &g_sa[((size_t)b*LL + i0 + ty*4 + u)*DM + tx*8];
        *(float4*)orow       = make_float4(Oacc[u][0]*inv, Oacc[u][1]*inv, Oacc[u][2]*inv, Oacc[u][3]*inv);
        *(float4*)(orow + 4) = make_float4(Oacc[u][4]*inv, Oacc[u][5]*inv, Oacc[u][6]*inv, Oacc[u][7]*inv);
    }
}

// ---------------- 9: residual + layernorm ----------------
__global__ void ln_kernel(const float* __restrict__ a, const float* __restrict__ bsrc,
                          const float* __restrict__ g, const float* __restrict__ beta,
                          float* __restrict__ out) {
    int row = blockIdx.x, t = threadIdx.x;
    float x = a[(size_t)row*DM + t] + bsrc[(size_t)row*DM + t];
    float s = x, q = x*x;
    for (int o = 16; o; o >>= 1) {
        s += __shfl_xor_sync(0xffffffffu, s, o);
        q += __shfl_xor_sync(0xffffffffu, q, o);
    }
    __shared__ float ss[4], qq[4];
    if ((t & 31) == 0) { ss[t >> 5] = s; qq[t >> 5] = q; }
    __syncthreads();
    s = ss[0]+ss[1]+ss[2]+ss[3];
    q = qq[0]+qq[1]+qq[2]+qq[3];
    float m = s * (1.f/128.f);
    float v = q * (1.f/128.f) - m*m;
    out[(size_t)row*DM + t] = (x - m) * rsqrtf(v + 1e-5f) * g[t] + beta[t];
}

// ---------------- 10: final projection 128->16 (masked) ----------------
__global__ void out_kernel(const float* __restrict__ w_lin, const float* __restrict__ mask,
                           float* __restrict__ dout) {
    int row = blockIdx.x, t = threadIdx.x;
    __shared__ float hs[128];
    hs[t] = g_h2[(size_t)row*DM + t];
    __syncthreads();
    if (t < 16) {
        float s = 0.f;
        #pragma unroll
        for (int d = 0; d < 128; d++) s += hs[d] * w_lin[t*128 + d];
        dout[(size_t)row*16 + t] = s * mask[row];
    }
}

// ---------------- 11: length = sum(mask, axis=1) ----------------
__global__ void len_kernel(const float* __restrict__ mask, float* __restrict__ dout) {
    int b = blockIdx.x, t = threadIdx.x;
    float s = mask[(size_t)b*LL + t];
    for (int o = 16; o; o >>= 1) s += __shfl_xor_sync(0xffffffffu, s, o);
    __shared__ float ws[32];
    if ((t & 31) == 0) ws[t >> 5] = s;
    __syncthreads();
    if (t == 0) {
        float tot = 0.f;
        for (int w = 0; w < 32; w++) tot += ws[w];
        dout[(size_t)NB*LL*16 + b] = tot;
    }
}

extern "C" void kernel_launch(void* const* d_in, const int* in_sizes, int n_in,
                              void* d_out, int out_size) {
    const float* x      = (const float*)d_in[0];
    const float* mask   = (const float*)d_in[1];
    const float* conv_w = (const float*)d_in[2];
    const float* conv_b = (const float*)d_in[3];
    const float* w_in   = (const float*)d_in[4];
    const float* b_in   = (const float*)d_in[5];
    const float* w_out  = (const float*)d_in[6];
    const float* b_out  = (const float*)d_in[7];
    const float* w_ff1  = (const float*)d_in[8];
    const float* b_ff1  = (const float*)d_in[9];
    const float* w_ff2  = (const float*)d_in[10];
    const float* b_ff2  = (const float*)d_in[11];
    const float* ln1_g  = (const float*)d_in[12];
    const float* ln1_b  = (const float*)d_in[13];
    const float* ln2_g  = (const float*)d_in[14];
    const float* ln2_b  = (const float*)d_in[15];
    const float* w_lin  = (const float*)d_in[16];
    float* dout = (float*)d_out;

    float* ph;   cudaGetSymbolAddress((void**)&ph,   g_h);
    float* pqkv; cudaGetSymbolAddress((void**)&pqkv, g_qkv);
    float* psa;  cudaGetSymbolAddress((void**)&psa,  g_sa);
    float* ptmp; cudaGetSymbolAddress((void**)&ptmp, g_tmp);
    float* ph1;  cudaGetSymbolAddress((void**)&ph1,  g_h1);
    float* pff;  cudaGetSymbolAddress((void**)&pff,  g_ff);
    float* ph2;  cudaGetSymbolAddress((void**)&ph2,  g_h2);

    cudaFuncSetAttribute(flash_kernel, cudaFuncAttributeMaxDynamicSharedMemorySize, FLASH_SMEM);

    prep_wp<<<1, 128>>>(conv_w);
    conv_kernel<<<dim3(64, 32), 128>>>(x, conv_b, mask);
    norm2_kernel<<<NB*LL, 128>>>();
    d2_kernel<<<dim3(16, 8, NB), 256>>>();
    softdtw_kernel<<<NB, 1024>>>();
    normalize_kernel<<<dim3(32, 32, NB), dim3(32, 32)>>>();
    gemm_nt_kernel<<<dim3(6, 512), 256>>>(ph, w_in, b_in, pqkv, 384, 0);
    flash_kernel<<<dim3(16, NB), 256, FLASH_SMEM>>>(mask);
    gemm_nt_kernel<<<dim3(2, 512), 256>>>(psa, w_out, b_out, ptmp, 128, 0);
    ln_kernel<<<NB*LL, 128>>>(ph, ptmp, ln1_g, ln1_b, ph1);
    gemm_nt_kernel<<<dim3(2, 512), 256>>>(ph1, w_ff1, b_ff1, pff, 128, 1);
    gemm_nt_kernel<<<dim3(2, 512), 256>>>(pff, w_ff2, b_ff2, ptmp, 128, 0);
    ln_kernel<<<NB*LL, 128>>>(ph1, ptmp, ln2_g, ln2_b, ph2);
    out_kernel<<<NB*LL, 128>>>(w_lin, mask, dout);
    len_kernel<<<NB, 1024>>>(mask, dout);
}

// round 9
// speedup vs baseline: 1.3093x; 1.0878x over previous
#include <cuda_runtime.h>
#include <math.h>

#define NB 32
#define LL 1024
#define DM 128
#define TT 4095
#define NDIAG 2047
#define DSTRIDE ((size_t)NDIAG*LL)
#define INFV __int_as_float(0x7f800000)

// ---------------- device scratch ----------------
__device__ float g_wp[DM*12*7];
__device__ float g_h[(size_t)NB*LL*DM];
__device__ float g_norm2[NB*LL];
__device__ float g_Dskew[(size_t)NB*NDIAG*LL];   // D, then R in place (skewed)
__device__ float g_Rmin[NB];
__device__ float g_Rmax[NB];
__device__ float g_Rn[(size_t)NB*LL*LL];         // normalized R (attention bias)
__device__ float g_qkv[(size_t)NB*LL*384];
__device__ float g_sa[(size_t)NB*LL*DM];
__device__ float g_tmp[(size_t)NB*LL*DM];
__device__ float g_h1[(size_t)NB*LL*DM];
__device__ float g_ff[(size_t)NB*LL*DM];
__device__ float g_h2[(size_t)NB*LL*DM];

// ---------------- 0: fold conv+avgpool weights ----------------
__global__ void prep_wp(const float* __restrict__ conv_w) {
    int d = threadIdx.x;
    for (int c = 0; c < 12; c++)
        for (int p = 0; p < 7; p++) {
            float s = 0.f;
            int klo = p - 3 > 0 ? p - 3 : 0;
            int khi = p < 3 ? p : 3;
            for (int k = klo; k <= khi; k++) s += conv_w[(d*12 + c)*4 + k];
            g_wp[(d*12 + c)*7 + p] = 0.25f * s;
        }
}

// ---------------- 1: conv+pool+relu+mask -> h[B,L,128] ----------------
__global__ void conv_kernel(const float* __restrict__ x, const float* __restrict__ conv_b,
                            const float* __restrict__ mask) {
    int b = blockIdx.y, l0 = blockIdx.x * 16, d = threadIdx.x;
    __shared__ float xs[12][68];
    __shared__ float wps[128][85];
    for (int i = d; i < 128*84; i += 128) { wps[i/84][i%84] = g_wp[i]; }
    for (int i = d; i < 12*67; i += 128) {
        int c = i / 67, t = i % 67;
        int xi = 4*l0 - 2 + t;
        xs[c][t] = (xi >= 0 && xi < TT) ? x[((size_t)b*12 + c)*TT + xi] : 0.f;
    }
    __syncthreads();
    float bb = conv_b[d];
    for (int ll = 0; ll < 16; ll++) {
        float acc = bb;
        #pragma unroll
        for (int c = 0; c < 12; c++)
            #pragma unroll
            for (int p = 0; p < 7; p++)
                acc += xs[c][4*ll + p] * wps[d][c*7 + p];
        float hv = fmaxf(acc, 0.f) * mask[b*LL + l0 + ll];
        g_h[((size_t)b*LL + l0 + ll)*DM + d] = hv;
    }
}

// ---------------- 2: row squared norms ----------------
__global__ void norm2_kernel() {
    int row = blockIdx.x, t = threadIdx.x;
    float v = g_h[(size_t)row*DM + t];
    float s = v * v;
    for (int o = 16; o; o >>= 1) s += __shfl_down_sync(0xffffffffu, s, o);
    __shared__ float ws[4];
    if ((t & 31) == 0) ws[t >> 5] = s;
    __syncthreads();
    if (t == 0) g_norm2[row] = ws[0] + ws[1] + ws[2] + ws[3];
}

// ---------------- 3: pairwise D2 (128x64 tile, 8x4 microtile) -> skewed ----------------
__global__ void __launch_bounds__(256) d2_kernel() {
    int b = blockIdx.z, i0 = blockIdx.y*128, j0 = blockIdx.x*64;
    __shared__ float As[16][132], Bs[16][68];
    __shared__ float Cs[128][66];
    __shared__ float na[128], ns[64];
    int tid = threadIdx.x, ty = tid>>4, tx = tid&15;
    const float* A  = g_h;
    const float* Bm = g_h + (size_t)b*LL*DM;
    float acc[8][4] = {};
    for (int kc = 0; kc < 8; kc++) {
        __syncthreads();
        #pragma unroll
        for (int rep = 0; rep < 2; rep++) {
            int idx = rep*256 + tid;
            int i = idx>>2, k4 = idx&3;
            float4 av = *(const float4*)&A[(size_t)(i0+i)*DM + kc*16 + k4*4];
            As[k4*4+0][i]=av.x; As[k4*4+1][i]=av.y; As[k4*4+2][i]=av.z; As[k4*4+3][i]=av.w;
        }
        {
            int jcol = tid>>2, k4 = tid&3;
            float4 bv = *(const float4*)&Bm[(size_t)(j0+jcol)*DM + kc*16 + k4*4];
            Bs[k4*4+0][jcol]=bv.x; Bs[k4*4+1][jcol]=bv.y; Bs[k4*4+2][jcol]=bv.z; Bs[k4*4+3][jcol]=bv.w;
        }
        __syncthreads();
        #pragma unroll
        for (int kk = 0; kk < 16; kk++) {
            float4 a0 = *(const float4*)&As[kk][ty*8];
            float4 a1 = *(const float4*)&As[kk][ty*8+4];
            float4 b4 = *(const float4*)&Bs[kk][tx*4];
            float a[8] = {a0.x,a0.y,a0.z,a0.w,a1.x,a1.y,a1.z,a1.w};
            float bb[4] = {b4.x,b4.y,b4.z,b4.w};
            #pragma unroll
            for (int u = 0; u < 8; u++)
                #pragma unroll
                for (int v = 0; v < 4; v++) acc[u][v] += a[u]*bb[v];
        }
    }
    __syncthreads();
    if (tid < 128) na[tid] = g_norm2[i0 + tid];
    else if (tid < 192) ns[tid-128] = g_norm2[b*LL + j0 + tid - 128];
    __syncthreads();
    #pragma unroll
    for (int u = 0; u < 8; u++)
        #pragma unroll
        for (int v = 0; v < 4; v++)
            Cs[ty*8+u][tx*4+v] = na[ty*8+u] + ns[tx*4+v] - 2.f*acc[u][v];
    __syncthreads();
    float* Dk = g_Dskew + (size_t)b*DSTRIDE;
    for (int kb = 0; kb < 192; kb += 4) {
        int kk = kb + (tid >> 6);
        int jo = tid & 63;
        if (kk < 191) {
            int io = kk - jo;
            if (io >= 0 && io < 128) {
                int k = i0 + j0 + kk;
                Dk[(size_t)k*LL + i0 + io] = Cs[io][jo];
            }
        }
    }
}

// ---------------- 4: soft-DTW wavefront (R in place) ----------------
__global__ void __launch_bounds__(1024) softdtw_kernel() {
    int b = blockIdx.x, i = threadIdx.x;
    __shared__ float s0[1024], s1[1024], s2[1024];
    __shared__ float rmn[32], rmx[32];
    float *prev2 = s0, *prev1 = s1, *cur = s2;
    prev2[i] = INFV; prev1[i] = INFV;
    float rprev = INFV;
    float* Dk = g_Dskew + (size_t)b*DSTRIDE;
    float vmin = INFV, vmax = -INFV;
    const float cExp = 0.28853900817779268f;   // 1/(gamma*ln2), gamma=5
    const float cLog = 3.4657359027997265f;    // gamma*ln2
    float dbuf[8];
    #pragma unroll
    for (int p = 0; p < 8; p++) dbuf[p] = Dk[(size_t)p*LL + i];
    __syncthreads();
    for (int kb = 0; kb < 2048; kb += 8) {
        #pragma unroll
        for (int p = 0; p < 8; p++) {
            int k = kb + p;
            if (k >= NDIAG) break;
            float d = dbuf[p];
            if (k + 8 < NDIAG) dbuf[p] = Dk[(size_t)(k+8)*LL + i];
            float r_l = rprev;
            float r_u, r_ul;
            if (i == 0) { r_u = INFV; r_ul = (k == 0) ? 0.f : INFV; }
            else        { r_u = prev1[i-1]; r_ul = prev2[i-1]; }
            int j = k - i;
            float rv;
            if (j >= 0 && j < LL) {
                float m = fminf(r_ul, fminf(r_u, r_l));
                float s = exp2f((m - r_ul)*cExp) + exp2f((m - r_u)*cExp) + exp2f((m - r_l)*cExp);
                rv = d + m - cLog * __log2f(s);
                cur[i] = rv;
                Dk[(size_t)k*LL + i] = rv;
                vmin = fminf(vmin, rv); vmax = fmaxf(vmax, rv);
            } else { rv = INFV; cur[i] = INFV; }
            rprev = rv;
            __syncthreads();
            float* t = prev2; prev2 = prev1; prev1 = cur; cur = t;
        }
    }
    for (int o = 16; o; o >>= 1) {
        vmin = fminf(vmin, __shfl_down_sync(0xffffffffu, vmin, o));
        vmax = fmaxf(vmax, __shfl_down_sync(0xffffffffu, vmax, o));
    }
    if ((i & 31) == 0) { rmn[i >> 5] = vmin; rmx[i >> 5] = vmax; }
    __syncthreads();
    if (i < 32) {
        vmin = rmn[i]; vmax = rmx[i];
        for (int o = 16; o; o >>= 1) {
            vmin = fminf(vmin, __shfl_down_sync(0xffffffffu, vmin, o));
            vmax = fmaxf(vmax, __shfl_down_sync(0xffffffffu, vmax, o));
        }
        if (i == 0) { g_Rmin[b] = vmin; g_Rmax[b] = vmax; }
    }
}

// ---------------- 5: unskew + minmax-normalize -> Rn[b][i][j] ----------------
__global__ void normalize_kernel() {
    int b = blockIdx.z, i0 = blockIdx.y*32, j0 = blockIdx.x*32;
    __shared__ float s[63*33];
    int tid = threadIdx.y*32 + threadIdx.x;
    float mn = g_Rmin[b];
    float inv = 1.f / (g_Rmax[b] - mn);
    const float* Rk = g_Dskew + (size_t)b*DSTRIDE;
    for (int idx = tid; idx < 63*32; idx += 1024) {
        int r = idx >> 5, c = idx & 31;
        s[r*33 + c] = Rk[(size_t)(i0 + j0 + r)*LL + i0 + c];
    }
    __syncthreads();
    float v = s[(threadIdx.y + threadIdx.x)*33 + threadIdx.y];
    g_Rn[(size_t)b*LL*LL + (size_t)(i0 + threadIdx.y)*LL + j0 + threadIdx.x] = (v - mn)*inv + 1.f;
}

// ---------------- generic NT GEMM (128x64 tile, 8x4 microtile): C=A*B^T (+bias)(relu) ----------------
__global__ void __launch_bounds__(256) gemm_nt_kernel(const float* __restrict__ A,
                               const float* __restrict__ Bw,
                               const float* __restrict__ bias, float* __restrict__ C,
                               int N, int relu) {
    int m0 = blockIdx.y*128, n0 = blockIdx.x*64;
    __shared__ float As[16][132], Bs[16][68];
    int tid = threadIdx.x, ty = tid>>4, tx = tid&15;
    float acc[8][4] = {};
    for (int kc = 0; kc < 8; kc++) {
        __syncthreads();
        #pragma unroll
        for (int rep = 0; rep < 2; rep++) {
            int idx = rep*256 + tid;
            int i = idx>>2, k4 = idx&3;
            float4 av = *(const float4*)&A[(size_t)(m0+i)*128 + kc*16 + k4*4];
            As[k4*4+0][i]=av.x; As[k4*4+1][i]=av.y; As[k4*4+2][i]=av.z; As[k4*4+3][i]=av.w;
        }
        {
            int jcol = tid>>2, k4 = tid&3;
            float4 bv = *(const float4*)&Bw[(size_t)(n0+jcol)*128 + kc*16 + k4*4];
            Bs[k4*4+0][jcol]=bv.x; Bs[k4*4+1][jcol]=bv.y; Bs[k4*4+2][jcol]=bv.z; Bs[k4*4+3][jcol]=bv.w;
        }
        __syncthreads();
        #pragma unroll
        for (int kk = 0; kk < 16; kk++) {
            float4 a0 = *(const float4*)&As[kk][ty*8];
            float4 a1 = *(const float4*)&As[kk][ty*8+4];
            float4 b4 = *(const float4*)&Bs[kk][tx*4];
            float a[8] = {a0.x,a0.y,a0.z,a0.w,a1.x,a1.y,a1.z,a1.w};
            float bb[4] = {b4.x,b4.y,b4.z,b4.w};
            #pragma unroll
            for (int u = 0; u < 8; u++)
                #pragma unroll
                for (int v = 0; v < 4; v++) acc[u][v] += a[u]*bb[v];
        }
    }
    #pragma unroll
    for (int u = 0; u < 8; u++) {
        float o[4];
        #pragma unroll
        for (int v = 0; v < 4; v++) {
            int n = n0 + tx*4 + v;
            float val = acc[u][v] + (bias ? bias[n] : 0.f);
            if (relu) val = fmaxf(val, 0.f);
            o[v] = val;
        }
        *(float4*)&C[(size_t)(m0 + ty*8 + u)*N + n0 + tx*4] = make_float4(o[0],o[1],o[2],o[3]);
    }
}

// ---------------- 6: flash attention v3 (64q x 128k, 8x8 microtile, 128 thr) ----------------
#define FLASH_SMEM ((128*68 + 32*132 + 16*136 + 64*132)*4)
__global__ void __launch_bounds__(128) flash_kernel(const float* __restrict__ mask) {
    extern __shared__ float sm[];
    float* Qs = sm;                            // [128 k][68]  k-major
    float* Ks = sm + 128*68;                   // [32 k][132]  k-major
    float* Vs = sm + 128*68 + 32*132;          // [16 key][136] d-major
    float* Ps = sm + 128*68 + 32*132 + 16*136; // [64 q][132]
    int b = blockIdx.y, i0 = blockIdx.x*64;
    int tid = threadIdx.x, ty = tid>>4, tx = tid&15;
    const float* Qg = g_qkv + (size_t)b*LL*384;
    const float* Kg = Qg + 128;
    const float* Vg = Qg + 256;
    const float* Rn = g_Rn + (size_t)b*LL*LL;
    const float* mk = mask + (size_t)b*LL;
    const float scale = 0.08838834764831845f;  // 1/sqrt(128)

    // load Q tile once: [128 k][64 q]
    #pragma unroll
    for (int rep = 0; rep < 16; rep++) {
        int idx = rep*128 + tid;
        int q = idx>>5, k4 = idx&31;
        float4 qv = *(const float4*)&Qg[(size_t)(i0+q)*384 + k4*4];
        Qs[(k4*4+0)*68+q]=qv.x; Qs[(k4*4+1)*68+q]=qv.y;
        Qs[(k4*4+2)*68+q]=qv.z; Qs[(k4*4+3)*68+q]=qv.w;
    }
    __syncthreads();

    float Oacc[8][8] = {};
    float mrow[8], lrow[8];
    #pragma unroll
    for (int u = 0; u < 8; u++) { mrow[u] = -1e30f; lrow[u] = 0.f; }

    for (int kt = 0; kt < 8; kt++) {
        // ---- S = Q K^T  (64q x 128k) ----
        float acc[8][8] = {};
        for (int kc = 0; kc < 4; kc++) {
            __syncthreads();
            #pragma unroll
            for (int rep = 0; rep < 8; rep++) {
                int idx = rep*128 + tid;
                int key = idx>>3, k4 = idx&7;
                float4 kv = *(const float4*)&Kg[(size_t)(kt*128+key)*384 + kc*32 + k4*4];
                Ks[(k4*4+0)*132+key]=kv.x; Ks[(k4*4+1)*132+key]=kv.y;
                Ks[(k4*4+2)*132+key]=kv.z; Ks[(k4*4+3)*132+key]=kv.w;
            }
            __syncthreads();
            #pragma unroll
            for (int kk = 0; kk < 32; kk++) {
                float4 a0 = *(const float4*)&Qs[(kc*32+kk)*68 + ty*8];
                float4 a1 = *(const float4*)&Qs[(kc*32+kk)*68 + ty*8 + 4];
                float4 b0 = *(const float4*)&Ks[kk*132 + tx*8];
                float4 b1 = *(const float4*)&Ks[kk*132 + tx*8 + 4];
                float a[8] = {a0.x,a0.y,a0.z,a0.w,a1.x,a1.y,a1.z,a1.w};
                float bb[8] = {b0.x,b0.y,b0.z,b0.w,b1.x,b1.y,b1.z,b1.w};
                #pragma unroll
                for (int u = 0; u < 8; u++)
                    #pragma unroll
                    for (int v = 0; v < 8; v++) acc[u][v] += a[u]*bb[v];
            }
        }
        // ---- bias + mask + online softmax ----
        float mkv[8];
        *(float4*)&mkv[0] = *(const float4*)&mk[kt*128 + tx*8];
        *(float4*)&mkv[4] = *(const float4*)&mk[kt*128 + tx*8 + 4];
        #pragma unroll
        for (int u = 0; u < 8; u++) {
            float bb[8];
            *(float4*)&bb[0] = *(const float4*)&Rn[(size_t)(i0+ty*8+u)*LL + kt*128 + tx*8];
            *(float4*)&bb[4] = *(const float4*)&Rn[(size_t)(i0+ty*8+u)*LL + kt*128 + tx*8 + 4];
            float rm = -1e30f;
            #pragma unroll
            for (int v = 0; v < 8; v++) {
                float xv = acc[u][v]*scale + bb[v];
                xv = (mkv[v] > 0.f) ? xv : -1e30f;
                acc[u][v] = xv; rm = fmaxf(rm, xv);
            }
            for (int o = 8; o; o >>= 1) rm = fmaxf(rm, __shfl_xor_sync(0xffffffffu, rm, o));
            float mt = fmaxf(mrow[u], rm);
            float f = __expf(mrow[u] - mt);
            mrow[u] = mt;
            float rs = 0.f;
            #pragma unroll
            for (int v = 0; v < 8; v++) { float p = __expf(acc[u][v] - mt); acc[u][v] = p; rs += p; }
            for (int o = 8; o; o >>= 1) rs += __shfl_xor_sync(0xffffffffu, rs, o);
            lrow[u] = lrow[u]*f + rs;
            #pragma unroll
            for (int dd = 0; dd < 8; dd++) Oacc[u][dd] *= f;
            *(float4*)&Ps[(ty*8+u)*132 + tx*8]     = make_float4(acc[u][0],acc[u][1],acc[u][2],acc[u][3]);
            *(float4*)&Ps[(ty*8+u)*132 + tx*8 + 4] = make_float4(acc[u][4],acc[u][5],acc[u][6],acc[u][7]);
        }
        // ---- O += P V ----
        for (int kc2 = 0; kc2 < 8; kc2++) {
            __syncthreads();
            #pragma unroll
            for (int rep = 0; rep < 4; rep++) {
                int idx = rep*128 + tid;
                int vr = idx>>5, vc4 = idx&31;
                *(float4*)&Vs[vr*136 + vc4*4] =
                    *(const float4*)&Vg[(size_t)(kt*128 + kc2*16 + vr)*384 + vc4*4];
            }
            __syncthreads();
            #pragma unroll
            for (int kk = 0; kk < 16; kk++) {
                float4 va = *(const float4*)&Vs[kk*136 + tx*8];
                float4 vb = *(const float4*)&Vs[kk*136 + tx*8 + 4];
                float pv[8];
                #pragma unroll
                for (int u = 0; u < 8; u++) pv[u] = Ps[(ty*8+u)*132 + kc2*16 + kk];
                #pragma unroll
                for (int u = 0; u < 8; u++) {
                    Oacc[u][0] += pv[u]*va.x; Oacc[u][1] += pv[u]*va.y;
                    Oacc[u][2] += pv[u]*va.z; Oacc[u][3] += pv[u]*va.w;
                    Oacc[u][4] += pv[u]*vb.x; Oacc[u][5] += pv[u]*vb.y;
                    Oacc[u][6] += pv[u]*vb.z; Oacc[u][7] += pv[u]*vb.w;
                }
            }
        }
    }
    // ---- epilogue ----
    #pragma unroll
    for (int u = 0; u < 8; u++) {
        float inv = 1.f / lrow[u];
        float* orow = &g_sa[((size_t)b*LL + i0 + ty*8 + u)*DM + tx*8];
        *(float4*)orow       = make_float4(Oacc[u][0]*inv, Oacc[u][1]*inv, Oacc[u][2]*inv, Oacc[u][3]*inv);
        *(float4*)(orow + 4) = make_float4(Oacc[u][4]*inv, Oacc[u][5]*inv, Oacc[u][6]*inv, Oacc[u][7]*inv);
    }
}

// ---------------- 9: residual + layernorm ----------------
__global__ void ln_kernel(const float* __restrict__ a, const float* __restrict__ bsrc,
                          const float* __restrict__ g, const float* __restrict__ beta,
                          float* __restrict__ out) {
    int row = blockIdx.x, t = threadIdx.x;
    float x = a[(size_t)row*DM + t] + bsrc[(size_t)row*DM + t];
    float s = x, q = x*x;
    for (int o = 16; o; o >>= 1) {
        s += __shfl_xor_sync(0xffffffffu, s, o);
        q += __shfl_xor_sync(0xffffffffu, q, o);
    }
    __shared__ float ss[4], qq[4];
    if ((t & 31) == 0) { ss[t >> 5] = s; qq[t >> 5] = q; }
    __syncthreads();
    s = ss[0]+ss[1]+ss[2]+ss[3];
    q = qq[0]+qq[1]+qq[2]+qq[3];
    float m = s * (1.f/128.f);
    float v = q * (1.f/128.f) - m*m;
    out[(size_t)row*DM + t] = (x - m) * rsqrtf(v + 1e-5f) * g[t] + beta[t];
}

// ---------------- 10: final projection 128->16 (masked) ----------------
__global__ void out_kernel(const float* __restrict__ w_lin, const float* __restrict__ mask,
                           float* __restrict__ dout) {
    int row = blockIdx.x, t = threadIdx.x;
    __shared__ float hs[128];
    hs[t] = g_h2[(size_t)row*DM + t];
    __syncthreads();
    if (t < 16) {
        float s = 0.f;
        #pragma unroll
        for (int d = 0; d < 128; d++) s += hs[d] * w_lin[t*128 + d];
        dout[(size_t)row*16 + t] = s * mask[row];
    }
}

// ---------------- 11: length = sum(mask, axis=1) ----------------
__global__ void len_kernel(const float* __restrict__ mask, float* __restrict__ dout) {
    int b = blockIdx.x, t = threadIdx.x;
    float s = mask[(size_t)b*LL + t];
    for (int o = 16; o; o >>= 1) s += __shfl_xor_sync(0xffffffffu, s, o);
    __shared__ float ws[32];
    if ((t & 31) == 0) ws[t >> 5] = s;
    __syncthreads();
    if (t == 0) {
        float tot = 0.f;
        for (int w = 0; w < 32; w++) tot += ws[w];
        dout[(size_t)NB*LL*16 + b] = tot;
    }
}

extern "C" void kernel_launch(void* const* d_in, const int* in_sizes, int n_in,
                              void* d_out, int out_size) {
    const float* x      = (const float*)d_in[0];
    const float* mask   = (const float*)d_in[1];
    const float* conv_w = (const float*)d_in[2];
    const float* conv_b = (const float*)d_in[3];
    const float* w_in   = (const float*)d_in[4];
    const float* b_in   = (const float*)d_in[5];
    const float* w_out  = (const float*)d_in[6];
    const float* b_out  = (const float*)d_in[7];
    const float* w_ff1  = (const float*)d_in[8];
    const float* b_ff1  = (const float*)d_in[9];
    const float* w_ff2  = (const float*)d_in[10];
    const float* b_ff2  = (const float*)d_in[11];
    const float* ln1_g  = (const float*)d_in[12];
    const float* ln1_b  = (const float*)d_in[13];
    const float* ln2_g  = (const float*)d_in[14];
    const float* ln2_b  = (const float*)d_in[15];
    const float* w_lin  = (const float*)d_in[16];
    float* dout = (float*)d_out;

    float* ph;   cudaGetSymbolAddress((void**)&ph,   g_h);
    float* pqkv; cudaGetSymbolAddress((void**)&pqkv, g_qkv);
    float* psa;  cudaGetSymbolAddress((void**)&psa,  g_sa);
    float* ptmp; cudaGetSymbolAddress((void**)&ptmp, g_tmp);
    float* ph1;  cudaGetSymbolAddress((void**)&ph1,  g_h1);
    float* pff;  cudaGetSymbolAddress((void**)&pff,  g_ff);
    float* ph2;  cudaGetSymbolAddress((void**)&ph2,  g_h2);

    cudaFuncSetAttribute(flash_kernel, cudaFuncAttributeMaxDynamicSharedMemorySize, FLASH_SMEM);

    prep_wp<<<1, 128>>>(conv_w);
    conv_kernel<<<dim3(64, 32), 128>>>(x, conv_b, mask);
    norm2_kernel<<<NB*LL, 128>>>();
    d2_kernel<<<dim3(16, 8, NB), 256>>>();
    softdtw_kernel<<<NB, 1024>>>();
    normalize_kernel<<<dim3(32, 32, NB), dim3(32, 32)>>>();
    gemm_nt_kernel<<<dim3(6, 256), 256>>>(ph, w_in, b_in, pqkv, 384, 0);
    flash_kernel<<<dim3(16, NB), 128, FLASH_SMEM>>>(mask);
    gemm_nt_kernel<<<dim3(2, 256), 256>>>(psa, w_out, b_out, ptmp, 128, 0);
    ln_kernel<<<NB*LL, 128>>>(ph, ptmp, ln1_g, ln1_b, ph1);
    gemm_nt_kernel<<<dim3(2, 256), 256>>>(ph1, w_ff1, b_ff1, pff, 128, 1);
    gemm_nt_kernel<<<dim3(2, 256), 256>>>(pff, w_ff2, b_ff2, ptmp, 128, 0);
    ln_kernel<<<NB*LL, 128>>>(ph1, ptmp, ln2_g, ln2_b, ph2);
    out_kernel<<<NB*LL, 128>>>(w_lin, mask, dout);
    len_kernel<<<NB, 1024>>>(mask, dout);
}

// round 10
// speedup vs baseline: 1.3122x; 1.0022x over previous
#include <cuda_runtime.h>
#include <math.h>

#define NB 32
#define LL 1024
#define DM 128
#define TT 4095
#define NDIAG 2047
#define DSTRIDE ((size_t)NDIAG*LL)
#define INFV __int_as_float(0x7f800000)

// ---------------- device scratch ----------------
__device__ float g_wp[DM*12*7];
__device__ float g_h[(size_t)NB*LL*DM];
__device__ float g_norm2[NB*LL];
__device__ float g_Dskew[(size_t)NB*NDIAG*LL];   // D, then R in place (skewed)
__device__ float g_Rmin[NB];
__device__ float g_Rmax[NB];
__device__ float g_Rn[(size_t)NB*LL*LL];         // normalized R (attention bias)
__device__ float g_qkv[(size_t)NB*LL*384];
__device__ float g_sa[(size_t)NB*LL*DM];
__device__ float g_tmp[(size_t)NB*LL*DM];
__device__ float g_h1[(size_t)NB*LL*DM];
__device__ float g_ff[(size_t)NB*LL*DM];
__device__ float g_h2[(size_t)NB*LL*DM];

__device__ __forceinline__ float ex2f(float x) {
    float y; asm("ex2.approx.f32 %0, %1;" : "=f"(y) : "f"(x)); return y;
}

// ---------------- 0: fold conv+avgpool weights ----------------
__global__ void prep_wp(const float* __restrict__ conv_w) {
    int d = threadIdx.x;
    for (int c = 0; c < 12; c++)
        for (int p = 0; p < 7; p++) {
            float s = 0.f;
            int klo = p - 3 > 0 ? p - 3 : 0;
            int khi = p < 3 ? p : 3;
            for (int k = klo; k <= khi; k++) s += conv_w[(d*12 + c)*4 + k];
            g_wp[(d*12 + c)*7 + p] = 0.25f * s;
        }
}

// ---------------- 1: conv+pool+relu+mask -> h[B,L,128] ----------------
__global__ void conv_kernel(const float* __restrict__ x, const float* __restrict__ conv_b,
                            const float* __restrict__ mask) {
    int b = blockIdx.y, l0 = blockIdx.x * 16, d = threadIdx.x;
    __shared__ float xs[12][68];
    __shared__ float wps[128][85];
    for (int i = d; i < 128*84; i += 128) { wps[i/84][i%84] = g_wp[i]; }
    for (int i = d; i < 12*67; i += 128) {
        int c = i / 67, t = i % 67;
        int xi = 4*l0 - 2 + t;
        xs[c][t] = (xi >= 0 && xi < TT) ? x[((size_t)b*12 + c)*TT + xi] : 0.f;
    }
    __syncthreads();
    float bb = conv_b[d];
    for (int ll = 0; ll < 16; ll++) {
        float acc = bb;
        #pragma unroll
        for (int c = 0; c < 12; c++)
            #pragma unroll
            for (int p = 0; p < 7; p++)
                acc += xs[c][4*ll + p] * wps[d][c*7 + p];
        float hv = fmaxf(acc, 0.f) * mask[b*LL + l0 + ll];
        g_h[((size_t)b*LL + l0 + ll)*DM + d] = hv;
    }
}

// ---------------- 2: row squared norms ----------------
__global__ void norm2_kernel() {
    int row = blockIdx.x, t = threadIdx.x;
    float v = g_h[(size_t)row*DM + t];
    float s = v * v;
    for (int o = 16; o; o >>= 1) s += __shfl_down_sync(0xffffffffu, s, o);
    __shared__ float ws[4];
    if ((t & 31) == 0) ws[t >> 5] = s;
    __syncthreads();
    if (t == 0) g_norm2[row] = ws[0] + ws[1] + ws[2] + ws[3];
}

// ---------------- 3: pairwise D2 (128x64 tile, 8x4 microtile) -> skewed ----------------
__global__ void __launch_bounds__(256) d2_kernel() {
    int b = blockIdx.z, i0 = blockIdx.y*128, j0 = blockIdx.x*64;
    __shared__ float As[16][132], Bs[16][68];
    __shared__ float Cs[128][66];
    __shared__ float na[128], ns[64];
    int tid = threadIdx.x, ty = tid>>4, tx = tid&15;
    const float* A  = g_h;
    const float* Bm = g_h + (size_t)b*LL*DM;
    float acc[8][4] = {};
    for (int kc = 0; kc < 8; kc++) {
        __syncthreads();
        #pragma unroll
        for (int rep = 0; rep < 2; rep++) {
            int idx = rep*256 + tid;
            int i = idx>>2, k4 = idx&3;
            float4 av = *(const float4*)&A[(size_t)(i0+i)*DM + kc*16 + k4*4];
            As[k4*4+0][i]=av.x; As[k4*4+1][i]=av.y; As[k4*4+2][i]=av.z; As[k4*4+3][i]=av.w;
        }
        {
            int jcol = tid>>2, k4 = tid&3;
            float4 bv = *(const float4*)&Bm[(size_t)(j0+jcol)*DM + kc*16 + k4*4];
            Bs[k4*4+0][jcol]=bv.x; Bs[k4*4+1][jcol]=bv.y; Bs[k4*4+2][jcol]=bv.z; Bs[k4*4+3][jcol]=bv.w;
        }
        __syncthreads();
        #pragma unroll
        for (int kk = 0; kk < 16; kk++) {
            float4 a0 = *(const float4*)&As[kk][ty*8];
            float4 a1 = *(const float4*)&As[kk][ty*8+4];
            float4 b4 = *(const float4*)&Bs[kk][tx*4];
            float a[8] = {a0.x,a0.y,a0.z,a0.w,a1.x,a1.y,a1.z,a1.w};
            float bb[4] = {b4.x,b4.y,b4.z,b4.w};
            #pragma unroll
            for (int u = 0; u < 8; u++)
                #pragma unroll
                for (int v = 0; v < 4; v++) acc[u][v] += a[u]*bb[v];
        }
    }
    __syncthreads();
    if (tid < 128) na[tid] = g_norm2[i0 + tid];
    else if (tid < 192) ns[tid-128] = g_norm2[b*LL + j0 + tid - 128];
    __syncthreads();
    #pragma unroll
    for (int u = 0; u < 8; u++)
        #pragma unroll
        for (int v = 0; v < 4; v++)
            Cs[ty*8+u][tx*4+v] = na[ty*8+u] + ns[tx*4+v] - 2.f*acc[u][v];
    __syncthreads();
    float* Dk = g_Dskew + (size_t)b*DSTRIDE;
    for (int kb = 0; kb < 192; kb += 4) {
        int kk = kb + (tid >> 6);
        int jo = tid & 63;
        if (kk < 191) {
            int io = kk - jo;
            if (io >= 0 && io < 128) {
                int k = i0 + j0 + kk;
                Dk[(size_t)k*LL + i0 + io] = Cs[io][jo];
            }
        }
    }
}

// ---------------- 4: soft-DTW wavefront (R in place) ----------------
__global__ void __launch_bounds__(1024) softdtw_kernel() {
    int b = blockIdx.x, i = threadIdx.x;
    __shared__ float s0[1024], s1[1024], s2[1024];
    __shared__ float rmn[32], rmx[32];
    float *prev2 = s0, *prev1 = s1, *cur = s2;
    prev2[i] = INFV; prev1[i] = INFV;
    float rprev = INFV;
    float* Dk = g_Dskew + (size_t)b*DSTRIDE;
    float vmin = INFV, vmax = -INFV;
    const float cExp = 0.28853900817779268f;   // 1/(gamma*ln2), gamma=5
    const float cLog = 3.4657359027997265f;    // gamma*ln2
    float dbuf[8];
    #pragma unroll
    for (int p = 0; p < 8; p++) dbuf[p] = Dk[(size_t)p*LL + i];
    __syncthreads();
    for (int kb = 0; kb < 2048; kb += 8) {
        #pragma unroll
        for (int p = 0; p < 8; p++) {
            int k = kb + p;
            if (k >= NDIAG) break;
            float d = dbuf[p];
            if (k + 8 < NDIAG) dbuf[p] = Dk[(size_t)(k+8)*LL + i];
            float r_l = rprev;
            float r_u, r_ul;
            if (i == 0) { r_u = INFV; r_ul = (k == 0) ? 0.f : INFV; }
            else        { r_u = prev1[i-1]; r_ul = prev2[i-1]; }
            int j = k - i;
            float rv;
            if (j >= 0 && j < LL) {
                float m = fminf(r_ul, fminf(r_u, r_l));
                float s = ex2f((m - r_ul)*cExp) + ex2f((m - r_u)*cExp) + ex2f((m - r_l)*cExp);
                rv = d + m - cLog * __log2f(s);
                cur[i] = rv;
                Dk[(size_t)k*LL + i] = rv;
                vmin = fminf(vmin, rv); vmax = fmaxf(vmax, rv);
            } else { rv = INFV; cur[i] = INFV; }
            rprev = rv;
            __syncthreads();
            float* t = prev2; prev2 = prev1; prev1 = cur; cur = t;
        }
    }
    for (int o = 16; o; o >>= 1) {
        vmin = fminf(vmin, __shfl_down_sync(0xffffffffu, vmin, o));
        vmax = fmaxf(vmax, __shfl_down_sync(0xffffffffu, vmax, o));
    }
    if ((i & 31) == 0) { rmn[i >> 5] = vmin; rmx[i >> 5] = vmax; }
    __syncthreads();
    if (i < 32) {
        vmin = rmn[i]; vmax = rmx[i];
        for (int o = 16; o; o >>= 1) {
            vmin = fminf(vmin, __shfl_down_sync(0xffffffffu, vmin, o));
            vmax = fmaxf(vmax, __shfl_down_sync(0xffffffffu, vmax, o));
        }
        if (i == 0) { g_Rmin[b] = vmin; g_Rmax[b] = vmax; }
    }
}

// ---------------- 5: unskew + minmax-normalize -> Rn[b][i][j] ----------------
__global__ void normalize_kernel() {
    int b = blockIdx.z, i0 = blockIdx.y*32, j0 = blockIdx.x*32;
    __shared__ float s[63*33];
    int tid = threadIdx.y*32 + threadIdx.x;
    float mn = g_Rmin[b];
    float inv = 1.f / (g_Rmax[b] - mn);
    const float* Rk = g_Dskew + (size_t)b*DSTRIDE;
    for (int idx = tid; idx < 63*32; idx += 1024) {
        int r = idx >> 5, c = idx & 31;
        s[r*33 + c] = Rk[(size_t)(i0 + j0 + r)*LL + i0 + c];
    }
    __syncthreads();
    float v = s[(threadIdx.y + threadIdx.x)*33 + threadIdx.y];
    g_Rn[(size_t)b*LL*LL + (size_t)(i0 + threadIdx.y)*LL + j0 + threadIdx.x] = (v - mn)*inv + 1.f;
}

// ---------------- generic NT GEMM (128x64 tile, 8x4 microtile): C=A*B^T (+bias)(relu) ----------------
__global__ void __launch_bounds__(256) gemm_nt_kernel(const float* __restrict__ A,
                               const float* __restrict__ Bw,
                               const float* __restrict__ bias, float* __restrict__ C,
                               int N, int relu) {
    int m0 = blockIdx.y*128, n0 = blockIdx.x*64;
    __shared__ float As[16][132], Bs[16][68];
    int tid = threadIdx.x, ty = tid>>4, tx = tid&15;
    float acc[8][4] = {};
    for (int kc = 0; kc < 8; kc++) {
        __syncthreads();
        #pragma unroll
        for (int rep = 0; rep < 2; rep++) {
            int idx = rep*256 + tid;
            int i = idx>>2, k4 = idx&3;
            float4 av = *(const float4*)&A[(size_t)(m0+i)*128 + kc*16 + k4*4];
            As[k4*4+0][i]=av.x; As[k4*4+1][i]=av.y; As[k4*4+2][i]=av.z; As[k4*4+3][i]=av.w;
        }
        {
            int jcol = tid>>2, k4 = tid&3;
            float4 bv = *(const float4*)&Bw[(size_t)(n0+jcol)*128 + kc*16 + k4*4];
            Bs[k4*4+0][jcol]=bv.x; Bs[k4*4+1][jcol]=bv.y; Bs[k4*4+2][jcol]=bv.z; Bs[k4*4+3][jcol]=bv.w;
        }
        __syncthreads();
        #pragma unroll
        for (int kk = 0; kk < 16; kk++) {
            float4 a0 = *(const float4*)&As[kk][ty*8];
            float4 a1 = *(const float4*)&As[kk][ty*8+4];
            float4 b4 = *(const float4*)&Bs[kk][tx*4];
            float a[8] = {a0.x,a0.y,a0.z,a0.w,a1.x,a1.y,a1.z,a1.w};
            float bb[4] = {b4.x,b4.y,b4.z,b4.w};
            #pragma unroll
            for (int u = 0; u < 8; u++)
                #pragma unroll
                for (int v = 0; v < 4; v++) acc[u][v] += a[u]*bb[v];
        }
    }
    #pragma unroll
    for (int u = 0; u < 8; u++) {
        float o[4];
        #pragma unroll
        for (int v = 0; v < 4; v++) {
            int n = n0 + tx*4 + v;
            float val = acc[u][v] + (bias ? bias[n] : 0.f);
            if (relu) val = fmaxf(val, 0.f);
            o[v] = val;
        }
        *(float4*)&C[(size_t)(m0 + ty*8 + u)*N + n0 + tx*4] = make_float4(o[0],o[1],o[2],o[3]);
    }
}

// ---------------- 6: flash attention v3 (64q x 128k, 8x8 microtile, 128 thr) ----------------
#define FLASH_SMEM ((128*68 + 32*132 + 16*136 + 64*132)*4)
__global__ void __launch_bounds__(128) flash_kernel(const float* __restrict__ mask) {
    extern __shared__ float sm[];
    float* Qs = sm;                            // [128 k][68]  k-major
    float* Ks = sm + 128*68;                   // [32 k][132]  k-major
    float* Vs = sm + 128*68 + 32*132;          // [16 key][136] d-major
    float* Ps = sm + 128*68 + 32*132 + 16*136; // [64 q][132]
    int b = blockIdx.y, i0 = blockIdx.x*64;
    int tid = threadIdx.x, ty = tid>>4, tx = tid&15;
    const float* Qg = g_qkv + (size_t)b*LL*384;
    const float* Kg = Qg + 128;
    const float* Vg = Qg + 256;
    const float* Rn = g_Rn + (size_t)b*LL*LL;
    const float* mk = mask + (size_t)b*LL;
    const float scale = 0.08838834764831845f;  // 1/sqrt(128)

    // load Q tile once: [128 k][64 q]
    #pragma unroll
    for (int rep = 0; rep < 16; rep++) {
        int idx = rep*128 + tid;
        int q = idx>>5, k4 = idx&31;
        float4 qv = *(const float4*)&Qg[(size_t)(i0+q)*384 + k4*4];
        Qs[(k4*4+0)*68+q]=qv.x; Qs[(k4*4+1)*68+q]=qv.y;
        Qs[(k4*4+2)*68+q]=qv.z; Qs[(k4*4+3)*68+q]=qv.w;
    }
    __syncthreads();

    float Oacc[8][8] = {};
    float mrow[8], lrow[8];
    #pragma unroll
    for (int u = 0; u < 8; u++) { mrow[u] = -1e30f; lrow[u] = 0.f; }

    for (int kt = 0; kt < 8; kt++) {
        // ---- S = Q K^T  (64q x 128k) ----
        float acc[8][8] = {};
        for (int kc = 0; kc < 4; kc++) {
            __syncthreads();
            #pragma unroll
            for (int rep = 0; rep < 8; rep++) {
                int idx = rep*128 + tid;
                int key = idx>>3, k4 = idx&7;
                float4 kv = *(const float4*)&Kg[(size_t)(kt*128+key)*384 + kc*32 + k4*4];
                Ks[(k4*4+0)*132+key]=kv.x; Ks[(k4*4+1)*132+key]=kv.y;
                Ks[(k4*4+2)*132+key]=kv.z; Ks[(k4*4+3)*132+key]=kv.w;
            }
            __syncthreads();
            #pragma unroll
            for (int kk = 0; kk < 32; kk++) {
                float4 a0 = *(const float4*)&Qs[(kc*32+kk)*68 + ty*8];
                float4 a1 = *(const float4*)&Qs[(kc*32+kk)*68 + ty*8 + 4];
                float4 b0 = *(const float4*)&Ks[kk*132 + tx*8];
                float4 b1 = *(const float4*)&Ks[kk*132 + tx*8 + 4];
                float a[8] = {a0.x,a0.y,a0.z,a0.w,a1.x,a1.y,a1.z,a1.w};
                float bb[8] = {b0.x,b0.y,b0.z,b0.w,b1.x,b1.y,b1.z,b1.w};
                #pragma unroll
                for (int u = 0; u < 8; u++)
                    #pragma unroll
                    for (int v = 0; v < 8; v++) acc[u][v] += a[u]*bb[v];
            }
        }
        // ---- bias + mask + online softmax ----
        float mkv[8];
        *(float4*)&mkv[0] = *(const float4*)&mk[kt*128 + tx*8];
        *(float4*)&mkv[4] = *(const float4*)&mk[kt*128 + tx*8 + 4];
        #pragma unroll
        for (int u = 0; u < 8; u++) {
            float bb[8];
            *(float4*)&bb[0] = *(const float4*)&Rn[(size_t)(i0+ty*8+u)*LL + kt*128 + tx*8];
            *(float4*)&bb[4] = *(const float4*)&Rn[(size_t)(i0+ty*8+u)*LL + kt*128 + tx*8 + 4];
            float rm = -1e30f;
            #pragma unroll
            for (int v = 0; v < 8; v++) {
                float xv = acc[u][v]*scale + bb[v];
                xv = (mkv[v] > 0.f) ? xv : -1e30f;
                acc[u][v] = xv; rm = fmaxf(rm, xv);
            }
            for (int o = 8; o; o >>= 1) rm = fmaxf(rm, __shfl_xor_sync(0xffffffffu, rm, o));
            float mt = fmaxf(mrow[u], rm);
            float f = __expf(mrow[u] - mt);
            mrow[u] = mt;
            float rs = 0.f;
            #pragma unroll
            for (int v = 0; v < 8; v++) { float p = __expf(acc[u][v] - mt); acc[u][v] = p; rs += p; }
            for (int o = 8; o; o >>= 1) rs += __shfl_xor_sync(0xffffffffu, rs, o);
            lrow[u] = lrow[u]*f + rs;
            #pragma unroll
            for (int dd = 0; dd < 8; dd++) Oacc[u][dd] *= f;
            *(float4*)&Ps[(ty*8+u)*132 + tx*8]     = make_float4(acc[u][0],acc[u][1],acc[u][2],acc[u][3]);
            *(float4*)&Ps[(ty*8+u)*132 + tx*8 + 4] = make_float4(acc[u][4],acc[u][5],acc[u][6],acc[u][7]);
        }
        // ---- O += P V  (vectorized P reads via kk4 blocking) ----
        for (int kc2 = 0; kc2 < 8; kc2++) {
            __syncthreads();
            #pragma unroll
            for (int rep = 0; rep < 4; rep++) {
                int idx = rep*128 + tid;
                int vr = idx>>5, vc4 = idx&31;
                *(float4*)&Vs[vr*136 + vc4*4] =
                    *(const float4*)&Vg[(size_t)(kt*128 + kc2*16 + vr)*384 + vc4*4];
            }
            __syncthreads();
            #pragma unroll
            for (int kk4 = 0; kk4 < 4; kk4++) {
                float4 pv4[8];
                #pragma unroll
                for (int u = 0; u < 8; u++)
                    pv4[u] = *(const float4*)&Ps[(ty*8+u)*132 + kc2*16 + kk4*4];
                #pragma unroll
                for (int q = 0; q < 4; q++) {
                    int kk = kk4*4 + q;
                    float4 va = *(const float4*)&Vs[kk*136 + tx*8];
                    float4 vb = *(const float4*)&Vs[kk*136 + tx*8 + 4];
                    #pragma unroll
                    for (int u = 0; u < 8; u++) {
                        float pvq = (q == 0) ? pv4[u].x : (q == 1) ? pv4[u].y
                                  : (q == 2) ? pv4[u].z : pv4[u].w;
                        Oacc[u][0] += pvq*va.x; Oacc[u][1] += pvq*va.y;
                        Oacc[u][2] += pvq*va.z; Oacc[u][3] += pvq*va.w;
                        Oacc[u][4] += pvq*vb.x; Oacc[u][5] += pvq*vb.y;
                        Oacc[u][6] += pvq*vb.z; Oacc[u][7] += pvq*vb.w;
                    }
                }
            }
        }
    }
    // ---- epilogue ----
    #pragma unroll
    for (int u = 0; u < 8; u++) {
        float inv = 1.f / lrow[u];
        float* orow = &g_sa[((size_t)b*LL + i0 + ty*8 + u)*DM + tx*8];
        *(float4*)orow       = make_float4(Oacc[u][0]*inv, Oacc[u][1]*inv, Oacc[u][2]*inv, Oacc[u][3]*inv);
        *(float4*)(orow + 4) = make_float4(Oacc[u][4]*inv, Oacc[u][5]*inv, Oacc[u][6]*inv, Oacc[u][7]*inv);
    }
}

// ---------------- 9: residual + layernorm ----------------
__global__ void ln_kernel(const float* __restrict__ a, const float* __restrict__ bsrc,
                          const float* __restrict__ g, const float* __restrict__ beta,
                          float* __restrict__ out) {
    int row = blockIdx.x, t = threadIdx.x;
    float x = a[(size_t)row*DM + t] + bsrc[(size_t)row*DM + t];
    float s = x, q = x*x;
    for (int o = 16; o; o >>= 1) {
        s += __shfl_xor_sync(0xffffffffu, s, o);
        q += __shfl_xor_sync(0xffffffffu, q, o);
    }
    __shared__ float ss[4], qq[4];
    if ((t & 31) == 0) { ss[t >> 5] = s; qq[t >> 5] = q; }
    __syncthreads();
    s = ss[0]+ss[1]+ss[2]+ss[3];
    q = qq[0]+qq[1]+qq[2]+qq[3];
    float m = s * (1.f/128.f);
    float v = q * (1.f/128.f) - m*m;
    out[(size_t)row*DM + t] = (x - m) * rsqrtf(v + 1e-5f) * g[t] + beta[t];
}

// ---------------- 10: final projection 128->16 (masked) ----------------
__global__ void out_kernel(const float* __restrict__ w_lin, const float* __restrict__ mask,
                           float* __restrict__ dout) {
    int row = blockIdx.x, t = threadIdx.x;
    __shared__ float hs[128];
    hs[t] = g_h2[(size_t)row*DM + t];
    __syncthreads();
    if (t < 16) {
        float s = 0.f;
        #pragma unroll
        for (int d = 0; d < 128; d++) s += hs[d] * w_lin[t*128 + d];
        dout[(size_t)row*16 + t] = s * mask[row];
    }
}

// ---------------- 11: length = sum(mask, axis=1) ----------------
__global__ void len_kernel(const float* __restrict__ mask, float* __restrict__ dout) {
    int b = blockIdx.x, t = threadIdx.x;
    float s = mask[(size_t)b*LL + t];
    for (int o = 16; o; o >>= 1) s += __shfl_xor_sync(0xffffffffu, s, o);
    __shared__ float ws[32];
    if ((t & 31) == 0) ws[t >> 5] = s;
    __syncthreads();
    if (t == 0) {
        float tot = 0.f;
        for (int w = 0; w < 32; w++) tot += ws[w];
        dout[(size_t)NB*LL*16 + b] = tot;
    }
}

extern "C" void kernel_launch(void* const* d_in, const int* in_sizes, int n_in,
                              void* d_out, int out_size) {
    const float* x      = (const float*)d_in[0];
    const float* mask   = (const float*)d_in[1];
    const float* conv_w = (const float*)d_in[2];
    const float* conv_b = (const float*)d_in[3];
    const float* w_in   = (const float*)d_in[4];
    const float* b_in   = (const float*)d_in[5];
    const float* w_out  = (const float*)d_in[6];
    const float* b_out  = (const float*)d_in[7];
    const float* w_ff1  = (const float*)d_in[8];
    const float* b_ff1  = (const float*)d_in[9];
    const float* w_ff2  = (const float*)d_in[10];
    const float* b_ff2  = (const float*)d_in[11];
    const float* ln1_g  = (const float*)d_in[12];
    const float* ln1_b  = (const float*)d_in[13];
    const float* ln2_g  = (const float*)d_in[14];
    const float* ln2_b  = (const float*)d_in[15];
    const float* w_lin  = (const float*)d_in[16];
    float* dout = (float*)d_out;

    float* ph;   cudaGetSymbolAddress((void**)&ph,   g_h);
    float* pqkv; cudaGetSymbolAddress((void**)&pqkv, g_qkv);
    float* psa;  cudaGetSymbolAddress((void**)&psa,  g_sa);
    float* ptmp; cudaGetSymbolAddress((void**)&ptmp, g_tmp);
    float* ph1;  cudaGetSymbolAddress((void**)&ph1,  g_h1);
    float* pff;  cudaGetSymbolAddress((void**)&pff,  g_ff);
    float* ph2;  cudaGetSymbolAddress((void**)&ph2,  g_h2);

    cudaFuncSetAttribute(flash_kernel, cudaFuncAttributeMaxDynamicSharedMemorySize, FLASH_SMEM);

    // lazily-created side stream + fork/join events (host resources only; no device mem)
    static cudaStream_t s2 = nullptr;
    static cudaEvent_t evF = nullptr, evJ = nullptr;
    if (s2 == nullptr) {
        cudaStreamCreateWithFlags(&s2, cudaStreamNonBlocking);
        cudaEventCreateWithFlags(&evF, cudaEventDisableTiming);
        cudaEventCreateWithFlags(&evJ, cudaEventDisableTiming);
    }

    prep_wp<<<1, 128>>>(conv_w);
    conv_kernel<<<dim3(64, 32), 128>>>(x, conv_b, mask);

    // fork: qkv projection + length run concurrently with the DTW chain
    cudaEventRecord(evF, 0);
    cudaStreamWaitEvent(s2, evF, 0);

    norm2_kernel<<<NB*LL, 128>>>();
    d2_kernel<<<dim3(16, 8, NB), 256>>>();
    softdtw_kernel<<<NB, 1024>>>();
    normalize_kernel<<<dim3(32, 32, NB), dim3(32, 32)>>>();

    gemm_nt_kernel<<<dim3(6, 256), 256, 0, s2>>>(ph, w_in, b_in, pqkv, 384, 0);
    len_kernel<<<NB, 1024, 0, s2>>>(mask, dout);

    // join
    cudaEventRecord(evJ, s2);
    cudaStreamWaitEvent(0, evJ, 0);

    flash_kernel<<<dim3(16, NB), 128, FLASH_SMEM>>>(mask);
    gemm_nt_kernel<<<dim3(2, 256), 256>>>(psa, w_out, b_out, ptmp, 128, 0);
    ln_kernel<<<NB*LL, 128>>>(ph, ptmp, ln1_g, ln1_b, ph1);
    gemm_nt_kernel<<<dim3(2, 256), 256>>>(ph1, w_ff1, b_ff1, pff, 128, 1);
    gemm_nt_kernel<<<dim3(2, 256), 256>>>(pff, w_ff2, b_ff2, ptmp, 128, 0);
    ln_kernel<<<NB*LL, 128>>>(ph1, ptmp, ln2_g, ln2_b, ph2);
    out_kernel<<<NB*LL, 128>>>(w_lin, mask, dout);
}

// round 14
// speedup vs baseline: 1.3624x; 1.0382x over previous
#include <cuda_runtime.h>
#include <cuda_bf16.h>
#include <cstdint>
#include <math.h>

#define NB 32
#define LL 1024
#define DM 128
#define TT 4095
#define NDIAG 2047
#define DSTRIDE ((size_t)NDIAG*LL)
#define INFV __int_as_float(0x7f800000)

// ---------------- device scratch ----------------
__device__ float g_wp[DM*12*7];
__device__ float g_h[(size_t)NB*LL*DM];
__device__ __nv_bfloat16 g_hhi[(size_t)NB*LL*DM];
__device__ __nv_bfloat16 g_hlo[(size_t)NB*LL*DM];
__device__ float g_norm2[NB*LL];
__device__ float g_Dskew[(size_t)NB*NDIAG*LL];   // D, then R in place (skewed)
__device__ float g_Rmin[NB];
__device__ float g_Rmax[NB];
__device__ float g_Rn[(size_t)NB*LL*LL];         // normalized R (attention bias)
__device__ float g_qkv[(size_t)NB*LL*384];
__device__ float g_sa[(size_t)NB*LL*DM];
__device__ float g_tmp[(size_t)NB*LL*DM];
__device__ float g_h1[(size_t)NB*LL*DM];
__device__ float g_ff[(size_t)NB*LL*DM];
__device__ float g_h2[(size_t)NB*LL*DM];

__device__ __forceinline__ float ex2f(float x) {
    float y; asm("ex2.approx.f32 %0, %1;" : "=f"(y) : "f"(x)); return y;
}
__device__ __forceinline__ uint32_t smem_u32(const void* p) {
    uint32_t a;
    asm("{ .reg .u64 t; cvta.to.shared.u64 t, %1; cvt.u32.u64 %0, t; }" : "=r"(a) : "l"(p));
    return a;
}

// ---------------- 0: fold conv+avgpool weights ----------------
__global__ void prep_wp(const float* __restrict__ conv_w) {
    int d = threadIdx.x;
    for (int c = 0; c < 12; c++)
        for (int p = 0; p < 7; p++) {
            float s = 0.f;
            int klo = p - 3 > 0 ? p - 3 : 0;
            int khi = p < 3 ? p : 3;
            for (int k = klo; k <= khi; k++) s += conv_w[(d*12 + c)*4 + k];
            g_wp[(d*12 + c)*7 + p] = 0.25f * s;
        }
}

// ---------------- 1: conv+pool+relu+mask -> h[B,L,128] ----------------
__global__ void conv_kernel(const float* __restrict__ x, const float* __restrict__ conv_b,
                            const float* __restrict__ mask) {
    int b = blockIdx.y, l0 = blockIdx.x * 16, d = threadIdx.x;
    __shared__ float xs[12][68];
    __shared__ float wps[128][85];
    for (int i = d; i < 128*84; i += 128) { wps[i/84][i%84] = g_wp[i]; }
    for (int i = d; i < 12*67; i += 128) {
        int c = i / 67, t = i % 67;
        int xi = 4*l0 - 2 + t;
        xs[c][t] = (xi >= 0 && xi < TT) ? x[((size_t)b*12 + c)*TT + xi] : 0.f;
    }
    __syncthreads();
    float bb = conv_b[d];
    for (int ll = 0; ll < 16; ll++) {
        float acc = bb;
        #pragma unroll
        for (int c = 0; c < 12; c++)
            #pragma unroll
            for (int p = 0; p < 7; p++)
                acc += xs[c][4*ll + p] * wps[d][c*7 + p];
        float hv = fmaxf(acc, 0.f) * mask[b*LL + l0 + ll];
        g_h[((size_t)b*LL + l0 + ll)*DM + d] = hv;
    }
}

// ---------------- 1b: split h into bf16 hi/lo ----------------
__global__ void cvt_kernel() {
    size_t i = (size_t)blockIdx.x*256 + threadIdx.x;
    float v = g_h[i];
    __nv_bfloat16 hi = __float2bfloat16(v);
    g_hhi[i] = hi;
    g_hlo[i] = __float2bfloat16(v - __bfloat162float(hi));
}

// ---------------- 2: row squared norms ----------------
__global__ void norm2_kernel() {
    int row = blockIdx.x, t = threadIdx.x;
    float v = g_h[(size_t)row*DM + t];
    float s = v * v;
    for (int o = 16; o; o >>= 1) s += __shfl_down_sync(0xffffffffu, s, o);
    __shared__ float ws[4];
    if ((t & 31) == 0) ws[t >> 5] = s;
    __syncthreads();
    if (t == 0) g_norm2[row] = ws[0] + ws[1] + ws[2] + ws[3];
}

// ---------------- 3: pairwise D2 via mma.sync bf16x2 (128x64 tiles) -> skewed ----------------
#define D2M_SMEM 104832

#define MMA_BF16(accv, av, bv) \
    asm volatile("mma.sync.aligned.m16n8k16.row.col.f32.bf16.bf16.f32 " \
        "{%0,%1,%2,%3}, {%4,%5,%6,%7}, {%8,%9}, {%0,%1,%2,%3};" \
        : "+f"(accv[0]), "+f"(accv[1]), "+f"(accv[2]), "+f"(accv[3]) \
        : "r"(av[0]), "r"(av[1]), "r"(av[2]), "r"(av[3]), "r"(bv[0]), "r"(bv[1]))

__global__ void __launch_bounds__(256) d2m_kernel() {
    extern __shared__ char dsm[];
    __nv_bfloat16* Ahi = (__nv_bfloat16*)dsm;        // [128][136]
    __nv_bfloat16* Alo = Ahi + 128*136;
    __nv_bfloat16* Bhi = Alo + 128*136;              // [64][136]
    __nv_bfloat16* Blo = Bhi + 64*136;
    float* nsArr = (float*)(Blo + 64*136);           // 64 floats
    int b = blockIdx.z, i0 = blockIdx.y*128, j0 = blockIdx.x*64;
    int tid = threadIdx.x, wid = tid>>5, lane = tid&31;

    for (int c = tid; c < 128*16; c += 256) {
        int r = c >> 4, ch = c & 15;
        size_t g = (size_t)(i0 + r)*DM + ch*8;
        *(uint4*)&Ahi[r*136 + ch*8] = *(const uint4*)&g_hhi[g];
        *(uint4*)&Alo[r*136 + ch*8] = *(const uint4*)&g_hlo[g];
    }
    for (int c = tid; c < 64*16; c += 256) {
        int r = c >> 4, ch = c & 15;
        size_t g = (size_t)(b*LL + j0 + r)*DM + ch*8;
        *(uint4*)&Bhi[r*136 + ch*8] = *(const uint4*)&g_hhi[g];
        *(uint4*)&Blo[r*136 + ch*8] = *(const uint4*)&g_hlo[g];
    }
    if (tid < 64) nsArr[tid] = g_norm2[b*LL + j0 + tid];
    __syncthreads();

    float acc[8][4] = {};
    int mrow = wid*16;
    // canonical ldmatrix addressing
    uint32_t aoff = (uint32_t)((mrow + (lane & 15))*136 + (lane >> 4)*8) * 2u;
    uint32_t a_hi = smem_u32(Ahi) + aoff;
    uint32_t a_lo = smem_u32(Alo) + aoff;
    uint32_t boff = (uint32_t)((lane & 7)*136 + ((lane >> 3) & 1)*8) * 2u;
    uint32_t b_hi = smem_u32(Bhi) + boff;
    uint32_t b_lo = smem_u32(Blo) + boff;

    for (int ks = 0; ks < 8; ks++) {
        uint32_t ah[4], al[4];
        asm volatile("ldmatrix.sync.aligned.m8n8.x4.shared.b16 {%0,%1,%2,%3}, [%4];"
            : "=r"(ah[0]), "=r"(ah[1]), "=r"(ah[2]), "=r"(ah[3]) : "r"(a_hi + ks*32));
        asm volatile("ldmatrix.sync.aligned.m8n8.x4.shared.b16 {%0,%1,%2,%3}, [%4];"
            : "=r"(al[0]), "=r"(al[1]), "=r"(al[2]), "=r"(al[3]) : "r"(a_lo + ks*32));
        #pragma unroll
        for (int nt = 0; nt < 8; nt++) {
            uint32_t bh[2], bl[2];
            uint32_t badd = (uint32_t)(nt*8*136)*2u + (uint32_t)ks*32u;
            asm volatile("ldmatrix.sync.aligned.m8n8.x2.shared.b16 {%0,%1}, [%2];"
                : "=r"(bh[0]), "=r"(bh[1]) : "r"(b_hi + badd));
            asm volatile("ldmatrix.sync.aligned.m8n8.x2.shared.b16 {%0,%1}, [%2];"
                : "=r"(bl[0]), "=r"(bl[1]) : "r"(b_lo + badd));
            MMA_BF16(acc[nt], ah, bh);
            MMA_BF16(acc[nt], ah, bl);
            MMA_BF16(acc[nt], al, bh);
        }
    }
    __syncthreads();   // done reading A/B smem; safe to alias with Cs

    // epilogue: d2 = na + ns - 2*dot -> Cs[128][66] (aliases Ahi/Alo region)
    float* Cs = (float*)dsm;
    int g = lane >> 2, tg = lane & 3;
    float na0 = g_norm2[i0 + mrow + g];
    float na1 = g_norm2[i0 + mrow + g + 8];
    #pragma unroll
    for (int nt = 0; nt < 8; nt++) {
        int c = nt*8 + tg*2;
        float ns0 = nsArr[c], ns1 = nsArr[c+1];
        Cs[(mrow+g)*66 + c]       = na0 + ns0 - 2.f*acc[nt][0];
        Cs[(mrow+g)*66 + c + 1]   = na0 + ns1 - 2.f*acc[nt][1];
        Cs[(mrow+g+8)*66 + c]     = na1 + ns0 - 2.f*acc[nt][2];
        Cs[(mrow+g+8)*66 + c + 1] = na1 + ns1 - 2.f*acc[nt][3];
    }
    __syncthreads();
    float* Dk = g_Dskew + (size_t)b*DSTRIDE;
    for (int kb = 0; kb < 192; kb += 4) {
        int kk = kb + (tid >> 6);
        int jo = tid & 63;
        if (kk < 191) {
            int io = kk - jo;
            if (io >= 0 && io < 128)
                Dk[(size_t)(i0 + j0 + kk)*LL + i0 + io] = Cs[io*66 + jo];
        }
    }
}

// ---------------- 4: soft-DTW wavefront (R in place, 2-exp softmin) ----------------
__global__ void __launch_bounds__(1024) softdtw_kernel() {
    int b = blockIdx.x, i = threadIdx.x;
    __shared__ float s0[1024], s1[1024], s2[1024];
    __shared__ float rmn[32], rmx[32];
    float *prev2 = s0, *prev1 = s1, *cur = s2;
    prev2[i] = INFV; prev1[i] = INFV;
    float rprev = INFV;
    float* Dk = g_Dskew + (size_t)b*DSTRIDE;
    float vmin = INFV, vmax = -INFV;
    const float cExp = 0.28853900817779268f;   // 1/(gamma*ln2), gamma=5
    const float cLog = 3.4657359027997265f;    // gamma*ln2
    float dbuf[8];
    #pragma unroll
    for (int p = 0; p < 8; p++) dbuf[p] = Dk[(size_t)p*LL + i];
    __syncthreads();
    for (int kb = 0; kb < 2048; kb += 8) {
        #pragma unroll
        for (int p = 0; p < 8; p++) {
            int k = kb + p;
            if (k >= NDIAG) break;
            float d = dbuf[p];
            if (k + 8 < NDIAG) dbuf[p] = Dk[(size_t)(k+8)*LL + i];
            float r_l = rprev;
            float r_u, r_ul;
            if (i == 0) { r_u = INFV; r_ul = (k == 0) ? 0.f : INFV; }
            else        { r_u = prev1[i-1]; r_ul = prev2[i-1]; }
            int j = k - i;
            float rv;
            if (j >= 0 && j < LL) {
                float lo  = fminf(r_u, r_l);
                float hi2 = fmaxf(r_u, r_l);
                float m   = fminf(r_ul, lo);
                float o1  = fmaxf(r_ul, lo);
                float s = 1.0f + ex2f((m - o1)*cExp) + ex2f((m - hi2)*cExp);
                rv = d + m - cLog * __log2f(s);
                cur[i] = rv;
                Dk[(size_t)k*LL + i] = rv;
                vmin = fminf(vmin, rv); vmax = fmaxf(vmax, rv);
            } else { rv = INFV; cur[i] = INFV; }
            rprev = rv;
            __syncthreads();
            float* t = prev2; prev2 = prev1; prev1 = cur; cur = t;
        }
    }
    for (int o = 16; o; o >>= 1) {
        vmin = fminf(vmin, __shfl_down_sync(0xffffffffu, vmin, o));
        vmax = fmaxf(vmax, __shfl_down_sync(0xffffffffu, vmax, o));
    }
    if ((i & 31) == 0) { rmn[i >> 5] = vmin; rmx[i >> 5] = vmax; }
    __syncthreads();
    if (i < 32) {
        vmin = rmn[i]; vmax = rmx[i];
        for (int o = 16; o; o >>= 1) {
            vmin = fminf(vmin, __shfl_down_sync(0xffffffffu, vmin, o));
            vmax = fmaxf(vmax, __shfl_down_sync(0xffffffffu, vmax, o));
        }
        if (i == 0) { g_Rmin[b] = vmin; g_Rmax[b] = vmax; }
    }
}

// ---------------- 5: unskew + minmax-normalize -> Rn[b][i][j] ----------------
__global__ void normalize_kernel() {
    int b = blockIdx.z, i0 = blockIdx.y*32, j0 = blockIdx.x*32;
    __shared__ float s[63*33];
    int tid = threadIdx.y*32 + threadIdx.x;
    float mn = g_Rmin[b];
    float inv = 1.f / (g_Rmax[b] - mn);
    const float* Rk = g_Dskew + (size_t)b*DSTRIDE;
    for (int idx = tid; idx < 63*32; idx += 1024) {
        int r = idx >> 5, c = idx & 31;
        s[r*33 + c] = Rk[(size_t)(i0 + j0 + r)*LL + i0 + c];
    }
    __syncthreads();
    float v = s[(threadIdx.y + threadIdx.x)*33 + threadIdx.y];
    g_Rn[(size_t)b*LL*LL + (size_t)(i0 + threadIdx.y)*LL + j0 + threadIdx.x] = (v - mn)*inv + 1.f;
}

// ---------------- generic NT GEMM (128x64 tile, 8x4 microtile): C=A*B^T (+bias)(relu) ----------------
__global__ void __launch_bounds__(256) gemm_nt_kernel(const float* __restrict__ A,
                               const float* __restrict__ Bw,
                               const float* __restrict__ bias, float* __restrict__ C,
                               int N, int relu) {
    int m0 = blockIdx.y*128, n0 = blockIdx.x*64;
    __shared__ float As[16][132], Bs[16][68];
    int tid = threadIdx.x, ty = tid>>4, tx = tid&15;
    float acc[8][4] = {};
    for (int kc = 0; kc < 8; kc++) {
        __syncthreads();
        #pragma unroll
        for (int rep = 0; rep < 2; rep++) {
            int idx = rep*256 + tid;
            int i = idx>>2, k4 = idx&3;
            float4 av = *(const float4*)&A[(size_t)(m0+i)*128 + kc*16 + k4*4];
            As[k4*4+0][i]=av.x; As[k4*4+1][i]=av.y; As[k4*4+2][i]=av.z; As[k4*4+3][i]=av.w;
        }
        {
            int jcol = tid>>2, k4 = tid&3;
            float4 bv = *(const float4*)&Bw[(size_t)(n0+jcol)*128 + kc*16 + k4*4];
            Bs[k4*4+0][jcol]=bv.x; Bs[k4*4+1][jcol]=bv.y; Bs[k4*4+2][jcol]=bv.z; Bs[k4*4+3][jcol]=bv.w;
        }
        __syncthreads();
        #pragma unroll
        for (int kk = 0; kk < 16; kk++) {
            float4 a0 = *(const float4*)&As[kk][ty*8];
            float4 a1 = *(const float4*)&As[kk][ty*8+4];
            float4 b4 = *(const float4*)&Bs[kk][tx*4];
            float a[8] = {a0.x,a0.y,a0.z,a0.w,a1.x,a1.y,a1.z,a1.w};
            float bb[4] = {b4.x,b4.y,b4.z,b4.w};
            #pragma unroll
            for (int u = 0; u < 8; u++)
                #pragma unroll
                for (int v = 0; v < 4; v++) acc[u][v] += a[u]*bb[v];
        }
    }
    #pragma unroll
    for (int u = 0; u < 8; u++) {
        float o[4];
        #pragma unroll
        for (int v = 0; v < 4; v++) {
            int n = n0 + tx*4 + v;
            float val = acc[u][v] + (bias ? bias[n] : 0.f);
            if (relu) val = fmaxf(val, 0.f);
            o[v] = val;
        }
        *(float4*)&C[(size_t)(m0 + ty*8 + u)*N + n0 + tx*4] = make_float4(o[0],o[1],o[2],o[3]);
    }
}

// ---------------- 6: flash attention v3 (64q x 128k, 8x8 microtile, 128 thr) ----------------
#define FLASH_SMEM ((128*68 + 32*132 + 16*136 + 64*132)*4)
__global__ void __launch_bounds__(128) flash_kernel(const float* __restrict__ mask) {
    extern __shared__ float sm[];
    float* Qs = sm;                            // [128 k][68]  k-major
    float* Ks = sm + 128*68;                   // [32 k][132]  k-major
    float* Vs = sm + 128*68 + 32*132;          // [16 key][136] d-major
    float* Ps = sm + 128*68 + 32*132 + 16*136; // [64 q][132]
    int b = blockIdx.y, i0 = blockIdx.x*64;
    int tid = threadIdx.x, ty = tid>>4, tx = tid&15;
    const float* Qg = g_qkv + (size_t)b*LL*384;
    const float* Kg = Qg + 128;
    const float* Vg = Qg + 256;
    const float* Rn = g_Rn + (size_t)b*LL*LL;
    const float* mk = mask + (size_t)b*LL;
    const float scale = 0.08838834764831845f;  // 1/sqrt(128)

    #pragma unroll
    for (int rep = 0; rep < 16; rep++) {
        int idx = rep*128 + tid;
        int q = idx>>5, k4 = idx&31;
        float4 qv = *(const float4*)&Qg[(size_t)(i0+q)*384 + k4*4];
        Qs[(k4*4+0)*68+q]=qv.x; Qs[(k4*4+1)*68+q]=qv.y;
        Qs[(k4*4+2)*68+q]=qv.z; Qs[(k4*4+3)*68+q]=qv.w;
    }
    __syncthreads();

    float Oacc[8][8] = {};
    float mrow[8], lrow[8];
    #pragma unroll
    for (int u = 0; u < 8; u++) { mrow[u] = -1e30f; lrow[u] = 0.f; }

    for (int kt = 0; kt < 8; kt++) {
        float acc[8][8] = {};
        for (int kc = 0; kc < 4; kc++) {
            __syncthreads();
            #pragma unroll
            for (int rep = 0; rep < 8; rep++) {
                int idx = rep*128 + tid;
                int key = idx>>3, k4 = idx&7;
                float4 kv = *(const float4*)&Kg[(size_t)(kt*128+key)*384 + kc*32 + k4*4];
                Ks[(k4*4+0)*132+key]=kv.x; Ks[(k4*4+1)*132+key]=kv.y;
                Ks[(k4*4+2)*132+key]=kv.z; Ks[(k4*4+3)*132+key]=kv.w;
            }
            __syncthreads();
            #pragma unroll
            for (int kk = 0; kk < 32; kk++) {
                float4 a0 = *(const float4*)&Qs[(kc*32+kk)*68 + ty*8];
                float4 a1 = *(const float4*)&Qs[(kc*32+kk)*68 + ty*8 + 4];
                float4 b0 = *(const float4*)&Ks[kk*132 + tx*8];
                float4 b1 = *(const float4*)&Ks[kk*132 + tx*8 + 4];
                float a[8] = {a0.x,a0.y,a0.z,a0.w,a1.x,a1.y,a1.z,a1.w};
                float bb[8] = {b0.x,b0.y,b0.z,b0.w,b1.x,b1.y,b1.z,b1.w};
                #pragma unroll
                for (int u = 0; u < 8; u++)
                    #pragma unroll
                    for (int v = 0; v < 8; v++) acc[u][v] += a[u]*bb[v];
            }
        }
        float mkv[8];
        *(float4*)&mkv[0] = *(const float4*)&mk[kt*128 + tx*8];
        *(float4*)&mkv[4] = *(const float4*)&mk[kt*128 + tx*8 + 4];
        #pragma unroll
        for (int u = 0; u < 8; u++) {
            float bb[8];
            *(float4*)&bb[0] = *(const float4*)&Rn[(size_t)(i0+ty*8+u)*LL + kt*128 + tx*8];
            *(float4*)&bb[4] = *(const float4*)&Rn[(size_t)(i0+ty*8+u)*LL + kt*128 + tx*8 + 4];
            float rm = -1e30f;
            #pragma unroll
            for (int v = 0; v < 8; v++) {
                float xv = acc[u][v]*scale + bb[v];
                xv = (mkv[v] > 0.f) ? xv : -1e30f;
                acc[u][v] = xv; rm = fmaxf(rm, xv);
            }
            for (int o = 8; o; o >>= 1) rm = fmaxf(rm, __shfl_xor_sync(0xffffffffu, rm, o));
            float mt = fmaxf(mrow[u], rm);
            float f = __expf(mrow[u] - mt);
            mrow[u] = mt;
            float rs = 0.f;
            #pragma unroll
            for (int v = 0; v < 8; v++) { float p = __expf(acc[u][v] - mt); acc[u][v] = p; rs += p; }
            for (int o = 8; o; o >>= 1) rs += __shfl_xor_sync(0xffffffffu, rs, o);
            lrow[u] = lrow[u]*f + rs;
            #pragma unroll
            for (int dd = 0; dd < 8; dd++) Oacc[u][dd] *= f;
            *(float4*)&Ps[(ty*8+u)*132 + tx*8]     = make_float4(acc[u][0],acc[u][1],acc[u][2],acc[u][3]);
            *(float4*)&Ps[(ty*8+u)*132 + tx*8 + 4] = make_float4(acc[u][4],acc[u][5],acc[u][6],acc[u][7]);
        }
        for (int kc2 = 0; kc2 < 8; kc2++) {
            __syncthreads();
            #pragma unroll
            for (int rep = 0; rep < 4; rep++) {
                int idx = rep*128 + tid;
                int vr = idx>>5, vc4 = idx&31;
                *(float4*)&Vs[vr*136 + vc4*4] =
                    *(const float4*)&Vg[(size_t)(kt*128 + kc2*16 + vr)*384 + vc4*4];
            }
            __syncthreads();
            #pragma unroll
            for (int kk4 = 0; kk4 < 4; kk4++) {
                float4 pv4[8];
                #pragma unroll
                for (int u = 0; u < 8; u++)
                    pv4[u] = *(const float4*)&Ps[(ty*8+u)*132 + kc2*16 + kk4*4];
                #pragma unroll
                for (int q = 0; q < 4; q++) {
                    int kk = kk4*4 + q;
                    float4 va = *(const float4*)&Vs[kk*136 + tx*8];
                    float4 vb = *(const float4*)&Vs[kk*136 + tx*8 + 4];
                    #pragma unroll
                    for (int u = 0; u < 8; u++) {
                        float pvq = (q == 0) ? pv4[u].x : (q == 1) ? pv4[u].y
                                  : (q == 2) ? pv4[u].z : pv4[u].w;
                        Oacc[u][0] += pvq*va.x; Oacc[u][1] += pvq*va.y;
                        Oacc[u][2] += pvq*va.z; Oacc[u][3] += pvq*va.w;
                        Oacc[u][4] += pvq*vb.x; Oacc[u][5] += pvq*vb.y;
                        Oacc[u][6] += pvq*vb.z; Oacc[u][7] += pvq*vb.w;
                    }
                }
            }
        }
    }
    #pragma unroll
    for (int u = 0; u < 8; u++) {
        float inv = 1.f / lrow[u];
        float* orow = &g_sa[((size_t)b*LL + i0 + ty*8 + u)*DM + tx*8];
        *(float4*)orow       = make_float4(Oacc[u][0]*inv, Oacc[u][1]*inv, Oacc[u][2]*inv, Oacc[u][3]*inv);
        *(float4*)(orow + 4) = make_float4(Oacc[u][4]*inv, Oacc[u][5]*inv, Oacc[u][6]*inv, Oacc[u][7]*inv);
    }
}

// ---------------- 9: residual + layernorm ----------------
__global__ void ln_kernel(const float* __restrict__ a, const float* __restrict__ bsrc,
                          const float* __restrict__ g, const float* __restrict__ beta,
                          float* __restrict__ out) {
    int row = blockIdx.x, t = threadIdx.x;
    float x = a[(size_t)row*DM + t] + bsrc[(size_t)row*DM + t];
    float s = x, q = x*x;
    for (int o = 16; o; o >>= 1) {
        s += __shfl_xor_sync(0xffffffffu, s, o);
        q += __shfl_xor_sync(0xffffffffu, q, o);
    }
    __shared__ float ss[4], qq[4];
    if ((t & 31) == 0) { ss[t >> 5] = s; qq[t >> 5] = q; }
    __syncthreads();
    s = ss[0]+ss[1]+ss[2]+ss[3];
    q = qq[0]+qq[1]+qq[2]+qq[3];
    float m = s * (1.f/128.f);
    float v = q * (1.f/128.f) - m*m;
    out[(size_t)row*DM + t] = (x - m) * rsqrtf(v + 1e-5f) * g[t] + beta[t];
}

// ---------------- 10: final projection 128->16 (masked) ----------------
__global__ void out_kernel(const float* __restrict__ w_lin, const float* __restrict__ mask,
                           float* __restrict__ dout) {
    int row = blockIdx.x, t = threadIdx.x;
    __shared__ float hs[128];
    hs[t] = g_h2[(size_t)row*DM + t];
    __syncthreads();
    if (t < 16) {
        float s = 0.f;
        #pragma unroll
        for (int d = 0; d < 128; d++) s += hs[d] * w_lin[t*128 + d];
        dout[(size_t)row*16 + t] = s * mask[row];
    }
}

// ---------------- 11: length = sum(mask, axis=1) ----------------
__global__ void len_kernel(const float* __restrict__ mask, float* __restrict__ dout) {
    int b = blockIdx.x, t = threadIdx.x;
    float s = mask[(size_t)b*LL + t];
    for (int o = 16; o; o >>= 1) s += __shfl_xor_sync(0xffffffffu, s, o);
    __shared__ float ws[32];
    if ((t & 31) == 0) ws[t >> 5] = s;
    __syncthreads();
    if (t == 0) {
        float tot = 0.f;
        for (int w = 0; w < 32; w++) tot += ws[w];
        dout[(size_t)NB*LL*16 + b] = tot;
    }
}

extern "C" void kernel_launch(void* const* d_in, const int* in_sizes, int n_in,
                              void* d_out, int out_size) {
    const float* x      = (const float*)d_in[0];
    const float* mask   = (const float*)d_in[1];
    const float* conv_w = (const float*)d_in[2];
    const float* conv_b = (const float*)d_in[3];
    const float* w_in   = (const float*)d_in[4];
    const float* b_in   = (const float*)d_in[5];
    const float* w_out  = (const float*)d_in[6];
    const float* b_out  = (const float*)d_in[7];
    const float* w_ff1  = (const float*)d_in[8];
    const float* b_ff1  = (const float*)d_in[9];
    const float* w_ff2  = (const float*)d_in[10];
    const float* b_ff2  = (const float*)d_in[11];
    const float* ln1_g  = (const float*)d_in[12];
    const float* ln1_b  = (const float*)d_in[13];
    const float* ln2_g  = (const float*)d_in[14];
    const float* ln2_b  = (const float*)d_in[15];
    const float* w_lin  = (const float*)d_in[16];
    float* dout = (float*)d_out;

    float* ph;   cudaGetSymbolAddress((void**)&ph,   g_h);
    float* pqkv; cudaGetSymbolAddress((void**)&pqkv, g_qkv);
    float* psa;  cudaGetSymbolAddress((void**)&psa,  g_sa);
    float* ptmp; cudaGetSymbolAddress((void**)&ptmp, g_tmp);
    float* ph1;  cudaGetSymbolAddress((void**)&ph1,  g_h1);
    float* pff;  cudaGetSymbolAddress((void**)&pff,  g_ff);
    float* ph2;  cudaGetSymbolAddress((void**)&ph2,  g_h2);

    cudaFuncSetAttribute(flash_kernel, cudaFuncAttributeMaxDynamicSharedMemorySize, FLASH_SMEM);
    cudaFuncSetAttribute(d2m_kernel, cudaFuncAttributeMaxDynamicSharedMemorySize, D2M_SMEM);

    static cudaStream_t s2 = nullptr;
    static cudaEvent_t evF = nullptr, evJ = nullptr;
    if (s2 == nullptr) {
        cudaStreamCreateWithFlags(&s2, cudaStreamNonBlocking);
        cudaEventCreateWithFlags(&evF, cudaEventDisableTiming);
        cudaEventCreateWithFlags(&evJ, cudaEventDisableTiming);
    }

    prep_wp<<<1, 128>>>(conv_w);
    conv_kernel<<<dim3(64, 32), 128>>>(x, conv_b, mask);

    cudaEventRecord(evF, 0);
    cudaStreamWaitEvent(s2, evF, 0);

    cvt_kernel<<<16384, 256>>>();
    norm2_kernel<<<NB*LL, 128>>>();
    d2m_kernel<<<dim3(16, 8, NB), 256, D2M_SMEM>>>();
    softdtw_kernel<<<NB, 1024>>>();
    normalize_kernel<<<dim3(32, 32, NB), dim3(32, 32)>>>();

    gemm_nt_kernel<<<dim3(6, 256), 256, 0, s2>>>(ph, w_in, b_in, pqkv, 384, 0);
    len_kernel<<<NB, 1024, 0, s2>>>(mask, dout);

    cudaEventRecord(evJ, s2);
    cudaStreamWaitEvent(0, evJ, 0);

    flash_kernel<<<dim3(16, NB), 128, FLASH_SMEM>>>(mask);
    gemm_nt_kernel<<<dim3(2, 256), 256>>>(psa, w_out, b_out, ptmp, 128, 0);
    ln_kernel<<<NB*LL, 128>>>(ph, ptmp, ln1_g, ln1_b, ph1);
    gemm_nt_kernel<<<dim3(2, 256), 256>>>(ph1, w_ff1, b_ff1, pff, 128, 1);
    gemm_nt_kernel<<<dim3(2, 256), 256>>>(pff, w_ff2, b_ff2, ptmp, 128, 0);
    ln_kernel<<<NB*LL, 128>>>(ph1, ptmp, ln2_g, ln2_b, ph2);
    out_kernel<<<NB*LL, 128>>>(w_lin, mask, dout);
}

// round 15
// speedup vs baseline: 1.4096x; 1.0346x over previous
#include <cuda_runtime.h>
#include <cuda_bf16.h>
#include <cstdint>
#include <math.h>

#define NB 32
#define LL 1024
#define DM 128
#define TT 4095
#define NDIAG 2047
#define DSTRIDE ((size_t)NDIAG*LL)
#define INFV __int_as_float(0x7f800000)

// ---------------- device scratch ----------------
__device__ float g_wp[DM*12*7];
__device__ float g_h[(size_t)NB*LL*DM];
__device__ __nv_bfloat16 g_hhi[(size_t)NB*LL*DM];
__device__ __nv_bfloat16 g_hlo[(size_t)NB*LL*DM];
__device__ float g_norm2[NB*LL];
__device__ float g_Dskew[(size_t)NB*NDIAG*LL];   // D, then R in place (skewed)
__device__ float g_Rmin[NB];
__device__ float g_Rmax[NB];
__device__ float g_Rn[(size_t)NB*LL*LL];         // normalized R (attention bias)
__device__ float g_qkv[(size_t)NB*LL*384];
__device__ __nv_bfloat16 g_qh[(size_t)NB*LL*384];
__device__ __nv_bfloat16 g_ql[(size_t)NB*LL*384];
__device__ float g_sa[(size_t)NB*LL*DM];
__device__ float g_tmp[(size_t)NB*LL*DM];
__device__ float g_h1[(size_t)NB*LL*DM];
__device__ float g_ff[(size_t)NB*LL*DM];
__device__ float g_h2[(size_t)NB*LL*DM];

__device__ __forceinline__ float ex2f(float x) {
    float y; asm("ex2.approx.f32 %0, %1;" : "=f"(y) : "f"(x)); return y;
}
__device__ __forceinline__ uint32_t smem_u32(const void* p) {
    uint32_t a;
    asm("{ .reg .u64 t; cvta.to.shared.u64 t, %1; cvt.u32.u64 %0, t; }" : "=r"(a) : "l"(p));
    return a;
}
__device__ __forceinline__ uint32_t pack2bf(float a, float b) {
    __nv_bfloat162 t = __floats2bfloat162_rn(a, b);
    return *(uint32_t*)&t;
}
__device__ __forceinline__ float bfhi(float a) {
    return __bfloat162float(__float2bfloat16(a));
}

#define MMA_BF16(accv, av, bv) \
    asm volatile("mma.sync.aligned.m16n8k16.row.col.f32.bf16.bf16.f32 " \
        "{%0,%1,%2,%3}, {%4,%5,%6,%7}, {%8,%9}, {%0,%1,%2,%3};" \
        : "+f"(accv[0]), "+f"(accv[1]), "+f"(accv[2]), "+f"(accv[3]) \
        : "r"(av[0]), "r"(av[1]), "r"(av[2]), "r"(av[3]), "r"(bv[0]), "r"(bv[1]))

// ---------------- 0: fold conv+avgpool weights ----------------
__global__ void prep_wp(const float* __restrict__ conv_w) {
    int d = threadIdx.x;
    for (int c = 0; c < 12; c++)
        for (int p = 0; p < 7; p++) {
            float s = 0.f;
            int klo = p - 3 > 0 ? p - 3 : 0;
            int khi = p < 3 ? p : 3;
            for (int k = klo; k <= khi; k++) s += conv_w[(d*12 + c)*4 + k];
            g_wp[(d*12 + c)*7 + p] = 0.25f * s;
        }
}

// ---------------- 1: conv+pool+relu+mask -> h[B,L,128] ----------------
__global__ void conv_kernel(const float* __restrict__ x, const float* __restrict__ conv_b,
                            const float* __restrict__ mask) {
    int b = blockIdx.y, l0 = blockIdx.x * 16, d = threadIdx.x;
    __shared__ float xs[12][68];
    __shared__ float wps[128][85];
    for (int i = d; i < 128*84; i += 128) { wps[i/84][i%84] = g_wp[i]; }
    for (int i = d; i < 12*67; i += 128) {
        int c = i / 67, t = i % 67;
        int xi = 4*l0 - 2 + t;
        xs[c][t] = (xi >= 0 && xi < TT) ? x[((size_t)b*12 + c)*TT + xi] : 0.f;
    }
    __syncthreads();
    float bb = conv_b[d];
    for (int ll = 0; ll < 16; ll++) {
        float acc = bb;
        #pragma unroll
        for (int c = 0; c < 12; c++)
            #pragma unroll
            for (int p = 0; p < 7; p++)
                acc += xs[c][4*ll + p] * wps[d][c*7 + p];
        float hv = fmaxf(acc, 0.f) * mask[b*LL + l0 + ll];
        g_h[((size_t)b*LL + l0 + ll)*DM + d] = hv;
    }
}

// ---------------- 1b: split h into bf16 hi/lo ----------------
__global__ void cvt_kernel() {
    size_t i = (size_t)blockIdx.x*256 + threadIdx.x;
    float v = g_h[i];
    __nv_bfloat16 hi = __float2bfloat16(v);
    g_hhi[i] = hi;
    g_hlo[i] = __float2bfloat16(v - __bfloat162float(hi));
}

// ---------------- 1c: split qkv into bf16 hi/lo ----------------
__global__ void cvt_qkv_kernel() {
    size_t i = (size_t)blockIdx.x*256 + threadIdx.x;
    float v = g_qkv[i];
    __nv_bfloat16 hi = __float2bfloat16(v);
    g_qh[i] = hi;
    g_ql[i] = __float2bfloat16(v - __bfloat162float(hi));
}

// ---------------- 2: row squared norms ----------------
__global__ void norm2_kernel() {
    int row = blockIdx.x, t = threadIdx.x;
    float v = g_h[(size_t)row*DM + t];
    float s = v * v;
    for (int o = 16; o; o >>= 1) s += __shfl_down_sync(0xffffffffu, s, o);
    __shared__ float ws[4];
    if ((t & 31) == 0) ws[t >> 5] = s;
    __syncthreads();
    if (t == 0) g_norm2[row] = ws[0] + ws[1] + ws[2] + ws[3];
}

// ---------------- 3: pairwise D2 via mma.sync bf16x2 (128x64 tiles) -> skewed ----------------
#define D2M_SMEM 104832

__global__ void __launch_bounds__(256) d2m_kernel() {
    extern __shared__ char dsm[];
    __nv_bfloat16* Ahi = (__nv_bfloat16*)dsm;        // [128][136]
    __nv_bfloat16* Alo = Ahi + 128*136;
    __nv_bfloat16* Bhi = Alo + 128*136;              // [64][136]
    __nv_bfloat16* Blo = Bhi + 64*136;
    float* nsArr = (float*)(Blo + 64*136);           // 64 floats
    int b = blockIdx.z, i0 = blockIdx.y*128, j0 = blockIdx.x*64;
    int tid = threadIdx.x, wid = tid>>5, lane = tid&31;

    for (int c = tid; c < 128*16; c += 256) {
        int r = c >> 4, ch = c & 15;
        size_t g = (size_t)(i0 + r)*DM + ch*8;
        *(uint4*)&Ahi[r*136 + ch*8] = *(const uint4*)&g_hhi[g];
        *(uint4*)&Alo[r*136 + ch*8] = *(const uint4*)&g_hlo[g];
    }
    for (int c = tid; c < 64*16; c += 256) {
        int r = c >> 4, ch = c & 15;
        size_t g = (size_t)(b*LL + j0 + r)*DM + ch*8;
        *(uint4*)&Bhi[r*136 + ch*8] = *(const uint4*)&g_hhi[g];
        *(uint4*)&Blo[r*136 + ch*8] = *(const uint4*)&g_hlo[g];
    }
    if (tid < 64) nsArr[tid] = g_norm2[b*LL + j0 + tid];
    __syncthreads();

    float acc[8][4] = {};
    int mrow = wid*16;
    uint32_t aoff = (uint32_t)((mrow + (lane & 15))*136 + (lane >> 4)*8) * 2u;
    uint32_t a_hi = smem_u32(Ahi) + aoff;
    uint32_t a_lo = smem_u32(Alo) + aoff;
    uint32_t boff = (uint32_t)((lane & 7)*136 + ((lane >> 3) & 1)*8) * 2u;
    uint32_t b_hi = smem_u32(Bhi) + boff;
    uint32_t b_lo = smem_u32(Blo) + boff;

    for (int ks = 0; ks < 8; ks++) {
        uint32_t ah[4], al[4];
        asm volatile("ldmatrix.sync.aligned.m8n8.x4.shared.b16 {%0,%1,%2,%3}, [%4];"
            : "=r"(ah[0]), "=r"(ah[1]), "=r"(ah[2]), "=r"(ah[3]) : "r"(a_hi + ks*32));
        asm volatile("ldmatrix.sync.aligned.m8n8.x4.shared.b16 {%0,%1,%2,%3}, [%4];"
            : "=r"(al[0]), "=r"(al[1]), "=r"(al[2]), "=r"(al[3]) : "r"(a_lo + ks*32));
        #pragma unroll
        for (int nt = 0; nt < 8; nt++) {
            uint32_t bh[2], bl[2];
            uint32_t badd = (uint32_t)(nt*8*136)*2u + (uint32_t)ks*32u;
            asm volatile("ldmatrix.sync.aligned.m8n8.x2.shared.b16 {%0,%1}, [%2];"
                : "=r"(bh[0]), "=r"(bh[1]) : "r"(b_hi + badd));
            asm volatile("ldmatrix.sync.aligned.m8n8.x2.shared.b16 {%0,%1}, [%2];"
                : "=r"(bl[0]), "=r"(bl[1]) : "r"(b_lo + badd));
            MMA_BF16(acc[nt], ah, bh);
            MMA_BF16(acc[nt], ah, bl);
            MMA_BF16(acc[nt], al, bh);
        }
    }
    __syncthreads();

    float* Cs = (float*)dsm;
    int g = lane >> 2, tg = lane & 3;
    float na0 = g_norm2[i0 + mrow + g];
    float na1 = g_norm2[i0 + mrow + g + 8];
    #pragma unroll
    for (int nt = 0; nt < 8; nt++) {
        int c = nt*8 + tg*2;
        float ns0 = nsArr[c], ns1 = nsArr[c+1];
        Cs[(mrow+g)*66 + c]       = na0 + ns0 - 2.f*acc[nt][0];
        Cs[(mrow+g)*66 + c + 1]   = na0 + ns1 - 2.f*acc[nt][1];
        Cs[(mrow+g+8)*66 + c]     = na1 + ns0 - 2.f*acc[nt][2];
        Cs[(mrow+g+8)*66 + c + 1] = na1 + ns1 - 2.f*acc[nt][3];
    }
    __syncthreads();
    float* Dk = g_Dskew + (size_t)b*DSTRIDE;
    for (int kb = 0; kb < 192; kb += 4) {
        int kk = kb + (tid >> 6);
        int jo = tid & 63;
        if (kk < 191) {
            int io = kk - jo;
            if (io >= 0 && io < 128)
                Dk[(size_t)(i0 + j0 + kk)*LL + i0 + io] = Cs[io*66 + jo];
        }
    }
}

// ---------------- 4: soft-DTW wavefront (R in place, 2-exp softmin) ----------------
__global__ void __launch_bounds__(1024) softdtw_kernel() {
    int b = blockIdx.x, i = threadIdx.x;
    __shared__ float s0[1024], s1[1024], s2[1024];
    __shared__ float rmn[32], rmx[32];
    float *prev2 = s0, *prev1 = s1, *cur = s2;
    prev2[i] = INFV; prev1[i] = INFV;
    float rprev = INFV;
    float* Dk = g_Dskew + (size_t)b*DSTRIDE;
    float vmin = INFV, vmax = -INFV;
    const float cExp = 0.28853900817779268f;
    const float cLog = 3.4657359027997265f;
    float dbuf[8];
    #pragma unroll
    for (int p = 0; p < 8; p++) dbuf[p] = Dk[(size_t)p*LL + i];
    __syncthreads();
    for (int kb = 0; kb < 2048; kb += 8) {
        #pragma unroll
        for (int p = 0; p < 8; p++) {
            int k = kb + p;
            if (k >= NDIAG) break;
            float d = dbuf[p];
            if (k + 8 < NDIAG) dbuf[p] = Dk[(size_t)(k+8)*LL + i];
            float r_l = rprev;
            float r_u, r_ul;
            if (i == 0) { r_u = INFV; r_ul = (k == 0) ? 0.f : INFV; }
            else        { r_u = prev1[i-1]; r_ul = prev2[i-1]; }
            int j = k - i;
            float rv;
            if (j >= 0 && j < LL) {
                float lo  = fminf(r_u, r_l);
                float hi2 = fmaxf(r_u, r_l);
                float m   = fminf(r_ul, lo);
                float o1  = fmaxf(r_ul, lo);
                float s = 1.0f + ex2f((m - o1)*cExp) + ex2f((m - hi2)*cExp);
                rv = d + m - cLog * __log2f(s);
                cur[i] = rv;
                Dk[(size_t)k*LL + i] = rv;
                vmin = fminf(vmin, rv); vmax = fmaxf(vmax, rv);
            } else { rv = INFV; cur[i] = INFV; }
            rprev = rv;
            __syncthreads();
            float* t = prev2; prev2 = prev1; prev1 = cur; cur = t;
        }
    }
    for (int o = 16; o; o >>= 1) {
        vmin = fminf(vmin, __shfl_down_sync(0xffffffffu, vmin, o));
        vmax = fmaxf(vmax, __shfl_down_sync(0xffffffffu, vmax, o));
    }
    if ((i & 31) == 0) { rmn[i >> 5] = vmin; rmx[i >> 5] = vmax; }
    __syncthreads();
    if (i < 32) {
        vmin = rmn[i]; vmax = rmx[i];
        for (int o = 16; o; o >>= 1) {
            vmin = fminf(vmin, __shfl_down_sync(0xffffffffu, vmin, o));
            vmax = fmaxf(vmax, __shfl_down_sync(0xffffffffu, vmax, o));
        }
        if (i == 0) { g_Rmin[b] = vmin; g_Rmax[b] = vmax; }
    }
}

// ---------------- 5: unskew + minmax-normalize -> Rn[b][i][j] ----------------
__global__ void normalize_kernel() {
    int b = blockIdx.z, i0 = blockIdx.y*32, j0 = blockIdx.x*32;
    __shared__ float s[63*33];
    int tid = threadIdx.y*32 + threadIdx.x;
    float mn = g_Rmin[b];
    float inv = 1.f / (g_Rmax[b] - mn);
    const float* Rk = g_Dskew + (size_t)b*DSTRIDE;
    for (int idx = tid; idx < 63*32; idx += 1024) {
        int r = idx >> 5, c = idx & 31;
        s[r*33 + c] = Rk[(size_t)(i0 + j0 + r)*LL + i0 + c];
    }
    __syncthreads();
    float v = s[(threadIdx.y + threadIdx.x)*33 + threadIdx.y];
    g_Rn[(size_t)b*LL*LL + (size_t)(i0 + threadIdx.y)*LL + j0 + threadIdx.x] = (v - mn)*inv + 1.f;
}

// ---------------- generic NT GEMM (128x64 tile, 8x4 microtile) ----------------
__global__ void __launch_bounds__(256) gemm_nt_kernel(const float* __restrict__ A,
                               const float* __restrict__ Bw,
                               const float* __restrict__ bias, float* __restrict__ C,
                               int N, int relu) {
    int m0 = blockIdx.y*128, n0 = blockIdx.x*64;
    __shared__ float As[16][132], Bs[16][68];
    int tid = threadIdx.x, ty = tid>>4, tx = tid&15;
    float acc[8][4] = {};
    for (int kc = 0; kc < 8; kc++) {
        __syncthreads();
        #pragma unroll
        for (int rep = 0; rep < 2; rep++) {
            int idx = rep*256 + tid;
            int i = idx>>2, k4 = idx&3;
            float4 av = *(const float4*)&A[(size_t)(m0+i)*128 + kc*16 + k4*4];
            As[k4*4+0][i]=av.x; As[k4*4+1][i]=av.y; As[k4*4+2][i]=av.z; As[k4*4+3][i]=av.w;
        }
        {
            int jcol = tid>>2, k4 = tid&3;
            float4 bv = *(const float4*)&Bw[(size_t)(n0+jcol)*128 + kc*16 + k4*4];
            Bs[k4*4+0][jcol]=bv.x; Bs[k4*4+1][jcol]=bv.y; Bs[k4*4+2][jcol]=bv.z; Bs[k4*4+3][jcol]=bv.w;
        }
        __syncthreads();
        #pragma unroll
        for (int kk = 0; kk < 16; kk++) {
            float4 a0 = *(const float4*)&As[kk][ty*8];
            float4 a1 = *(const float4*)&As[kk][ty*8+4];
            float4 b4 = *(const float4*)&Bs[kk][tx*4];
            float a[8] = {a0.x,a0.y,a0.z,a0.w,a1.x,a1.y,a1.z,a1.w};
            float bb[4] = {b4.x,b4.y,b4.z,b4.w};
            #pragma unroll
            for (int u = 0; u < 8; u++)
                #pragma unroll
                for (int v = 0; v < 4; v++) acc[u][v] += a[u]*bb[v];
        }
    }
    #pragma unroll
    for (int u = 0; u < 8; u++) {
        float o[4];
        #pragma unroll
        for (int v = 0; v < 4; v++) {
            int n = n0 + tx*4 + v;
            float val = acc[u][v] + (bias ? bias[n] : 0.f);
            if (relu) val = fmaxf(val, 0.f);
            o[v] = val;
        }
        *(float4*)&C[(size_t)(m0 + ty*8 + u)*N + n0 + tx*4] = make_float4(o[0],o[1],o[2],o[3]);
    }
}

// ---------------- 6: flash attention via mma.sync (64q tile, 4 warps) ----------------
#define FLASHM_SMEM 104448
__global__ void __launch_bounds__(128) flashm_kernel(const float* __restrict__ mask) {
    extern __shared__ char fsm[];
    __nv_bfloat16* Qh  = (__nv_bfloat16*)fsm;   // [64][136]
    __nv_bfloat16* Ql  = Qh + 64*136;
    __nv_bfloat16* KVh = Ql + 64*136;           // [128][136] shared K then V
    __nv_bfloat16* KVl = KVh + 128*136;
    int b = blockIdx.y, i0 = blockIdx.x*64;
    int tid = threadIdx.x, w = tid>>5, lane = tid&31;
    int g = lane >> 2, tg = lane & 3;
    const float scale = 0.08838834764831845f;   // 1/sqrt(128)
    const __nv_bfloat16* Qhg = g_qh + (size_t)b*LL*384;
    const __nv_bfloat16* Qlg = g_ql + (size_t)b*LL*384;
    const float* mk = mask + (size_t)b*LL;
    const float* rn0 = g_Rn + (size_t)b*LL*LL + (size_t)(i0 + w*16 + g)*LL;
    const float* rn1 = rn0 + 8*LL;

    // load Q tile (hi/lo)
    for (int c = tid; c < 64*16; c += 128) {
        int r = c >> 4, ch = c & 15;
        size_t gidx = (size_t)(i0 + r)*384 + ch*8;
        *(uint4*)&Qh[r*136 + ch*8] = *(const uint4*)&Qhg[gidx];
        *(uint4*)&Ql[r*136 + ch*8] = *(const uint4*)&Qlg[gidx];
    }

    uint32_t aoff = (uint32_t)((w*16 + (lane & 15))*136 + (lane >> 4)*8) * 2u;
    uint32_t q_hi = smem_u32(Qh) + aoff;
    uint32_t q_lo = smem_u32(Ql) + aoff;
    uint32_t boff = (uint32_t)((lane & 7)*136 + ((lane >> 3) & 1)*8) * 2u;
    uint32_t kv_hi = smem_u32(KVh);
    uint32_t kv_lo = smem_u32(KVl);
    uint32_t voff = (uint32_t)((lane & 15)*136) * 2u;   // + ks*16*272 + dn*16

    float Oacc[16][4] = {};
    float m0 = -1e30f, m1 = -1e30f, l0 = 0.f, l1 = 0.f;

    for (int kt = 0; kt < 8; kt++) {
        // ---- load K tile ----
        __syncthreads();
        for (int c = tid; c < 128*16; c += 128) {
            int r = c >> 4, ch = c & 15;
            size_t gidx = (size_t)(kt*128 + r)*384 + 128 + ch*8;
            *(uint4*)&KVh[r*136 + ch*8] = *(const uint4*)&Qhg[gidx];
            *(uint4*)&KVl[r*136 + ch*8] = *(const uint4*)&Qlg[gidx];
        }
        __syncthreads();
        // ---- S = Q K^T (16q x 128k per warp) ----
        float acc[16][4] = {};
        for (int ks = 0; ks < 8; ks++) {
            uint32_t ah[4], al[4];
            asm volatile("ldmatrix.sync.aligned.m8n8.x4.shared.b16 {%0,%1,%2,%3}, [%4];"
                : "=r"(ah[0]), "=r"(ah[1]), "=r"(ah[2]), "=r"(ah[3]) : "r"(q_hi + ks*32));
            asm volatile("ldmatrix.sync.aligned.m8n8.x4.shared.b16 {%0,%1,%2,%3}, [%4];"
                : "=r"(al[0]), "=r"(al[1]), "=r"(al[2]), "=r"(al[3]) : "r"(q_lo + ks*32));
            #pragma unroll
            for (int nt = 0; nt < 16; nt++) {
                uint32_t bh[2], bl[2];
                uint32_t badd = boff + (uint32_t)(nt*8*136)*2u + (uint32_t)ks*32u;
                asm volatile("ldmatrix.sync.aligned.m8n8.x2.shared.b16 {%0,%1}, [%2];"
                    : "=r"(bh[0]), "=r"(bh[1]) : "r"(kv_hi + badd));
                asm volatile("ldmatrix.sync.aligned.m8n8.x2.shared.b16 {%0,%1}, [%2];"
                    : "=r"(bl[0]), "=r"(bl[1]) : "r"(kv_lo + badd));
                MMA_BF16(acc[nt], ah, bh);
                MMA_BF16(acc[nt], ah, bl);
                MMA_BF16(acc[nt], al, bh);
            }
        }
        // ---- bias + mask + online softmax (fragment layout) ----
        float rmax0 = -1e30f, rmax1 = -1e30f;
        #pragma unroll
        for (int nt = 0; nt < 16; nt++) {
            int col = kt*128 + nt*8 + 2*tg;
            float2 mv = *(const float2*)&mk[col];
            float2 b0v = *(const float2*)&rn0[col];
            float2 b1v = *(const float2*)&rn1[col];
            float x0 = acc[nt][0]*scale + b0v.x; x0 = (mv.x > 0.f) ? x0 : -1e30f;
            float x1 = acc[nt][1]*scale + b0v.y; x1 = (mv.y > 0.f) ? x1 : -1e30f;
            float x2 = acc[nt][2]*scale + b1v.x; x2 = (mv.x > 0.f) ? x2 : -1e30f;
            float x3 = acc[nt][3]*scale + b1v.y; x3 = (mv.y > 0.f) ? x3 : -1e30f;
            acc[nt][0] = x0; acc[nt][1] = x1; acc[nt][2] = x2; acc[nt][3] = x3;
            rmax0 = fmaxf(rmax0, fmaxf(x0, x1));
            rmax1 = fmaxf(rmax1, fmaxf(x2, x3));
        }
        rmax0 = fmaxf(rmax0, __shfl_xor_sync(0xffffffffu, rmax0, 1));
        rmax0 = fmaxf(rmax0, __shfl_xor_sync(0xffffffffu, rmax0, 2));
        rmax1 = fmaxf(rmax1, __shfl_xor_sync(0xffffffffu, rmax1, 1));
        rmax1 = fmaxf(rmax1, __shfl_xor_sync(0xffffffffu, rmax1, 2));
        float mt0 = fmaxf(m0, rmax0), f0 = __expf(m0 - mt0); m0 = mt0;
        float mt1 = fmaxf(m1, rmax1), f1 = __expf(m1 - mt1); m1 = mt1;
        float s0 = 0.f, s1 = 0.f;
        #pragma unroll
        for (int nt = 0; nt < 16; nt++) {
            float p0 = __expf(acc[nt][0] - mt0);
            float p1 = __expf(acc[nt][1] - mt0);
            float p2 = __expf(acc[nt][2] - mt1);
            float p3 = __expf(acc[nt][3] - mt1);
            acc[nt][0] = p0; acc[nt][1] = p1; acc[nt][2] = p2; acc[nt][3] = p3;
            s0 += p0 + p1; s1 += p2 + p3;
        }
        s0 += __shfl_xor_sync(0xffffffffu, s0, 1);
        s0 += __shfl_xor_sync(0xffffffffu, s0, 2);
        s1 += __shfl_xor_sync(0xffffffffu, s1, 1);
        s1 += __shfl_xor_sync(0xffffffffu, s1, 2);
        l0 = l0*f0 + s0; l1 = l1*f1 + s1;
        #pragma unroll
        for (int dn = 0; dn < 16; dn++) {
            Oacc[dn][0] *= f0; Oacc[dn][1] *= f0;
            Oacc[dn][2] *= f1; Oacc[dn][3] *= f1;
        }
        // ---- pack P into A-fragments (hi/lo) ----
        uint32_t ph[8][4], pl[8][4];
        #pragma unroll
        for (int ks = 0; ks < 8; ks++) {
            float c0 = acc[2*ks][0],   c1 = acc[2*ks][1];
            float c2 = acc[2*ks][2],   c3 = acc[2*ks][3];
            float d0 = acc[2*ks+1][0], d1 = acc[2*ks+1][1];
            float d2 = acc[2*ks+1][2], d3 = acc[2*ks+1][3];
            ph[ks][0] = pack2bf(c0, c1); ph[ks][1] = pack2bf(c2, c3);
            ph[ks][2] = pack2bf(d0, d1); ph[ks][3] = pack2bf(d2, d3);
            pl[ks][0] = pack2bf(c0 - bfhi(c0), c1 - bfhi(c1));
            pl[ks][1] = pack2bf(c2 - bfhi(c2), c3 - bfhi(c3));
            pl[ks][2] = pack2bf(d0 - bfhi(d0), d1 - bfhi(d1));
            pl[ks][3] = pack2bf(d2 - bfhi(d2), d3 - bfhi(d3));
        }
        // ---- load V tile into same buffers ----
        __syncthreads();
        for (int c = tid; c < 128*16; c += 128) {
            int r = c >> 4, ch = c & 15;
            size_t gidx = (size_t)(kt*128 + r)*384 + 256 + ch*8;
            *(uint4*)&KVh[r*136 + ch*8] = *(const uint4*)&Qhg[gidx];
            *(uint4*)&KVl[r*136 + ch*8] = *(const uint4*)&Qlg[gidx];
        }
        __syncthreads();
        // ---- O += P V  (B via ldmatrix.trans on V[key][d]) ----
        for (int ks = 0; ks < 8; ks++) {
            uint32_t vbase = voff + (uint32_t)(ks*16*136)*2u;
            #pragma unroll
            for (int dn = 0; dn < 16; dn++) {
                uint32_t vh[2], vl[2];
                uint32_t vadd = vbase + (uint32_t)dn*16u;
                asm volatile("ldmatrix.sync.aligned.m8n8.x2.trans.shared.b16 {%0,%1}, [%2];"
                    : "=r"(vh[0]), "=r"(vh[1]) : "r"(kv_hi + vadd));
                asm volatile("ldmatrix.sync.aligned.m8n8.x2.trans.shared.b16 {%0,%1}, [%2];"
                    : "=r"(vl[0]), "=r"(vl[1]) : "r"(kv_lo + vadd));
                MMA_BF16(Oacc[dn], ph[ks], vh);
                MMA_BF16(Oacc[dn], ph[ks], vl);
                MMA_BF16(Oacc[dn], pl[ks], vh);
            }
        }
    }
    // ---- epilogue ----
    float inv0 = 1.f / l0, inv1 = 1.f / l1;
    float* o0 = &g_sa[((size_t)b*LL + i0 + w*16 + g)*DM];
    float* o1 = o0 + 8*DM;
    #pragma unroll
    for (int dn = 0; dn < 16; dn++) {
        int c = dn*8 + 2*tg;
        *(float2*)&o0[c] = make_float2(Oacc[dn][0]*inv0, Oacc[dn][1]*inv0);
        *(float2*)&o1[c] = make_float2(Oacc[dn][2]*inv1, Oacc[dn][3]*inv1);
    }
}

// ---------------- 9: residual + layernorm ----------------
__global__ void ln_kernel(const float* __restrict__ a, const float* __restrict__ bsrc,
                          const float* __restrict__ g, const float* __restrict__ beta,
                          float* __restrict__ out) {
    int row = blockIdx.x, t = threadIdx.x;
    float x = a[(size_t)row*DM + t] + bsrc[(size_t)row*DM + t];
    float s = x, q = x*x;
    for (int o = 16; o; o >>= 1) {
        s += __shfl_xor_sync(0xffffffffu, s, o);
        q += __shfl_xor_sync(0xffffffffu, q, o);
    }
    __shared__ float ss[4], qq[4];
    if ((t & 31) == 0) { ss[t >> 5] = s; qq[t >> 5] = q; }
    __syncthreads();
    s = ss[0]+ss[1]+ss[2]+ss[3];
    q = qq[0]+qq[1]+qq[2]+qq[3];
    float m = s * (1.f/128.f);
    float v = q * (1.f/128.f) - m*m;
    out[(size_t)row*DM + t] = (x - m) * rsqrtf(v + 1e-5f) * g[t] + beta[t];
}

// ---------------- 10: final projection 128->16 (masked) ----------------
__global__ void out_kernel(const float* __restrict__ w_lin, const float* __restrict__ mask,
                           float* __restrict__ dout) {
    int row = blockIdx.x, t = threadIdx.x;
    __shared__ float hs[128];
    hs[t] = g_h2[(size_t)row*DM + t];
    __syncthreads();
    if (t < 16) {
        float s = 0.f;
        #pragma unroll
        for (int d = 0; d < 128; d++) s += hs[d] * w_lin[t*128 + d];
        dout[(size_t)row*16 + t] = s * mask[row];
    }
}

// ---------------- 11: length = sum(mask, axis=1) ----------------
__global__ void len_kernel(const float* __restrict__ mask, float* __restrict__ dout) {
    int b = blockIdx.x, t = threadIdx.x;
    float s = mask[(size_t)b*LL + t];
    for (int o = 16; o; o >>= 1) s += __shfl_xor_sync(0xffffffffu, s, o);
    __shared__ float ws[32];
    if ((t & 31) == 0) ws[t >> 5] = s;
    __syncthreads();
    if (t == 0) {
        float tot = 0.f;
        for (int w = 0; w < 32; w++) tot += ws[w];
        dout[(size_t)NB*LL*16 + b] = tot;
    }
}

extern "C" void kernel_launch(void* const* d_in, const int* in_sizes, int n_in,
                              void* d_out, int out_size) {
    const float* x      = (const float*)d_in[0];
    const float* mask   = (const float*)d_in[1];
    const float* conv_w = (const float*)d_in[2];
    const float* conv_b = (const float*)d_in[3];
    const float* w_in   = (const float*)d_in[4];
    const float* b_in   = (const float*)d_in[5];
    const float* w_out  = (const float*)d_in[6];
    const float* b_out  = (const float*)d_in[7];
    const float* w_ff1  = (const float*)d_in[8];
    const float* b_ff1  = (const float*)d_in[9];
    const float* w_ff2  = (const float*)d_in[10];
    const float* b_ff2  = (const float*)d_in[11];
    const float* ln1_g  = (const float*)d_in[12];
    const float* ln1_b  = (const float*)d_in[13];
    const float* ln2_g  = (const float*)d_in[14];
    const float* ln2_b  = (const float*)d_in[15];
    const float* w_lin  = (const float*)d_in[16];
    float* dout = (float*)d_out;

    float* ph;   cudaGetSymbolAddress((void**)&ph,   g_h);
    float* pqkv; cudaGetSymbolAddress((void**)&pqkv, g_qkv);
    float* psa;  cudaGetSymbolAddress((void**)&psa,  g_sa);
    float* ptmp; cudaGetSymbolAddress((void**)&ptmp, g_tmp);
    float* ph1;  cudaGetSymbolAddress((void**)&ph1,  g_h1);
    float* pff;  cudaGetSymbolAddress((void**)&pff,  g_ff);
    float* ph2;  cudaGetSymbolAddress((void**)&ph2,  g_h2);

    cudaFuncSetAttribute(d2m_kernel, cudaFuncAttributeMaxDynamicSharedMemorySize, D2M_SMEM);
    cudaFuncSetAttribute(flashm_kernel, cudaFuncAttributeMaxDynamicSharedMemorySize, FLASHM_SMEM);

    static cudaStream_t s2 = nullptr;
    static cudaEvent_t evF = nullptr, evJ = nullptr;
    if (s2 == nullptr) {
        cudaStreamCreateWithFlags(&s2, cudaStreamNonBlocking);
        cudaEventCreateWithFlags(&evF, cudaEventDisableTiming);
        cudaEventCreateWithFlags(&evJ, cudaEventDisableTiming);
    }

    prep_wp<<<1, 128>>>(conv_w);
    conv_kernel<<<dim3(64, 32), 128>>>(x, conv_b, mask);

    cudaEventRecord(evF, 0);
    cudaStreamWaitEvent(s2, evF, 0);

    cvt_kernel<<<16384, 256>>>();
    norm2_kernel<<<NB*LL, 128>>>();
    d2m_kernel<<<dim3(16, 8, NB), 256, D2M_SMEM>>>();
    softdtw_kernel<<<NB, 1024>>>();
    normalize_kernel<<<dim3(32, 32, NB), dim3(32, 32)>>>();

    gemm_nt_kernel<<<dim3(6, 256), 256, 0, s2>>>(ph, w_in, b_in, pqkv, 384, 0);
    cvt_qkv_kernel<<<49152, 256, 0, s2>>>();
    len_kernel<<<NB, 1024, 0, s2>>>(mask, dout);

    cudaEventRecord(evJ, s2);
    cudaStreamWaitEvent(0, evJ, 0);

    flashm_kernel<<<dim3(16, NB), 128, FLASHM_SMEM>>>(mask);
    gemm_nt_kernel<<<dim3(2, 256), 256>>>(psa, w_out, b_out, ptmp, 128, 0);
    ln_kernel<<<NB*LL, 128>>>(ph, ptmp, ln1_g, ln1_b, ph1);
    gemm_nt_kernel<<<dim3(2, 256), 256>>>(ph1, w_ff1, b_ff1, pff, 128, 1);
    gemm_nt_kernel<<<dim3(2, 256), 256>>>(pff, w_ff2, b_ff2, ptmp, 128, 0);
    ln_kernel<<<NB*LL, 128>>>(ph1, ptmp, ln2_g, ln2_b, ph2);
    out_kernel<<<NB*LL, 128>>>(w_lin, mask, dout);
}

// round 16
// speedup vs baseline: 1.4403x; 1.0218x over previous
#include <cuda_runtime.h>
#include <cuda_bf16.h>
#include <cstdint>
#include <math.h>

#define NB 32
#define LL 1024
#define DM 128
#define TT 4095
#define NDIAG 2047
#define DSTRIDE ((size_t)NDIAG*LL)
#define INFV __int_as_float(0x7f800000)

// ---------------- device scratch ----------------
__device__ float g_wp[DM*12*7];
__device__ float g_h[(size_t)NB*LL*DM];
__device__ __nv_bfloat16 g_hhi[(size_t)NB*LL*DM];
__device__ __nv_bfloat16 g_hlo[(size_t)NB*LL*DM];
__device__ float g_norm2[NB*LL];
__device__ float g_Dskew[(size_t)NB*NDIAG*LL];   // D, then R in place (skewed)
__device__ float g_Rmin[NB];
__device__ float g_Rmax[NB];
__device__ float g_Rn[(size_t)NB*LL*LL];         // normalized R (attention bias)
__device__ __nv_bfloat16 g_qh[(size_t)NB*LL*384];
__device__ __nv_bfloat16 g_ql[(size_t)NB*LL*384];
__device__ __nv_bfloat16 g_whi[98304];           // w_in@0, w_out@49152, w_ff1@65536, w_ff2@81920
__device__ __nv_bfloat16 g_wlo[98304];
__device__ __nv_bfloat16 g_sahi[(size_t)NB*LL*DM];
__device__ __nv_bfloat16 g_salo[(size_t)NB*LL*DM];
__device__ __nv_bfloat16 g_h1hi[(size_t)NB*LL*DM];
__device__ __nv_bfloat16 g_h1lo[(size_t)NB*LL*DM];
__device__ __nv_bfloat16 g_ffhi[(size_t)NB*LL*DM];
__device__ __nv_bfloat16 g_fflo[(size_t)NB*LL*DM];
__device__ float g_tmp[(size_t)NB*LL*DM];
__device__ float g_h1[(size_t)NB*LL*DM];
__device__ float g_h2[(size_t)NB*LL*DM];

__device__ __forceinline__ float ex2f(float x) {
    float y; asm("ex2.approx.f32 %0, %1;" : "=f"(y) : "f"(x)); return y;
}
__device__ __forceinline__ uint32_t smem_u32(const void* p) {
    uint32_t a;
    asm("{ .reg .u64 t; cvta.to.shared.u64 t, %1; cvt.u32.u64 %0, t; }" : "=r"(a) : "l"(p));
    return a;
}
__device__ __forceinline__ uint32_t pack2bf(float a, float b) {
    __nv_bfloat162 t = __floats2bfloat162_rn(a, b);
    return *(uint32_t*)&t;
}
__device__ __forceinline__ float bfhi(float a) {
    return __bfloat162float(__float2bfloat16(a));
}
__device__ __forceinline__ void split2(float v0, float v1, uint32_t& hi, uint32_t& lo) {
    float h0 = bfhi(v0), h1 = bfhi(v1);
    hi = pack2bf(h0, h1);
    lo = pack2bf(v0 - h0, v1 - h1);
}

#define MMA_BF16(accv, av, bv) \
    asm volatile("mma.sync.aligned.m16n8k16.row.col.f32.bf16.bf16.f32 " \
        "{%0,%1,%2,%3}, {%4,%5,%6,%7}, {%8,%9}, {%0,%1,%2,%3};" \
        : "+f"(accv[0]), "+f"(accv[1]), "+f"(accv[2]), "+f"(accv[3]) \
        : "r"(av[0]), "r"(av[1]), "r"(av[2]), "r"(av[3]), "r"(bv[0]), "r"(bv[1]))

// ---------------- 0: fold conv+avgpool weights ----------------
__global__ void prep_wp(const float* __restrict__ conv_w) {
    int d = threadIdx.x;
    for (int c = 0; c < 12; c++)
        for (int p = 0; p < 7; p++) {
            float s = 0.f;
            int klo = p - 3 > 0 ? p - 3 : 0;
            int khi = p < 3 ? p : 3;
            for (int k = klo; k <= khi; k++) s += conv_w[(d*12 + c)*4 + k];
            g_wp[(d*12 + c)*7 + p] = 0.25f * s;
        }
}

// ---------------- 0b: split transformer weights into bf16 hi/lo ----------------
__global__ void prep_ws(const float* __restrict__ w_in, const float* __restrict__ w_out,
                        const float* __restrict__ w_ff1, const float* __restrict__ w_ff2) {
    int i = blockIdx.x*256 + threadIdx.x;
    float v;
    if (i < 49152) v = w_in[i];
    else if (i < 65536) v = w_out[i - 49152];
    else if (i < 81920) v = w_ff1[i - 65536];
    else v = w_ff2[i - 81920];
    __nv_bfloat16 hi = __float2bfloat16(v);
    g_whi[i] = hi;
    g_wlo[i] = __float2bfloat16(v - __bfloat162float(hi));
}

// ---------------- 1: conv+pool+relu+mask -> h[B,L,128] ----------------
__global__ void conv_kernel(const float* __restrict__ x, const float* __restrict__ conv_b,
                            const float* __restrict__ mask) {
    int b = blockIdx.y, l0 = blockIdx.x * 16, d = threadIdx.x;
    __shared__ float xs[12][68];
    __shared__ float wps[128][85];
    for (int i = d; i < 128*84; i += 128) { wps[i/84][i%84] = g_wp[i]; }
    for (int i = d; i < 12*67; i += 128) {
        int c = i / 67, t = i % 67;
        int xi = 4*l0 - 2 + t;
        xs[c][t] = (xi >= 0 && xi < TT) ? x[((size_t)b*12 + c)*TT + xi] : 0.f;
    }
    __syncthreads();
    float bb = conv_b[d];
    for (int ll = 0; ll < 16; ll++) {
        float acc = bb;
        #pragma unroll
        for (int c = 0; c < 12; c++)
            #pragma unroll
            for (int p = 0; p < 7; p++)
                acc += xs[c][4*ll + p] * wps[d][c*7 + p];
        float hv = fmaxf(acc, 0.f) * mask[b*LL + l0 + ll];
        g_h[((size_t)b*LL + l0 + ll)*DM + d] = hv;
    }
}

// ---------------- 1b: split h into bf16 hi/lo ----------------
__global__ void cvt_kernel() {
    size_t i = (size_t)blockIdx.x*256 + threadIdx.x;
    float v = g_h[i];
    __nv_bfloat16 hi = __float2bfloat16(v);
    g_hhi[i] = hi;
    g_hlo[i] = __float2bfloat16(v - __bfloat162float(hi));
}

// ---------------- 2: row squared norms ----------------
__global__ void norm2_kernel() {
    int row = blockIdx.x, t = threadIdx.x;
    float v = g_h[(size_t)row*DM + t];
    float s = v * v;
    for (int o = 16; o; o >>= 1) s += __shfl_down_sync(0xffffffffu, s, o);
    __shared__ float ws[4];
    if ((t & 31) == 0) ws[t >> 5] = s;
    __syncthreads();
    if (t == 0) g_norm2[row] = ws[0] + ws[1] + ws[2] + ws[3];
}

// ---------------- 3: pairwise D2 via mma.sync bf16x2 (128x64 tiles) -> skewed ----------------
#define D2M_SMEM 104832

__global__ void __launch_bounds__(256) d2m_kernel() {
    extern __shared__ char dsm[];
    __nv_bfloat16* Ahi = (__nv_bfloat16*)dsm;        // [128][136]
    __nv_bfloat16* Alo = Ahi + 128*136;
    __nv_bfloat16* Bhi = Alo + 128*136;              // [64][136]
    __nv_bfloat16* Blo = Bhi + 64*136;
    float* nsArr = (float*)(Blo + 64*136);           // 64 floats
    int b = blockIdx.z, i0 = blockIdx.y*128, j0 = blockIdx.x*64;
    int tid = threadIdx.x, wid = tid>>5, lane = tid&31;

    for (int c = tid; c < 128*16; c += 256) {
        int r = c >> 4, ch = c & 15;
        size_t g = (size_t)(i0 + r)*DM + ch*8;
        *(uint4*)&Ahi[r*136 + ch*8] = *(const uint4*)&g_hhi[g];
        *(uint4*)&Alo[r*136 + ch*8] = *(const uint4*)&g_hlo[g];
    }
    for (int c = tid; c < 64*16; c += 256) {
        int r = c >> 4, ch = c & 15;
        size_t g = (size_t)(b*LL + j0 + r)*DM + ch*8;
        *(uint4*)&Bhi[r*136 + ch*8] = *(const uint4*)&g_hhi[g];
        *(uint4*)&Blo[r*136 + ch*8] = *(const uint4*)&g_hlo[g];
    }
    if (tid < 64) nsArr[tid] = g_norm2[b*LL + j0 + tid];
    __syncthreads();

    float acc[8][4] = {};
    int mrow = wid*16;
    uint32_t aoff = (uint32_t)((mrow + (lane & 15))*136 + (lane >> 4)*8) * 2u;
    uint32_t a_hi = smem_u32(Ahi) + aoff;
    uint32_t a_lo = smem_u32(Alo) + aoff;
    uint32_t boff = (uint32_t)((lane & 7)*136 + ((lane >> 3) & 1)*8) * 2u;
    uint32_t b_hi = smem_u32(Bhi) + boff;
    uint32_t b_lo = smem_u32(Blo) + boff;

    for (int ks = 0; ks < 8; ks++) {
        uint32_t ah[4], al[4];
        asm volatile("ldmatrix.sync.aligned.m8n8.x4.shared.b16 {%0,%1,%2,%3}, [%4];"
            : "=r"(ah[0]), "=r"(ah[1]), "=r"(ah[2]), "=r"(ah[3]) : "r"(a_hi + ks*32));
        asm volatile("ldmatrix.sync.aligned.m8n8.x4.shared.b16 {%0,%1,%2,%3}, [%4];"
            : "=r"(al[0]), "=r"(al[1]), "=r"(al[2]), "=r"(al[3]) : "r"(a_lo + ks*32));
        #pragma unroll
        for (int nt = 0; nt < 8; nt++) {
            uint32_t bh[2], bl[2];
            uint32_t badd = (uint32_t)(nt*8*136)*2u + (uint32_t)ks*32u;
            asm volatile("ldmatrix.sync.aligned.m8n8.x2.shared.b16 {%0,%1}, [%2];"
                : "=r"(bh[0]), "=r"(bh[1]) : "r"(b_hi + badd));
            asm volatile("ldmatrix.sync.aligned.m8n8.x2.shared.b16 {%0,%1}, [%2];"
                : "=r"(bl[0]), "=r"(bl[1]) : "r"(b_lo + badd));
            MMA_BF16(acc[nt], ah, bh);
            MMA_BF16(acc[nt], ah, bl);
            MMA_BF16(acc[nt], al, bh);
        }
    }
    __syncthreads();

    float* Cs = (float*)dsm;
    int g = lane >> 2, tg = lane & 3;
    float na0 = g_norm2[i0 + mrow + g];
    float na1 = g_norm2[i0 + mrow + g + 8];
    #pragma unroll
    for (int nt = 0; nt < 8; nt++) {
        int c = nt*8 + tg*2;
        float ns0 = nsArr[c], ns1 = nsArr[c+1];
        Cs[(mrow+g)*66 + c]       = na0 + ns0 - 2.f*acc[nt][0];
        Cs[(mrow+g)*66 + c + 1]   = na0 + ns1 - 2.f*acc[nt][1];
        Cs[(mrow+g+8)*66 + c]     = na1 + ns0 - 2.f*acc[nt][2];
        Cs[(mrow+g+8)*66 + c + 1] = na1 + ns1 - 2.f*acc[nt][3];
    }
    __syncthreads();
    float* Dk = g_Dskew + (size_t)b*DSTRIDE;
    for (int kb = 0; kb < 192; kb += 4) {
        int kk = kb + (tid >> 6);
        int jo = tid & 63;
        if (kk < 191) {
            int io = kk - jo;
            if (io >= 0 && io < 128)
                Dk[(size_t)(i0 + j0 + kk)*LL + i0 + io] = Cs[io*66 + jo];
        }
    }
}

// ---------------- 4: soft-DTW wavefront (R in place, 2-exp softmin) ----------------
__global__ void __launch_bounds__(1024) softdtw_kernel() {
    int b = blockIdx.x, i = threadIdx.x;
    __shared__ float s0[1024], s1[1024], s2[1024];
    __shared__ float rmn[32], rmx[32];
    float *prev2 = s0, *prev1 = s1, *cur = s2;
    prev2[i] = INFV; prev1[i] = INFV;
    float rprev = INFV;
    float* Dk = g_Dskew + (size_t)b*DSTRIDE;
    float vmin = INFV, vmax = -INFV;
    const float cExp = 0.28853900817779268f;
    const float cLog = 3.4657359027997265f;
    float dbuf[8];
    #pragma unroll
    for (int p = 0; p < 8; p++) dbuf[p] = Dk[(size_t)p*LL + i];
    __syncthreads();
    for (int kb = 0; kb < 2048; kb += 8) {
        #pragma unroll
        for (int p = 0; p < 8; p++) {
            int k = kb + p;
            if (k >= NDIAG) break;
            float d = dbuf[p];
            if (k + 8 < NDIAG) dbuf[p] = Dk[(size_t)(k+8)*LL + i];
            float r_l = rprev;
            float r_u, r_ul;
            if (i == 0) { r_u = INFV; r_ul = (k == 0) ? 0.f : INFV; }
            else        { r_u = prev1[i-1]; r_ul = prev2[i-1]; }
            int j = k - i;
            float rv;
            if (j >= 0 && j < LL) {
                float lo  = fminf(r_u, r_l);
                float hi2 = fmaxf(r_u, r_l);
                float m   = fminf(r_ul, lo);
                float o1  = fmaxf(r_ul, lo);
                float s = 1.0f + ex2f((m - o1)*cExp) + ex2f((m - hi2)*cExp);
                rv = d + m - cLog * __log2f(s);
                cur[i] = rv;
                Dk[(size_t)k*LL + i] = rv;
                vmin = fminf(vmin, rv); vmax = fmaxf(vmax, rv);
            } else { rv = INFV; cur[i] = INFV; }
            rprev = rv;
            __syncthreads();
            float* t = prev2; prev2 = prev1; prev1 = cur; cur = t;
        }
    }
    for (int o = 16; o; o >>= 1) {
        vmin = fminf(vmin, __shfl_down_sync(0xffffffffu, vmin, o));
        vmax = fmaxf(vmax, __shfl_down_sync(0xffffffffu, vmax, o));
    }
    if ((i & 31) == 0) { rmn[i >> 5] = vmin; rmx[i >> 5] = vmax; }
    __syncthreads();
    if (i < 32) {
        vmin = rmn[i]; vmax = rmx[i];
        for (int o = 16; o; o >>= 1) {
            vmin = fminf(vmin, __shfl_down_sync(0xffffffffu, vmin, o));
            vmax = fmaxf(vmax, __shfl_down_sync(0xffffffffu, vmax, o));
        }
        if (i == 0) { g_Rmin[b] = vmin; g_Rmax[b] = vmax; }
    }
}

// ---------------- 5: unskew + minmax-normalize -> Rn[b][i][j] ----------------
__global__ void normalize_kernel() {
    int b = blockIdx.z, i0 = blockIdx.y*32, j0 = blockIdx.x*32;
    __shared__ float s[63*33];
    int tid = threadIdx.y*32 + threadIdx.x;
    float mn = g_Rmin[b];
    float inv = 1.f / (g_Rmax[b] - mn);
    const float* Rk = g_Dskew + (size_t)b*DSTRIDE;
    for (int idx = tid; idx < 63*32; idx += 1024) {
        int r = idx >> 5, c = idx & 31;
        s[r*33 + c] = Rk[(size_t)(i0 + j0 + r)*LL + i0 + c];
    }
    __syncthreads();
    float v = s[(threadIdx.y + threadIdx.x)*33 + threadIdx.y];
    g_Rn[(size_t)b*LL*LL + (size_t)(i0 + threadIdx.y)*LL + j0 + threadIdx.x] = (v - mn)*inv + 1.f;
}

// ---------------- 6: GEMM via mma.sync bf16x2: C[M,N] = A[M,128] W[N,128]^T + bias ----------------
#define GM_SMEM 104448
__global__ void __launch_bounds__(256) gemm_mma(
        const __nv_bfloat16* __restrict__ Ahig, const __nv_bfloat16* __restrict__ Alog,
        const __nv_bfloat16* __restrict__ Whig, const __nv_bfloat16* __restrict__ Wlog,
        const float* __restrict__ bias, float* __restrict__ Cf,
        __nv_bfloat16* __restrict__ Chi, __nv_bfloat16* __restrict__ Clo,
        int N, int relu) {
    extern __shared__ char gsm[];
    __nv_bfloat16* Ah = (__nv_bfloat16*)gsm;     // [128][136]
    __nv_bfloat16* Al = Ah + 128*136;
    __nv_bfloat16* Bh = Al + 128*136;            // [64][136]
    __nv_bfloat16* Bl = Bh + 64*136;
    int m0 = blockIdx.y*128, n0 = blockIdx.x*64;
    int tid = threadIdx.x, wid = tid>>5, lane = tid&31;

    for (int c = tid; c < 128*16; c += 256) {
        int r = c >> 4, ch = c & 15;
        size_t g = (size_t)(m0 + r)*128 + ch*8;
        *(uint4*)&Ah[r*136 + ch*8] = *(const uint4*)&Ahig[g];
        *(uint4*)&Al[r*136 + ch*8] = *(const uint4*)&Alog[g];
    }
    for (int c = tid; c < 64*16; c += 256) {
        int r = c >> 4, ch = c & 15;
        size_t g = (size_t)(n0 + r)*128 + ch*8;
        *(uint4*)&Bh[r*136 + ch*8] = *(const uint4*)&Whig[g];
        *(uint4*)&Bl[r*136 + ch*8] = *(const uint4*)&Wlog[g];
    }
    __syncthreads();

    float acc[8][4] = {};
    int mrow = wid*16;
    uint32_t aoff = (uint32_t)((mrow + (lane & 15))*136 + (lane >> 4)*8) * 2u;
    uint32_t a_hi = smem_u32(Ah) + aoff;
    uint32_t a_lo = smem_u32(Al) + aoff;
    uint32_t boff = (uint32_t)((lane & 7)*136 + ((lane >> 3) & 1)*8) * 2u;
    uint32_t b_hi = smem_u32(Bh) + boff;
    uint32_t b_lo = smem_u32(Bl) + boff;

    for (int ks = 0; ks < 8; ks++) {
        uint32_t ah[4], al[4];
        asm volatile("ldmatrix.sync.aligned.m8n8.x4.shared.b16 {%0,%1,%2,%3}, [%4];"
            : "=r"(ah[0]), "=r"(ah[1]), "=r"(ah[2]), "=r"(ah[3]) : "r"(a_hi + ks*32));
        asm volatile("ldmatrix.sync.aligned.m8n8.x4.shared.b16 {%0,%1,%2,%3}, [%4];"
            : "=r"(al[0]), "=r"(al[1]), "=r"(al[2]), "=r"(al[3]) : "r"(a_lo + ks*32));
        #pragma unroll
        for (int nt = 0; nt < 8; nt++) {
            uint32_t bh[2], bl[2];
            uint32_t badd = (uint32_t)(nt*8*136)*2u + (uint32_t)ks*32u;
            asm volatile("ldmatrix.sync.aligned.m8n8.x2.shared.b16 {%0,%1}, [%2];"
                : "=r"(bh[0]), "=r"(bh[1]) : "r"(b_hi + badd));
            asm volatile("ldmatrix.sync.aligned.m8n8.x2.shared.b16 {%0,%1}, [%2];"
                : "=r"(bl[0]), "=r"(bl[1]) : "r"(b_lo + badd));
            MMA_BF16(acc[nt], ah, bh);
            MMA_BF16(acc[nt], ah, bl);
            MMA_BF16(acc[nt], al, bh);
        }
    }

    int g = lane >> 2, tg = lane & 3;
    size_t row0 = (size_t)(m0 + mrow + g);
    size_t row1 = row0 + 8;
    #pragma unroll
    for (int nt = 0; nt < 8; nt++) {
        int c = nt*8 + tg*2;
        float b0 = bias[n0 + c], b1 = bias[n0 + c + 1];
        float v0 = acc[nt][0] + b0, v1 = acc[nt][1] + b1;
        float v2 = acc[nt][2] + b0, v3 = acc[nt][3] + b1;
        if (relu) {
            v0 = fmaxf(v0, 0.f); v1 = fmaxf(v1, 0.f);
            v2 = fmaxf(v2, 0.f); v3 = fmaxf(v3, 0.f);
        }
        if (Cf) {
            *(float2*)&Cf[row0*N + n0 + c] = make_float2(v0, v1);
            *(float2*)&Cf[row1*N + n0 + c] = make_float2(v2, v3);
        }
        if (Chi) {
            uint32_t h01, l01, h23, l23;
            split2(v0, v1, h01, l01);
            split2(v2, v3, h23, l23);
            *(uint32_t*)&Chi[row0*N + n0 + c] = h01;
            *(uint32_t*)&Clo[row0*N + n0 + c] = l01;
            *(uint32_t*)&Chi[row1*N + n0 + c] = h23;
            *(uint32_t*)&Clo[row1*N + n0 + c] = l23;
        }
    }
}

// ---------------- 7: flash attention via mma.sync (64q tile, 4 warps) ----------------
#define FLASHM_SMEM 104448
__global__ void __launch_bounds__(128) flashm_kernel(const float* __restrict__ mask) {
    extern __shared__ char fsm[];
    __nv_bfloat16* Qh  = (__nv_bfloat16*)fsm;   // [64][136]
    __nv_bfloat16* Ql  = Qh + 64*136;
    __nv_bfloat16* KVh = Ql + 64*136;           // [128][136] shared K then V
    __nv_bfloat16* KVl = KVh + 128*136;
    int b = blockIdx.y, i0 = blockIdx.x*64;
    int tid = threadIdx.x, w = tid>>5, lane = tid&31;
    int g = lane >> 2, tg = lane & 3;
    const float scale = 0.08838834764831845f;   // 1/sqrt(128)
    const __nv_bfloat16* Qhg = g_qh + (size_t)b*LL*384;
    const __nv_bfloat16* Qlg = g_ql + (size_t)b*LL*384;
    const float* mk = mask + (size_t)b*LL;
    const float* rn0 = g_Rn + (size_t)b*LL*LL + (size_t)(i0 + w*16 + g)*LL;
    const float* rn1 = rn0 + 8*LL;

    for (int c = tid; c < 64*16; c += 128) {
        int r = c >> 4, ch = c & 15;
        size_t gidx = (size_t)(i0 + r)*384 + ch*8;
        *(uint4*)&Qh[r*136 + ch*8] = *(const uint4*)&Qhg[gidx];
        *(uint4*)&Ql[r*136 + ch*8] = *(const uint4*)&Qlg[gidx];
    }

    uint32_t aoff = (uint32_t)((w*16 + (lane & 15))*136 + (lane >> 4)*8) * 2u;
    uint32_t q_hi = smem_u32(Qh) + aoff;
    uint32_t q_lo = smem_u32(Ql) + aoff;
    uint32_t boff = (uint32_t)((lane & 7)*136 + ((lane >> 3) & 1)*8) * 2u;
    uint32_t kv_hi = smem_u32(KVh);
    uint32_t kv_lo = smem_u32(KVl);
    uint32_t voff = (uint32_t)((lane & 15)*136) * 2u;

    float Oacc[16][4] = {};
    float m0 = -1e30f, m1 = -1e30f, l0 = 0.f, l1 = 0.f;

    for (int kt = 0; kt < 8; kt++) {
        __syncthreads();
        for (int c = tid; c < 128*16; c += 128) {
            int r = c >> 4, ch = c & 15;
            size_t gidx = (size_t)(kt*128 + r)*384 + 128 + ch*8;
            *(uint4*)&KVh[r*136 + ch*8] = *(const uint4*)&Qhg[gidx];
            *(uint4*)&KVl[r*136 + ch*8] = *(const uint4*)&Qlg[gidx];
        }
        __syncthreads();
        float acc[16][4] = {};
        for (int ks = 0; ks < 8; ks++) {
            uint32_t ah[4], al[4];
            asm volatile("ldmatrix.sync.aligned.m8n8.x4.shared.b16 {%0,%1,%2,%3}, [%4];"
                : "=r"(ah[0]), "=r"(ah[1]), "=r"(ah[2]), "=r"(ah[3]) : "r"(q_hi + ks*32));
            asm volatile("ldmatrix.sync.aligned.m8n8.x4.shared.b16 {%0,%1,%2,%3}, [%4];"
                : "=r"(al[0]), "=r"(al[1]), "=r"(al[2]), "=r"(al[3]) : "r"(q_lo + ks*32));
            #pragma unroll
            for (int nt = 0; nt < 16; nt++) {
                uint32_t bh[2], bl[2];
                uint32_t badd = boff + (uint32_t)(nt*8*136)*2u + (uint32_t)ks*32u;
                asm volatile("ldmatrix.sync.aligned.m8n8.x2.shared.b16 {%0,%1}, [%2];"
                    : "=r"(bh[0]), "=r"(bh[1]) : "r"(kv_hi + badd));
                asm volatile("ldmatrix.sync.aligned.m8n8.x2.shared.b16 {%0,%1}, [%2];"
                    : "=r"(bl[0]), "=r"(bl[1]) : "r"(kv_lo + badd));
                MMA_BF16(acc[nt], ah, bh);
                MMA_BF16(acc[nt], ah, bl);
                MMA_BF16(acc[nt], al, bh);
            }
        }
        float rmax0 = -1e30f, rmax1 = -1e30f;
        #pragma unroll
        for (int nt = 0; nt < 16; nt++) {
            int col = kt*128 + nt*8 + 2*tg;
            float2 mv = *(const float2*)&mk[col];
            float2 b0v = *(const float2*)&rn0[col];
            float2 b1v = *(const float2*)&rn1[col];
            float x0 = acc[nt][0]*scale + b0v.x; x0 = (mv.x > 0.f) ? x0 : -1e30f;
            float x1 = acc[nt][1]*scale + b0v.y; x1 = (mv.y > 0.f) ? x1 : -1e30f;
            float x2 = acc[nt][2]*scale + b1v.x; x2 = (mv.x > 0.f) ? x2 : -1e30f;
            float x3 = acc[nt][3]*scale + b1v.y; x3 = (mv.y > 0.f) ? x3 : -1e30f;
            acc[nt][0] = x0; acc[nt][1] = x1; acc[nt][2] = x2; acc[nt][3] = x3;
            rmax0 = fmaxf(rmax0, fmaxf(x0, x1));
            rmax1 = fmaxf(rmax1, fmaxf(x2, x3));
        }
        rmax0 = fmaxf(rmax0, __shfl_xor_sync(0xffffffffu, rmax0, 1));
        rmax0 = fmaxf(rmax0, __shfl_xor_sync(0xffffffffu, rmax0, 2));
        rmax1 = fmaxf(rmax1, __shfl_xor_sync(0xffffffffu, rmax1, 1));
        rmax1 = fmaxf(rmax1, __shfl_xor_sync(0xffffffffu, rmax1, 2));
        float mt0 = fmaxf(m0, rmax0), f0 = __expf(m0 - mt0); m0 = mt0;
        float mt1 = fmaxf(m1, rmax1), f1 = __expf(m1 - mt1); m1 = mt1;
        float s0 = 0.f, s1 = 0.f;
        #pragma unroll
        for (int nt = 0; nt < 16; nt++) {
            float p0 = __expf(acc[nt][0] - mt0);
            float p1 = __expf(acc[nt][1] - mt0);
            float p2 = __expf(acc[nt][2] - mt1);
            float p3 = __expf(acc[nt][3] - mt1);
            acc[nt][0] = p0; acc[nt][1] = p1; acc[nt][2] = p2; acc[nt][3] = p3;
            s0 += p0 + p1; s1 += p2 + p3;
        }
        s0 += __shfl_xor_sync(0xffffffffu, s0, 1);
        s0 += __shfl_xor_sync(0xffffffffu, s0, 2);
        s1 += __shfl_xor_sync(0xffffffffu, s1, 1);
        s1 += __shfl_xor_sync(0xffffffffu, s1, 2);
        l0 = l0*f0 + s0; l1 = l1*f1 + s1;
        #pragma unroll
        for (int dn = 0; dn < 16; dn++) {
            Oacc[dn][0] *= f0; Oacc[dn][1] *= f0;
            Oacc[dn][2] *= f1; Oacc[dn][3] *= f1;
        }
        uint32_t ph[8][4], pl[8][4];
        #pragma unroll
        for (int ks = 0; ks < 8; ks++) {
            float c0 = acc[2*ks][0],   c1 = acc[2*ks][1];
            float c2 = acc[2*ks][2],   c3 = acc[2*ks][3];
            float d0 = acc[2*ks+1][0], d1 = acc[2*ks+1][1];
            float d2 = acc[2*ks+1][2], d3 = acc[2*ks+1][3];
            ph[ks][0] = pack2bf(c0, c1); ph[ks][1] = pack2bf(c2, c3);
            ph[ks][2] = pack2bf(d0, d1); ph[ks][3] = pack2bf(d2, d3);
            pl[ks][0] = pack2bf(c0 - bfhi(c0), c1 - bfhi(c1));
            pl[ks][1] = pack2bf(c2 - bfhi(c2), c3 - bfhi(c3));
            pl[ks][2] = pack2bf(d0 - bfhi(d0), d1 - bfhi(d1));
            pl[ks][3] = pack2bf(d2 - bfhi(d2), d3 - bfhi(d3));
        }
        __syncthreads();
        for (int c = tid; c < 128*16; c += 128) {
            int r = c >> 4, ch = c & 15;
            size_t gidx = (size_t)(kt*128 + r)*384 + 256 + ch*8;
            *(uint4*)&KVh[r*136 + ch*8] = *(const uint4*)&Qhg[gidx];
            *(uint4*)&KVl[r*136 + ch*8] = *(const uint4*)&Qlg[gidx];
        }
        __syncthreads();
        for (int ks = 0; ks < 8; ks++) {
            uint32_t vbase = voff + (uint32_t)(ks*16*136)*2u;
            #pragma unroll
            for (int dn = 0; dn < 16; dn++) {
                uint32_t vh[2], vl[2];
                uint32_t vadd = vbase + (uint32_t)dn*16u;
                asm volatile("ldmatrix.sync.aligned.m8n8.x2.trans.shared.b16 {%0,%1}, [%2];"
                    : "=r"(vh[0]), "=r"(vh[1]) : "r"(kv_hi + vadd));
                asm volatile("ldmatrix.sync.aligned.m8n8.x2.trans.shared.b16 {%0,%1}, [%2];"
                    : "=r"(vl[0]), "=r"(vl[1]) : "r"(kv_lo + vadd));
                MMA_BF16(Oacc[dn], ph[ks], vh);
                MMA_BF16(Oacc[dn], ph[ks], vl);
                MMA_BF16(Oacc[dn], pl[ks], vh);
            }
        }
    }
    // ---- epilogue: sa as bf16 hi/lo ----
    float inv0 = 1.f / l0, inv1 = 1.f / l1;
    size_t row0 = (size_t)b*LL + i0 + w*16 + g;
    size_t row1 = row0 + 8;
    #pragma unroll
    for (int dn = 0; dn < 16; dn++) {
        int c = dn*8 + 2*tg;
        uint32_t h01, l01, h23, l23;
        split2(Oacc[dn][0]*inv0, Oacc[dn][1]*inv0, h01, l01);
        split2(Oacc[dn][2]*inv1, Oacc[dn][3]*inv1, h23, l23);
        *(uint32_t*)&g_sahi[row0*DM + c] = h01;
        *(uint32_t*)&g_salo[row0*DM + c] = l01;
        *(uint32_t*)&g_sahi[row1*DM + c] = h23;
        *(uint32_t*)&g_salo[row1*DM + c] = l23;
    }
}

// ---------------- 9: residual + layernorm (optional bf16 hi/lo out) ----------------
__global__ void ln_kernel(const float* __restrict__ a, const float* __restrict__ bsrc,
                          const float* __restrict__ g, const float* __restrict__ beta,
                          float* __restrict__ out,
                          __nv_bfloat16* __restrict__ ohi, __nv_bfloat16* __restrict__ olo) {
    int row = blockIdx.x, t = threadIdx.x;
    float x = a[(size_t)row*DM + t] + bsrc[(size_t)row*DM + t];
    float s = x, q = x*x;
    for (int o = 16; o; o >>= 1) {
        s += __shfl_xor_sync(0xffffffffu, s, o);
        q += __shfl_xor_sync(0xffffffffu, q, o);
    }
    __shared__ float ss[4], qq[4];
    if ((t & 31) == 0) { ss[t >> 5] = s; qq[t >> 5] = q; }
    __syncthreads();
    s = ss[0]+ss[1]+ss[2]+ss[3];
    q = qq[0]+qq[1]+qq[2]+qq[3];
    float m = s * (1.f/128.f);
    float v = q * (1.f/128.f) - m*m;
    float r = (x - m) * rsqrtf(v + 1e-5f) * g[t] + beta[t];
    out[(size_t)row*DM + t] = r;
    if (ohi) {
        __nv_bfloat16 hi = __float2bfloat16(r);
        ohi[(size_t)row*DM + t] = hi;
        olo[(size_t)row*DM + t] = __float2bfloat16(r - __bfloat162float(hi));
    }
}

// ---------------- 10: final projection 128->16 (masked) ----------------
__global__ void out_kernel(const float* __restrict__ w_lin, const float* __restrict__ mask,
                           float* __restrict__ dout) {
    int row = blockIdx.x, t = threadIdx.x;
    __shared__ float hs[128];
    hs[t] = g_h2[(size_t)row*DM + t];
    __syncthreads();
    if (t < 16) {
        float s = 0.f;
        #pragma unroll
        for (int d = 0; d < 128; d++) s += hs[d] * w_lin[t*128 + d];
        dout[(size_t)row*16 + t] = s * mask[row];
    }
}

// ---------------- 11: length = sum(mask, axis=1) ----------------
__global__ void len_kernel(const float* __restrict__ mask, float* __restrict__ dout) {
    int b = blockIdx.x, t = threadIdx.x;
    float s = mask[(size_t)b*LL + t];
    for (int o = 16; o; o >>= 1) s += __shfl_xor_sync(0xffffffffu, s, o);
    __shared__ float ws[32];
    if ((t & 31) == 0) ws[t >> 5] = s;
    __syncthreads();
    if (t == 0) {
        float tot = 0.f;
        for (int w = 0; w < 32; w++) tot += ws[w];
        dout[(size_t)NB*LL*16 + b] = tot;
    }
}

extern "C" void kernel_launch(void* const* d_in, const int* in_sizes, int n_in,
                              void* d_out, int out_size) {
    const float* x      = (const float*)d_in[0];
    const float* mask   = (const float*)d_in[1];
    const float* conv_w = (const float*)d_in[2];
    const float* conv_b = (const float*)d_in[3];
    const float* w_in   = (const float*)d_in[4];
    const float* b_in   = (const float*)d_in[5];
    const float* w_out  = (const float*)d_in[6];
    const float* b_out  = (const float*)d_in[7];
    const float* w_ff1  = (const float*)d_in[8];
    const float* b_ff1  = (const float*)d_in[9];
    const float* w_ff2  = (const float*)d_in[10];
    const float* b_ff2  = (const float*)d_in[11];
    const float* ln1_g  = (const float*)d_in[12];
    const float* ln1_b  = (const float*)d_in[13];
    const float* ln2_g  = (const float*)d_in[14];
    const float* ln2_b  = (const float*)d_in[15];
    const float* w_lin  = (const float*)d_in[16];
    float* dout = (float*)d_out;

    float* ph;   cudaGetSymbolAddress((void**)&ph,   g_h);
    float* ptmp; cudaGetSymbolAddress((void**)&ptmp, g_tmp);
    float* ph1;  cudaGetSymbolAddress((void**)&ph1,  g_h1);
    float* ph2;  cudaGetSymbolAddress((void**)&ph2,  g_h2);
    __nv_bfloat16 *phhi, *phlo, *pwhi, *pwlo, *pqh, *pql;
    __nv_bfloat16 *psahi, *psalo, *ph1hi, *ph1lo, *pffhi, *pfflo;
    cudaGetSymbolAddress((void**)&phhi, g_hhi);
    cudaGetSymbolAddress((void**)&phlo, g_hlo);
    cudaGetSymbolAddress((void**)&pwhi, g_whi);
    cudaGetSymbolAddress((void**)&pwlo, g_wlo);
    cudaGetSymbolAddress((void**)&pqh,  g_qh);
    cudaGetSymbolAddress((void**)&pql,  g_ql);
    cudaGetSymbolAddress((void**)&psahi, g_sahi);
    cudaGetSymbolAddress((void**)&psalo, g_salo);
    cudaGetSymbolAddress((void**)&ph1hi, g_h1hi);
    cudaGetSymbolAddress((void**)&ph1lo, g_h1lo);
    cudaGetSymbolAddress((void**)&pffhi, g_ffhi);
    cudaGetSymbolAddress((void**)&pfflo, g_fflo);

    cudaFuncSetAttribute(d2m_kernel, cudaFuncAttributeMaxDynamicSharedMemorySize, D2M_SMEM);
    cudaFuncSetAttribute(flashm_kernel, cudaFuncAttributeMaxDynamicSharedMemorySize, FLASHM_SMEM);
    cudaFuncSetAttribute(gemm_mma, cudaFuncAttributeMaxDynamicSharedMemorySize, GM_SMEM);

    static cudaStream_t s2 = nullptr;
    static cudaEvent_t evF = nullptr, evJ = nullptr;
    if (s2 == nullptr) {
        cudaStreamCreateWithFlags(&s2, cudaStreamNonBlocking);
        cudaEventCreateWithFlags(&evF, cudaEventDisableTiming);
        cudaEventCreateWithFlags(&evJ, cudaEventDisableTiming);
    }

    prep_wp<<<1, 128>>>(conv_w);
    prep_ws<<<384, 256>>>(w_in, w_out, w_ff1, w_ff2);
    conv_kernel<<<dim3(64, 32), 128>>>(x, conv_b, mask);
    cvt_kernel<<<16384, 256>>>();

    cudaEventRecord(evF, 0);
    cudaStreamWaitEvent(s2, evF, 0);

    norm2_kernel<<<NB*LL, 128>>>();
    d2m_kernel<<<dim3(16, 8, NB), 256, D2M_SMEM>>>();
    softdtw_kernel<<<NB, 1024>>>();
    normalize_kernel<<<dim3(32, 32, NB), dim3(32, 32)>>>();

    gemm_mma<<<dim3(6, 256), 256, GM_SMEM, s2>>>(phhi, phlo, pwhi, pwlo, b_in,
                                                 nullptr, pqh, pql, 384, 0);
    len_kernel<<<NB, 1024, 0, s2>>>(mask, dout);

    cudaEventRecord(evJ, s2);
    cudaStreamWaitEvent(0, evJ, 0);

    flashm_kernel<<<dim3(16, NB), 128, FLASHM_SMEM>>>(mask);
    gemm_mma<<<dim3(2, 256), 256, GM_SMEM>>>(psahi, psalo, pwhi + 49152, pwlo + 49152, b_out,
                                             ptmp, nullptr, nullptr, 128, 0);
    ln_kernel<<<NB*LL, 128>>>(ph, ptmp, ln1_g, ln1_b, ph1, ph1hi, ph1lo);
    gemm_mma<<<dim3(2, 256), 256, GM_SMEM>>>(ph1hi, ph1lo, pwhi + 65536, pwlo + 65536, b_ff1,
                                             nullptr, pffhi, pfflo, 128, 1);
    gemm_mma<<<dim3(2, 256), 256, GM_SMEM>>>(pffhi, pfflo, pwhi + 81920, pwlo + 81920, b_ff2,
                                             ptmp, nullptr, nullptr, 128, 0);
    ln_kernel<<<NB*LL, 128>>>(ph1, ptmp, ln2_g, ln2_b, ph2, nullptr, nullptr);
    out_kernel<<<NB*LL, 128>>>(w_lin, mask, dout);
}

// round 17
// speedup vs baseline: 1.5657x; 1.0871x over previous
#include <cuda_runtime.h>
#include <cuda_bf16.h>
#include <cstdint>
#include <math.h>

#define NB 32
#define LL 1024
#define DM 128
#define TT 4095
#define NDIAG 2047
#define DSTRIDE ((size_t)NDIAG*LL)
#define INFV __int_as_float(0x7f800000)

// ---------------- device scratch ----------------
__device__ float g_wp[DM*12*7];
__device__ float g_h[(size_t)NB*LL*DM];
__device__ __nv_bfloat16 g_hhi[(size_t)NB*LL*DM];
__device__ __nv_bfloat16 g_hlo[(size_t)NB*LL*DM];
__device__ float g_norm2[NB*LL];
__device__ float g_Dskew[(size_t)NB*NDIAG*LL];   // D, then R in place (skewed)
__device__ float g_Rmin[NB];
__device__ float g_Rmax[NB];
__device__ float g_Rn[(size_t)NB*LL*LL];         // normalized R (attention bias)
__device__ __nv_bfloat16 g_qh[(size_t)NB*LL*384];
__device__ __nv_bfloat16 g_ql[(size_t)NB*LL*384];
__device__ __nv_bfloat16 g_whi[98304];           // w_in@0, w_out@49152, w_ff1@65536, w_ff2@81920
__device__ __nv_bfloat16 g_wlo[98304];
__device__ __nv_bfloat16 g_sahi[(size_t)NB*LL*DM];
__device__ __nv_bfloat16 g_salo[(size_t)NB*LL*DM];
__device__ __nv_bfloat16 g_h1hi[(size_t)NB*LL*DM];
__device__ __nv_bfloat16 g_h1lo[(size_t)NB*LL*DM];
__device__ __nv_bfloat16 g_ffhi[(size_t)NB*LL*DM];
__device__ __nv_bfloat16 g_fflo[(size_t)NB*LL*DM];
__device__ float g_tmp[(size_t)NB*LL*DM];
__device__ float g_h1[(size_t)NB*LL*DM];
__device__ float g_h2[(size_t)NB*LL*DM];

__device__ __forceinline__ float ex2f(float x) {
    float y; asm("ex2.approx.f32 %0, %1;" : "=f"(y) : "f"(x)); return y;
}
__device__ __forceinline__ uint32_t smem_u32(const void* p) {
    uint32_t a;
    asm("{ .reg .u64 t; cvta.to.shared.u64 t, %1; cvt.u32.u64 %0, t; }" : "=r"(a) : "l"(p));
    return a;
}
__device__ __forceinline__ uint32_t pack2bf(float a, float b) {
    __nv_bfloat162 t = __floats2bfloat162_rn(a, b);
    return *(uint32_t*)&t;
}
__device__ __forceinline__ float bfhi(float a) {
    return __bfloat162float(__float2bfloat16(a));
}
__device__ __forceinline__ void split2(float v0, float v1, uint32_t& hi, uint32_t& lo) {
    float h0 = bfhi(v0), h1 = bfhi(v1);
    hi = pack2bf(h0, h1);
    lo = pack2bf(v0 - h0, v1 - h1);
}

#define MMA_BF16(accv, av, bv) \
    asm volatile("mma.sync.aligned.m16n8k16.row.col.f32.bf16.bf16.f32 " \
        "{%0,%1,%2,%3}, {%4,%5,%6,%7}, {%8,%9}, {%0,%1,%2,%3};" \
        : "+f"(accv[0]), "+f"(accv[1]), "+f"(accv[2]), "+f"(accv[3]) \
        : "r"(av[0]), "r"(av[1]), "r"(av[2]), "r"(av[3]), "r"(bv[0]), "r"(bv[1]))

#define LDSM_X4(r, addr) \
    asm volatile("ldmatrix.sync.aligned.m8n8.x4.shared.b16 {%0,%1,%2,%3}, [%4];" \
        : "=r"(r[0]), "=r"(r[1]), "=r"(r[2]), "=r"(r[3]) : "r"(addr))
#define LDSM_X4T(r, addr) \
    asm volatile("ldmatrix.sync.aligned.m8n8.x4.trans.shared.b16 {%0,%1,%2,%3}, [%4];" \
        : "=r"(r[0]), "=r"(r[1]), "=r"(r[2]), "=r"(r[3]) : "r"(addr))

// ---------------- 0: fold conv+avgpool weights ----------------
__global__ void prep_wp(const float* __restrict__ conv_w) {
    int d = threadIdx.x;
    for (int c = 0; c < 12; c++)
        for (int p = 0; p < 7; p++) {
            float s = 0.f;
            int klo = p - 3 > 0 ? p - 3 : 0;
            int khi = p < 3 ? p : 3;
            for (int k = klo; k <= khi; k++) s += conv_w[(d*12 + c)*4 + k];
            g_wp[(d*12 + c)*7 + p] = 0.25f * s;
        }
}

// ---------------- 0b: split transformer weights into bf16 hi/lo ----------------
__global__ void prep_ws(const float* __restrict__ w_in, const float* __restrict__ w_out,
                        const float* __restrict__ w_ff1, const float* __restrict__ w_ff2) {
    int i = blockIdx.x*256 + threadIdx.x;
    float v;
    if (i < 49152) v = w_in[i];
    else if (i < 65536) v = w_out[i - 49152];
    else if (i < 81920) v = w_ff1[i - 65536];
    else v = w_ff2[i - 81920];
    __nv_bfloat16 hi = __float2bfloat16(v);
    g_whi[i] = hi;
    g_wlo[i] = __float2bfloat16(v - __bfloat162float(hi));
}

// ---------------- 1: conv+pool+relu+mask -> h, hhi/hlo, norm2 (fused) ----------------
__global__ void conv_kernel(const float* __restrict__ x, const float* __restrict__ conv_b,
                            const float* __restrict__ mask) {
    int b = blockIdx.y, l0 = blockIdx.x * 16, d = threadIdx.x;
    __shared__ float xs[12][68];
    __shared__ float wps[128][85];
    __shared__ float wsum[16][4];
    for (int i = d; i < 128*84; i += 128) { wps[i/84][i%84] = g_wp[i]; }
    for (int i = d; i < 12*67; i += 128) {
        int c = i / 67, t = i % 67;
        int xi = 4*l0 - 2 + t;
        xs[c][t] = (xi >= 0 && xi < TT) ? x[((size_t)b*12 + c)*TT + xi] : 0.f;
    }
    __syncthreads();
    float bb = conv_b[d];
    int warp = d >> 5, lane = d & 31;
    for (int ll = 0; ll < 16; ll++) {
        float acc = bb;
        #pragma unroll
        for (int c = 0; c < 12; c++)
            #pragma unroll
            for (int p = 0; p < 7; p++)
                acc += xs[c][4*ll + p] * wps[d][c*7 + p];
        float hv = fmaxf(acc, 0.f) * mask[b*LL + l0 + ll];
        size_t idx = ((size_t)b*LL + l0 + ll)*DM + d;
        g_h[idx] = hv;
        __nv_bfloat16 hi = __float2bfloat16(hv);
        g_hhi[idx] = hi;
        g_hlo[idx] = __float2bfloat16(hv - __bfloat162float(hi));
        float sq = hv*hv;
        for (int o = 16; o; o >>= 1) sq += __shfl_xor_sync(0xffffffffu, sq, o);
        if (lane == 0) wsum[ll][warp] = sq;
    }
    __syncthreads();
    if (d < 16)
        g_norm2[b*LL + l0 + d] = wsum[d][0] + wsum[d][1] + wsum[d][2] + wsum[d][3];
}

// ---------------- 3: pairwise D2 via mma.sync bf16x2 (128x64 tiles) -> skewed ----------------
#define D2M_SMEM 104832

__global__ void __launch_bounds__(256) d2m_kernel() {
    extern __shared__ char dsm[];
    __nv_bfloat16* Ahi = (__nv_bfloat16*)dsm;        // [128][136]
    __nv_bfloat16* Alo = Ahi + 128*136;
    __nv_bfloat16* Bhi = Alo + 128*136;              // [64][136]
    __nv_bfloat16* Blo = Bhi + 64*136;
    float* nsArr = (float*)(Blo + 64*136);           // 64 floats
    int b = blockIdx.z, i0 = blockIdx.y*128, j0 = blockIdx.x*64;
    int tid = threadIdx.x, wid = tid>>5, lane = tid&31;

    for (int c = tid; c < 128*16; c += 256) {
        int r = c >> 4, ch = c & 15;
        size_t g = (size_t)(i0 + r)*DM + ch*8;
        *(uint4*)&Ahi[r*136 + ch*8] = *(const uint4*)&g_hhi[g];
        *(uint4*)&Alo[r*136 + ch*8] = *(const uint4*)&g_hlo[g];
    }
    for (int c = tid; c < 64*16; c += 256) {
        int r = c >> 4, ch = c & 15;
        size_t g = (size_t)(b*LL + j0 + r)*DM + ch*8;
        *(uint4*)&Bhi[r*136 + ch*8] = *(const uint4*)&g_hhi[g];
        *(uint4*)&Blo[r*136 + ch*8] = *(const uint4*)&g_hlo[g];
    }
    if (tid < 64) nsArr[tid] = g_norm2[b*LL + j0 + tid];
    __syncthreads();

    float acc[8][4] = {};
    int mrow = wid*16;
    uint32_t aoff = (uint32_t)((mrow + (lane & 15))*136 + (lane >> 4)*8) * 2u;
    uint32_t a_hi = smem_u32(Ahi) + aoff;
    uint32_t a_lo = smem_u32(Alo) + aoff;
    uint32_t boff4 = (uint32_t)((lane & 7) + ((lane >> 4) << 3))*272u + (uint32_t)((lane >> 3) & 1)*16u;
    uint32_t b_hi = smem_u32(Bhi) + boff4;
    uint32_t b_lo = smem_u32(Blo) + boff4;

    for (int ks = 0; ks < 8; ks++) {
        uint32_t ah[4], al[4];
        LDSM_X4(ah, a_hi + ks*32);
        LDSM_X4(al, a_lo + ks*32);
        #pragma unroll
        for (int nt = 0; nt < 8; nt += 2) {
            uint32_t bh[4], bl[4];
            uint32_t badd = (uint32_t)(nt*8*136)*2u + (uint32_t)ks*32u;
            LDSM_X4(bh, b_hi + badd);
            LDSM_X4(bl, b_lo + badd);
            MMA_BF16(acc[nt], ah, bh);
            MMA_BF16(acc[nt], ah, bl);
            MMA_BF16(acc[nt], al, bh);
            MMA_BF16(acc[nt+1], ah, (bh+2));
            MMA_BF16(acc[nt+1], ah, (bl+2));
            MMA_BF16(acc[nt+1], al, (bh+2));
        }
    }
    __syncthreads();

    float* Cs = (float*)dsm;
    int g = lane >> 2, tg = lane & 3;
    float na0 = g_norm2[i0 + mrow + g];
    float na1 = g_norm2[i0 + mrow + g + 8];
    #pragma unroll
    for (int nt = 0; nt < 8; nt++) {
        int c = nt*8 + tg*2;
        float ns0 = nsArr[c], ns1 = nsArr[c+1];
        Cs[(mrow+g)*66 + c]       = na0 + ns0 - 2.f*acc[nt][0];
        Cs[(mrow+g)*66 + c + 1]   = na0 + ns1 - 2.f*acc[nt][1];
        Cs[(mrow+g+8)*66 + c]     = na1 + ns0 - 2.f*acc[nt][2];
        Cs[(mrow+g+8)*66 + c + 1] = na1 + ns1 - 2.f*acc[nt][3];
    }
    __syncthreads();
    float* Dk = g_Dskew + (size_t)b*DSTRIDE;
    for (int kb = 0; kb < 192; kb += 4) {
        int kk = kb + (tid >> 6);
        int jo = tid & 63;
        if (kk < 191) {
            int io = kk - jo;
            if (io >= 0 && io < 128)
                Dk[(size_t)(i0 + j0 + kk)*LL + i0 + io] = Cs[io*66 + jo];
        }
    }
}

// ---------------- 4: soft-DTW wavefront (R in place, 2-exp softmin) ----------------
__global__ void __launch_bounds__(1024) softdtw_kernel() {
    int b = blockIdx.x, i = threadIdx.x;
    __shared__ float s0[1024], s1[1024], s2[1024];
    __shared__ float rmn[32], rmx[32];
    float *prev2 = s0, *prev1 = s1, *cur = s2;
    prev2[i] = INFV; prev1[i] = INFV;
    float rprev = INFV;
    float* Dk = g_Dskew + (size_t)b*DSTRIDE;
    float vmin = INFV, vmax = -INFV;
    const float cExp = 0.28853900817779268f;
    const float cLog = 3.4657359027997265f;
    float dbuf[8];
    #pragma unroll
    for (int p = 0; p < 8; p++) dbuf[p] = Dk[(size_t)p*LL + i];
    __syncthreads();
    for (int kb = 0; kb < 2048; kb += 8) {
        #pragma unroll
        for (int p = 0; p < 8; p++) {
            int k = kb + p;
            if (k >= NDIAG) break;
            float d = dbuf[p];
            if (k + 8 < NDIAG) dbuf[p] = Dk[(size_t)(k+8)*LL + i];
            float r_l = rprev;
            float r_u, r_ul;
            if (i == 0) { r_u = INFV; r_ul = (k == 0) ? 0.f : INFV; }
            else        { r_u = prev1[i-1]; r_ul = prev2[i-1]; }
            int j = k - i;
            float rv;
            if (j >= 0 && j < LL) {
                float lo  = fminf(r_u, r_l);
                float hi2 = fmaxf(r_u, r_l);
                float m   = fminf(r_ul, lo);
                float o1  = fmaxf(r_ul, lo);
                float s = 1.0f + ex2f((m - o1)*cExp) + ex2f((m - hi2)*cExp);
                rv = d + m - cLog * __log2f(s);
                cur[i] = rv;
                Dk[(size_t)k*LL + i] = rv;
                vmin = fminf(vmin, rv); vmax = fmaxf(vmax, rv);
            } else { rv = INFV; cur[i] = INFV; }
            rprev = rv;
            __syncthreads();
            float* t = prev2; prev2 = prev1; prev1 = cur; cur = t;
        }
    }
    for (int o = 16; o; o >>= 1) {
        vmin = fminf(vmin, __shfl_down_sync(0xffffffffu, vmin, o));
        vmax = fmaxf(vmax, __shfl_down_sync(0xffffffffu, vmax, o));
    }
    if ((i & 31) == 0) { rmn[i >> 5] = vmin; rmx[i >> 5] = vmax; }
    __syncthreads();
    if (i < 32) {
        vmin = rmn[i]; vmax = rmx[i];
        for (int o = 16; o; o >>= 1) {
            vmin = fminf(vmin, __shfl_down_sync(0xffffffffu, vmin, o));
            vmax = fmaxf(vmax, __shfl_down_sync(0xffffffffu, vmax, o));
        }
        if (i == 0) { g_Rmin[b] = vmin; g_Rmax[b] = vmax; }
    }
}

// ---------------- 5: unskew + minmax-normalize -> Rn[b][i][j] ----------------
__global__ void normalize_kernel() {
    int b = blockIdx.z, i0 = blockIdx.y*32, j0 = blockIdx.x*32;
    __shared__ float s[63*33];
    int tid = threadIdx.y*32 + threadIdx.x;
    float mn = g_Rmin[b];
    float inv = 1.f / (g_Rmax[b] - mn);
    const float* Rk = g_Dskew + (size_t)b*DSTRIDE;
    for (int idx = tid; idx < 63*32; idx += 1024) {
        int r = idx >> 5, c = idx & 31;
        s[r*33 + c] = Rk[(size_t)(i0 + j0 + r)*LL + i0 + c];
    }
    __syncthreads();
    float v = s[(threadIdx.y + threadIdx.x)*33 + threadIdx.y];
    g_Rn[(size_t)b*LL*LL + (size_t)(i0 + threadIdx.y)*LL + j0 + threadIdx.x] = (v - mn)*inv + 1.f;
}

// ---------------- 6: GEMM via mma.sync bf16x2: C[M,N] = A[M,128] W[N,128]^T + bias ----------------
#define GM_SMEM 104448
__global__ void __launch_bounds__(256) gemm_mma(
        const __nv_bfloat16* __restrict__ Ahig, const __nv_bfloat16* __restrict__ Alog,
        const __nv_bfloat16* __restrict__ Whig, const __nv_bfloat16* __restrict__ Wlog,
        const float* __restrict__ bias, float* __restrict__ Cf,
        __nv_bfloat16* __restrict__ Chi, __nv_bfloat16* __restrict__ Clo,
        int N, int relu) {
    extern __shared__ char gsm[];
    __nv_bfloat16* Ah = (__nv_bfloat16*)gsm;     // [128][136]
    __nv_bfloat16* Al = Ah + 128*136;
    __nv_bfloat16* Bh = Al + 128*136;            // [64][136]
    __nv_bfloat16* Bl = Bh + 64*136;
    int m0 = blockIdx.y*128, n0 = blockIdx.x*64;
    int tid = threadIdx.x, wid = tid>>5, lane = tid&31;

    for (int c = tid; c < 128*16; c += 256) {
        int r = c >> 4, ch = c & 15;
        size_t g = (size_t)(m0 + r)*128 + ch*8;
        *(uint4*)&Ah[r*136 + ch*8] = *(const uint4*)&Ahig[g];
        *(uint4*)&Al[r*136 + ch*8] = *(const uint4*)&Alog[g];
    }
    for (int c = tid; c < 64*16; c += 256) {
        int r = c >> 4, ch = c & 15;
        size_t g = (size_t)(n0 + r)*128 + ch*8;
        *(uint4*)&Bh[r*136 + ch*8] = *(const uint4*)&Whig[g];
        *(uint4*)&Bl[r*136 + ch*8] = *(const uint4*)&Wlog[g];
    }
    __syncthreads();

    float acc[8][4] = {};
    int mrow = wid*16;
    uint32_t aoff = (uint32_t)((mrow + (lane & 15))*136 + (lane >> 4)*8) * 2u;
    uint32_t a_hi = smem_u32(Ah) + aoff;
    uint32_t a_lo = smem_u32(Al) + aoff;
    uint32_t boff4 = (uint32_t)((lane & 7) + ((lane >> 4) << 3))*272u + (uint32_t)((lane >> 3) & 1)*16u;
    uint32_t b_hi = smem_u32(Bh) + boff4;
    uint32_t b_lo = smem_u32(Bl) + boff4;

    for (int ks = 0; ks < 8; ks++) {
        uint32_t ah[4], al[4];
        LDSM_X4(ah, a_hi + ks*32);
        LDSM_X4(al, a_lo + ks*32);
        #pragma unroll
        for (int nt = 0; nt < 8; nt += 2) {
            uint32_t bh[4], bl[4];
            uint32_t badd = (uint32_t)(nt*8*136)*2u + (uint32_t)ks*32u;
            LDSM_X4(bh, b_hi + badd);
            LDSM_X4(bl, b_lo + badd);
            MMA_BF16(acc[nt], ah, bh);
            MMA_BF16(acc[nt], ah, bl);
            MMA_BF16(acc[nt], al, bh);
            MMA_BF16(acc[nt+1], ah, (bh+2));
            MMA_BF16(acc[nt+1], ah, (bl+2));
            MMA_BF16(acc[nt+1], al, (bh+2));
        }
    }

    int g = lane >> 2, tg = lane & 3;
    size_t row0 = (size_t)(m0 + mrow + g);
    size_t row1 = row0 + 8;
    #pragma unroll
    for (int nt = 0; nt < 8; nt++) {
        int c = nt*8 + tg*2;
        float b0 = bias[n0 + c], b1 = bias[n0 + c + 1];
        float v0 = acc[nt][0] + b0, v1 = acc[nt][1] + b1;
        float v2 = acc[nt][2] + b0, v3 = acc[nt][3] + b1;
        if (relu) {
            v0 = fmaxf(v0, 0.f); v1 = fmaxf(v1, 0.f);
            v2 = fmaxf(v2, 0.f); v3 = fmaxf(v3, 0.f);
        }
        if (Cf) {
            *(float2*)&Cf[row0*N + n0 + c] = make_float2(v0, v1);
            *(float2*)&Cf[row1*N + n0 + c] = make_float2(v2, v3);
        }
        if (Chi) {
            uint32_t h01, l01, h23, l23;
            split2(v0, v1, h01, l01);
            split2(v2, v3, h23, l23);
            *(uint32_t*)&Chi[row0*N + n0 + c] = h01;
            *(uint32_t*)&Clo[row0*N + n0 + c] = l01;
            *(uint32_t*)&Chi[row1*N + n0 + c] = h23;
            *(uint32_t*)&Clo[row1*N + n0 + c] = l23;
        }
    }
}

// ---------------- 7: flash attention via mma.sync (64q tile, 4 warps) ----------------
#define FLASHM_SMEM 104448
__global__ void __launch_bounds__(128) flashm_kernel(const float* __restrict__ mask) {
    extern __shared__ char fsm[];
    __nv_bfloat16* Qh  = (__nv_bfloat16*)fsm;   // [64][136]
    __nv_bfloat16* Ql  = Qh + 64*136;
    __nv_bfloat16* KVh = Ql + 64*136;           // [128][136] shared K then V
    __nv_bfloat16* KVl = KVh + 128*136;
    int b = blockIdx.y, i0 = blockIdx.x*64;
    int tid = threadIdx.x, w = tid>>5, lane = tid&31;
    int g = lane >> 2, tg = lane & 3;
    const float scale = 0.08838834764831845f;   // 1/sqrt(128)
    const __nv_bfloat16* Qhg = g_qh + (size_t)b*LL*384;
    const __nv_bfloat16* Qlg = g_ql + (size_t)b*LL*384;
    const float* mk = mask + (size_t)b*LL;
    const float* rn0 = g_Rn + (size_t)b*LL*LL + (size_t)(i0 + w*16 + g)*LL;
    const float* rn1 = rn0 + 8*LL;

    for (int c = tid; c < 64*16; c += 128) {
        int r = c >> 4, ch = c & 15;
        size_t gidx = (size_t)(i0 + r)*384 + ch*8;
        *(uint4*)&Qh[r*136 + ch*8] = *(const uint4*)&Qhg[gidx];
        *(uint4*)&Ql[r*136 + ch*8] = *(const uint4*)&Qlg[gidx];
    }

    uint32_t aoff = (uint32_t)((w*16 + (lane & 15))*136 + (lane >> 4)*8) * 2u;
    uint32_t q_hi = smem_u32(Qh) + aoff;
    uint32_t q_lo = smem_u32(Ql) + aoff;
    uint32_t boff4 = (uint32_t)((lane & 7) + ((lane >> 4) << 3))*272u + (uint32_t)((lane >> 3) & 1)*16u;
    uint32_t kv_hi = smem_u32(KVh);
    uint32_t kv_lo = smem_u32(KVl);
    uint32_t voff4 = (uint32_t)(lane & 15)*272u + (uint32_t)(lane >> 4)*16u;

    float Oacc[16][4] = {};
    float m0 = -1e30f, m1 = -1e30f, l0 = 0.f, l1 = 0.f;

    for (int kt = 0; kt < 8; kt++) {
        __syncthreads();
        for (int c = tid; c < 128*16; c += 128) {
            int r = c >> 4, ch = c & 15;
            size_t gidx = (size_t)(kt*128 + r)*384 + 128 + ch*8;
            *(uint4*)&KVh[r*136 + ch*8] = *(const uint4*)&Qhg[gidx];
            *(uint4*)&KVl[r*136 + ch*8] = *(const uint4*)&Qlg[gidx];
        }
        __syncthreads();
        float acc[16][4] = {};
        for (int ks = 0; ks < 8; ks++) {
            uint32_t ah[4], al[4];
            LDSM_X4(ah, q_hi + ks*32);
            LDSM_X4(al, q_lo + ks*32);
            #pragma unroll
            for (int nt = 0; nt < 16; nt += 2) {
                uint32_t bh[4], bl[4];
                uint32_t badd = boff4 + (uint32_t)(nt*8*136)*2u + (uint32_t)ks*32u;
                LDSM_X4(bh, kv_hi + badd);
                LDSM_X4(bl, kv_lo + badd);
                MMA_BF16(acc[nt], ah, bh);
                MMA_BF16(acc[nt], ah, bl);
                MMA_BF16(acc[nt], al, bh);
                MMA_BF16(acc[nt+1], ah, (bh+2));
                MMA_BF16(acc[nt+1], ah, (bl+2));
                MMA_BF16(acc[nt+1], al, (bh+2));
            }
        }
        float rmax0 = -1e30f, rmax1 = -1e30f;
        #pragma unroll
        for (int nt = 0; nt < 16; nt++) {
            int col = kt*128 + nt*8 + 2*tg;
            float2 mv = *(const float2*)&mk[col];
            float2 b0v = *(const float2*)&rn0[col];
            float2 b1v = *(const float2*)&rn1[col];
            float x0 = acc[nt][0]*scale + b0v.x; x0 = (mv.x > 0.f) ? x0 : -1e30f;
            float x1 = acc[nt][1]*scale + b0v.y; x1 = (mv.y > 0.f) ? x1 : -1e30f;
            float x2 = acc[nt][2]*scale + b1v.x; x2 = (mv.x > 0.f) ? x2 : -1e30f;
            float x3 = acc[nt][3]*scale + b1v.y; x3 = (mv.y > 0.f) ? x3 : -1e30f;
            acc[nt][0] = x0; acc[nt][1] = x1; acc[nt][2] = x2; acc[nt][3] = x3;
            rmax0 = fmaxf(rmax0, fmaxf(x0, x1));
            rmax1 = fmaxf(rmax1, fmaxf(x2, x3));
        }
        rmax0 = fmaxf(rmax0, __shfl_xor_sync(0xffffffffu, rmax0, 1));
        rmax0 = fmaxf(rmax0, __shfl_xor_sync(0xffffffffu, rmax0, 2));
        rmax1 = fmaxf(rmax1, __shfl_xor_sync(0xffffffffu, rmax1, 1));
        rmax1 = fmaxf(rmax1, __shfl_xor_sync(0xffffffffu, rmax1, 2));
        float mt0 = fmaxf(m0, rmax0), f0 = __expf(m0 - mt0); m0 = mt0;
        float mt1 = fmaxf(m1, rmax1), f1 = __expf(m1 - mt1); m1 = mt1;
        float s0 = 0.f, s1 = 0.f;
        #pragma unroll
        for (int nt = 0; nt < 16; nt++) {
            float p0 = __expf(acc[nt][0] - mt0);
            float p1 = __expf(acc[nt][1] - mt0);
            float p2 = __expf(acc[nt][2] - mt1);
            float p3 = __expf(acc[nt][3] - mt1);
            acc[nt][0] = p0; acc[nt][1] = p1; acc[nt][2] = p2; acc[nt][3] = p3;
            s0 += p0 + p1; s1 += p2 + p3;
        }
        s0 += __shfl_xor_sync(0xffffffffu, s0, 1);
        s0 += __shfl_xor_sync(0xffffffffu, s0, 2);
        s1 += __shfl_xor_sync(0xffffffffu, s1, 1);
        s1 += __shfl_xor_sync(0xffffffffu, s1, 2);
        l0 = l0*f0 + s0; l1 = l1*f1 + s1;
        #pragma unroll
        for (int dn = 0; dn < 16; dn++) {
            Oacc[dn][0] *= f0; Oacc[dn][1] *= f0;
            Oacc[dn][2] *= f1; Oacc[dn][3] *= f1;
        }
        uint32_t ph[8][4], pl[8][4];
        #pragma unroll
        for (int ks = 0; ks < 8; ks++) {
            float c0 = acc[2*ks][0],   c1 = acc[2*ks][1];
            float c2 = acc[2*ks][2],   c3 = acc[2*ks][3];
            float d0 = acc[2*ks+1][0], d1 = acc[2*ks+1][1];
            float d2 = acc[2*ks+1][2], d3 = acc[2*ks+1][3];
            ph[ks][0] = pack2bf(c0, c1); ph[ks][1] = pack2bf(c2, c3);
            ph[ks][2] = pack2bf(d0, d1); ph[ks][3] = pack2bf(d2, d3);
            pl[ks][0] = pack2bf(c0 - bfhi(c0), c1 - bfhi(c1));
            pl[ks][1] = pack2bf(c2 - bfhi(c2), c3 - bfhi(c3));
            pl[ks][2] = pack2bf(d0 - bfhi(d0), d1 - bfhi(d1));
            pl[ks][3] = pack2bf(d2 - bfhi(d2), d3 - bfhi(d3));
        }
        __syncthreads();
        for (int c = tid; c < 128*16; c += 128) {
            int r = c >> 4, ch = c & 15;
            size_t gidx = (size_t)(kt*128 + r)*384 + 256 + ch*8;
            *(uint4*)&KVh[r*136 + ch*8] = *(const uint4*)&Qhg[gidx];
            *(uint4*)&KVl[r*136 + ch*8] = *(const uint4*)&Qlg[gidx];
        }
        __syncthreads();
        for (int ks = 0; ks < 8; ks++) {
            uint32_t vbase = voff4 + (uint32_t)(ks*16*136)*2u;
            #pragma unroll
            for (int dn = 0; dn < 16; dn += 2) {
                uint32_t vh[4], vl[4];
                uint32_t vadd = vbase + (uint32_t)dn*16u;
                LDSM_X4T(vh, kv_hi + vadd);
                LDSM_X4T(vl, kv_lo + vadd);
                MMA_BF16(Oacc[dn], ph[ks], vh);
                MMA_BF16(Oacc[dn], ph[ks], vl);
                MMA_BF16(Oacc[dn], pl[ks], vh);
                MMA_BF16(Oacc[dn+1], ph[ks], (vh+2));
                MMA_BF16(Oacc[dn+1], ph[ks], (vl+2));
                MMA_BF16(Oacc[dn+1], pl[ks], (vh+2));
            }
        }
    }
    // ---- epilogue: sa as bf16 hi/lo ----
    float inv0 = 1.f / l0, inv1 = 1.f / l1;
    size_t row0 = (size_t)b*LL + i0 + w*16 + g;
    size_t row1 = row0 + 8;
    #pragma unroll
    for (int dn = 0; dn < 16; dn++) {
        int c = dn*8 + 2*tg;
        uint32_t h01, l01, h23, l23;
        split2(Oacc[dn][0]*inv0, Oacc[dn][1]*inv0, h01, l01);
        split2(Oacc[dn][2]*inv1, Oacc[dn][3]*inv1, h23, l23);
        *(uint32_t*)&g_sahi[row0*DM + c] = h01;
        *(uint32_t*)&g_salo[row0*DM + c] = l01;
        *(uint32_t*)&g_sahi[row1*DM + c] = h23;
        *(uint32_t*)&g_salo[row1*DM + c] = l23;
    }
}

// ---------------- 9: residual + layernorm (optional bf16 hi/lo out) ----------------
__global__ void ln_kernel(const float* __restrict__ a, const float* __restrict__ bsrc,
                          const float* __restrict__ g, const float* __restrict__ beta,
                          float* __restrict__ out,
                          __nv_bfloat16* __restrict__ ohi, __nv_bfloat16* __restrict__ olo) {
    int row = blockIdx.x, t = threadIdx.x;
    float x = a[(size_t)row*DM + t] + bsrc[(size_t)row*DM + t];
    float s = x, q = x*x;
    for (int o = 16; o; o >>= 1) {
        s += __shfl_xor_sync(0xffffffffu, s, o);
        q += __shfl_xor_sync(0xffffffffu, q, o);
    }
    __shared__ float ss[4], qq[4];
    if ((t & 31) == 0) { ss[t >> 5] = s; qq[t >> 5] = q; }
    __syncthreads();
    s = ss[0]+ss[1]+ss[2]+ss[3];
    q = qq[0]+qq[1]+qq[2]+qq[3];
    float m = s * (1.f/128.f);
    float v = q * (1.f/128.f) - m*m;
    float r = (x - m) * rsqrtf(v + 1e-5f) * g[t] + beta[t];
    out[(size_t)row*DM + t] = r;
    if (ohi) {
        __nv_bfloat16 hi = __float2bfloat16(r);
        ohi[(size_t)row*DM + t] = hi;
        olo[(size_t)row*DM + t] = __float2bfloat16(r - __bfloat162float(hi));
    }
}

// ---------------- 10: final projection 128->16 (masked) ----------------
__global__ void out_kernel(const float* __restrict__ w_lin, const float* __restrict__ mask,
                           float* __restrict__ dout) {
    int row = blockIdx.x, t = threadIdx.x;
    __shared__ float hs[128];
    hs[t] = g_h2[(size_t)row*DM + t];
    __syncthreads();
    if (t < 16) {
        float s = 0.f;
        #pragma unroll
        for (int d = 0; d < 128; d++) s += hs[d] * w_lin[t*128 + d];
        dout[(size_t)row*16 + t] = s * mask[row];
    }
}

// ---------------- 11: length = sum(mask, axis=1) ----------------
__global__ void len_kernel(const float* __restrict__ mask, float* __restrict__ dout) {
    int b = blockIdx.x, t = threadIdx.x;
    float s = mask[(size_t)b*LL + t];
    for (int o = 16; o; o >>= 1) s += __shfl_xor_sync(0xffffffffu, s, o);
    __shared__ float ws[32];
    if ((t & 31) == 0) ws[t >> 5] = s;
    __syncthreads();
    if (t == 0) {
        float tot = 0.f;
        for (int w = 0; w < 32; w++) tot += ws[w];
        dout[(size_t)NB*LL*16 + b] = tot;
    }
}

extern "C" void kernel_launch(void* const* d_in, const int* in_sizes, int n_in,
                              void* d_out, int out_size) {
    const float* x      = (const float*)d_in[0];
    const float* mask   = (const float*)d_in[1];
    const float* conv_w = (const float*)d_in[2];
    const float* conv_b = (const float*)d_in[3];
    const float* w_in   = (const float*)d_in[4];
    const float* b_in   = (const float*)d_in[5];
    const float* w_out  = (const float*)d_in[6];
    const float* b_out  = (const float*)d_in[7];
    const float* w_ff1  = (const float*)d_in[8];
    const float* b_ff1  = (const float*)d_in[9];
    const float* w_ff2  = (const float*)d_in[10];
    const float* b_ff2  = (const float*)d_in[11];
    const float* ln1_g  = (const float*)d_in[12];
    const float* ln1_b  = (const float*)d_in[13];
    const float* ln2_g  = (const float*)d_in[14];
    const float* ln2_b  = (const float*)d_in[15];
    const float* w_lin  = (const float*)d_in[16];
    float* dout = (float*)d_out;

    float* ph;   cudaGetSymbolAddress((void**)&ph,   g_h);
    float* ptmp; cudaGetSymbolAddress((void**)&ptmp, g_tmp);
    float* ph1;  cudaGetSymbolAddress((void**)&ph1,  g_h1);
    float* ph2;  cudaGetSymbolAddress((void**)&ph2,  g_h2);
    __nv_bfloat16 *phhi, *phlo, *pwhi, *pwlo, *pqh, *pql;
    __nv_bfloat16 *psahi, *psalo, *ph1hi, *ph1lo, *pffhi, *pfflo;
    cudaGetSymbolAddress((void**)&phhi, g_hhi);
    cudaGetSymbolAddress((void**)&phlo, g_hlo);
    cudaGetSymbolAddress((void**)&pwhi, g_whi);
    cudaGetSymbolAddress((void**)&pwlo, g_wlo);
    cudaGetSymbolAddress((void**)&pqh,  g_qh);
    cudaGetSymbolAddress((void**)&pql,  g_ql);
    cudaGetSymbolAddress((void**)&psahi, g_sahi);
    cudaGetSymbolAddress((void**)&psalo, g_salo);
    cudaGetSymbolAddress((void**)&ph1hi, g_h1hi);
    cudaGetSymbolAddress((void**)&ph1lo, g_h1lo);
    cudaGetSymbolAddress((void**)&pffhi, g_ffhi);
    cudaGetSymbolAddress((void**)&pfflo, g_fflo);

    cudaFuncSetAttribute(d2m_kernel, cudaFuncAttributeMaxDynamicSharedMemorySize, D2M_SMEM);
    cudaFuncSetAttribute(flashm_kernel, cudaFuncAttributeMaxDynamicSharedMemorySize, FLASHM_SMEM);
    cudaFuncSetAttribute(gemm_mma, cudaFuncAttributeMaxDynamicSharedMemorySize, GM_SMEM);

    static cudaStream_t s2 = nullptr;
    static cudaEvent_t evF = nullptr, evJ = nullptr;
    if (s2 == nullptr) {
        cudaStreamCreateWithFlags(&s2, cudaStreamNonBlocking);
        cudaEventCreateWithFlags(&evF, cudaEventDisableTiming);
        cudaEventCreateWithFlags(&evJ, cudaEventDisableTiming);
    }

    prep_wp<<<1, 128>>>(conv_w);
    prep_ws<<<384, 256>>>(w_in, w_out, w_ff1, w_ff2);
    conv_kernel<<<dim3(64, 32), 128>>>(x, conv_b, mask);

    cudaEventRecord(evF, 0);
    cudaStreamWaitEvent(s2, evF, 0);

    d2m_kernel<<<dim3(16, 8, NB), 256, D2M_SMEM>>>();
    softdtw_kernel<<<NB, 1024>>>();
    normalize_kernel<<<dim3(32, 32, NB), dim3(32, 32)>>>();

    gemm_mma<<<dim3(6, 256), 256, GM_SMEM, s2>>>(phhi, phlo, pwhi, pwlo, b_in,
                                                 nullptr, pqh, pql, 384, 0);
    len_kernel<<<NB, 1024, 0, s2>>>(mask, dout);

    cudaEventRecord(evJ, s2);
    cudaStreamWaitEvent(0, evJ, 0);

    flashm_kernel<<<dim3(16, NB), 128, FLASHM_SMEM>>>(mask);
    gemm_mma<<<dim3(2, 256), 256, GM_SMEM>>>(psahi, psalo, pwhi + 49152, pwlo + 49152, b_out,
                                             ptmp, nullptr, nullptr, 128, 0);
    ln_kernel<<<NB*LL, 128>>>(ph, ptmp, ln1_g, ln1_b, ph1, ph1hi, ph1lo);
    gemm_mma<<<dim3(2, 256), 256, GM_SMEM>>>(ph1hi, ph1lo, pwhi + 65536, pwlo + 65536, b_ff1,
                                             nullptr, pffhi, pfflo, 128, 1);
    gemm_mma<<<dim3(2, 256), 256, GM_SMEM>>>(pffhi, pfflo, pwhi + 81920, pwlo + 81920, b_ff2,
                                             ptmp, nullptr, nullptr, 128, 0);
    ln_kernel<<<NB*LL, 128>>>(ph1, ptmp, ln2_g, ln2_b, ph2, nullptr, nullptr);
    out_kernel<<<NB*LL, 128>>>(w_lin, mask, dout);
}